// round 12
// baseline (speedup 1.0000x reference)
#include <cuda_runtime.h>
#include <cstdint>

#define BB     8
#define WIN    12
#define NNODE  2000
#define FIN    8
#define HD     64
#define NTOT   192000          // BB*WIN*NNODE
#define NE     2000000
#define BNS    16000           // BB*NNODE sequences
#define BNEPS  1e-5f
#define FC1IN  225
#define NBLK   750             // NTOT/256
#define HP     132             // LSTM Hs seq pitch
#define LSTM_SMEM ((16384 + 64*HP)*4)

// tc-gemm smem layout (bytes)
#define TC_AHI   4096
#define TC_ALO   20480
#define TC_WHI   36864
#define TC_WLO   69632
#define TC_SMEM  102400
#define TC_IDESC 0x8400910u     // kind::tf32, f32 D, M=128, N=256, K-major both

#if defined(__CUDA_ARCH_FEAT_SM103_ALL) || defined(__CUDA_ARCH_FEAT_SM100_ALL)
#define HAS_TCGEN05 1
#else
#define HAS_TCGEN05 0
#endif

// ---------------- scratch (device globals; allocation-free) ----------------
__device__ float g_deg[NTOT];
__device__ float g_dis[NTOT];
__device__ float g_xw  [NTOT*HD];
__device__ float g_agg1[NTOT*HD];
__device__ float g_agg2[NTOT*HD];
__device__ float g_stats[512];
__device__ float g_xproj[(size_t)WIN*BNS*4*HD];
__device__ float g_y1  [(size_t)WIN*BNS*HD];
__device__ float g_hn1 [BNS*HD];
__device__ float g_hn2 [BNS*HD];
__device__ float g_whi1[256*128];
__device__ float g_wlo1[256*128];
__device__ float g_whi2[256*64];
__device__ float g_wlo2[256*64];
// CSR scratch
__device__ int   g_cnt[NTOT];
__device__ int   g_rowstart[NTOT+1];
__device__ int   g_cursor[NTOT];
__device__ int   g_bsum[1024];
__device__ int2  g_edata[NE];

// ---------------- helpers ----------------
__device__ __forceinline__ float sigf(float x)  { return __fdividef(1.f, 1.f + __expf(-x)); }
__device__ __forceinline__ float tanhfast(float x){ return 1.f - __fdividef(2.f, __expf(2.f*x) + 1.f); }

__device__ __forceinline__ float2 ffma2(float2 a, float2 b, float2 c){
    float2 d;
    asm("fma.rn.f32x2 %0, %1, %2, %3;"
        : "=l"(reinterpret_cast<unsigned long long&>(d))
        : "l"(reinterpret_cast<unsigned long long&>(a)),
          "l"(reinterpret_cast<unsigned long long&>(b)),
          "l"(reinterpret_cast<unsigned long long&>(c)));
    return d;
}
__device__ __forceinline__ float2 dup2(float x){ return make_float2(x, x); }
__device__ __forceinline__ void fma4(float (&a)[4], float h, float4 w){
    a[0]=fmaf(h,w.x,a[0]); a[1]=fmaf(h,w.y,a[1]); a[2]=fmaf(h,w.z,a[2]); a[3]=fmaf(h,w.w,a[3]);
}
__device__ __forceinline__ float tf32r(float x){
    uint32_t u; asm("cvt.rna.tf32.f32 %0, %1;" : "=r"(u) : "f"(x));
    return __uint_as_float(u);
}

#if HAS_TCGEN05
__device__ __forceinline__ uint32_t smem_u32(const void* p){
    uint32_t a;
    asm("{ .reg .u64 t; cvta.to.shared.u64 t, %1; cvt.u32.u64 %0, t; }" : "=r"(a) : "l"(p));
    return a;
}
__device__ __forceinline__ uint32_t swz128(uint32_t off){ return off ^ ((off >> 3) & 0x70); }
__device__ __forceinline__ uint64_t mk_desc(uint32_t addr){
    return ((uint64_t)2 << 61) | ((uint64_t)1 << 46) | ((uint64_t)64 << 32) | ((uint64_t)1 << 16)
         | ((uint64_t)(addr >> 4) & 0x3FFF);
}
__device__ __forceinline__ void mma_tf32(uint32_t d, uint64_t ad, uint64_t bd, uint32_t en){
    asm volatile(
        "{\n\t.reg .pred p;\n\tsetp.ne.u32 p, %5, 0;\n\t"
        "tcgen05.mma.cta_group::1.kind::tf32 [%0], %1, %2, %3, {%4, %4, %4, %4}, p;\n\t}"
        :: "r"(d), "l"(ad), "l"(bd), "r"(TC_IDESC), "r"(0u), "r"(en) : "memory");
}
__device__ __forceinline__ void mbar_wait(uint32_t mb, uint32_t parity){
    asm volatile(
        "{\n\t.reg .pred P1;\n\t"
        "W_%=:\n\t"
        "mbarrier.try_wait.parity.acquire.cta.shared::cta.b64 P1, [%0], %1;\n\t"
        "@!P1 bra W_%=;\n\t}"
        :: "r"(mb), "r"(parity) : "memory");
}
#define LDTM_X32(r, addr) \
    asm volatile("tcgen05.ld.sync.aligned.32x32b.x32.b32 " \
        "{%0,%1,%2,%3,%4,%5,%6,%7,%8,%9,%10,%11,%12,%13,%14,%15," \
        "%16,%17,%18,%19,%20,%21,%22,%23,%24,%25,%26,%27,%28,%29,%30,%31}, [%32];" \
        : "=r"((r)[0]),"=r"((r)[1]),"=r"((r)[2]),"=r"((r)[3]),"=r"((r)[4]),"=r"((r)[5]),"=r"((r)[6]),"=r"((r)[7]), \
          "=r"((r)[8]),"=r"((r)[9]),"=r"((r)[10]),"=r"((r)[11]),"=r"((r)[12]),"=r"((r)[13]),"=r"((r)[14]),"=r"((r)[15]), \
          "=r"((r)[16]),"=r"((r)[17]),"=r"((r)[18]),"=r"((r)[19]),"=r"((r)[20]),"=r"((r)[21]),"=r"((r)[22]),"=r"((r)[23]), \
          "=r"((r)[24]),"=r"((r)[25]),"=r"((r)[26]),"=r"((r)[27]),"=r"((r)[28]),"=r"((r)[29]),"=r"((r)[30]),"=r"((r)[31]) \
        : "r"(addr))
#endif

// ---------------- init / degree / CSR ----------------
__global__ void k_init(float* deg, int* cnt){
    int i = blockIdx.x*blockDim.x + threadIdx.x;
    if (i < NTOT){ deg[i] = 1.0f; cnt[i] = 0; }
    if (i < 512) g_stats[i] = 0.f;
}
__global__ void k_deg_hist(const int* __restrict__ col, const float* __restrict__ w,
                           float* deg, int* cnt){
    int e = blockIdx.x*blockDim.x + threadIdx.x;
    if (e < NE){
        int c = col[e];
        atomicAdd(&deg[c], w[e]);
        atomicAdd(&cnt[c], 1);
    }
}
__global__ void k_dis(const float* __restrict__ deg, float* dis){
    int i = blockIdx.x*blockDim.x + threadIdx.x;
    if (i < NTOT){ float d = deg[i]; dis[i] = (d > 0.f) ? rsqrtf(d) : 0.f; }
}
__global__ void k_scan_a(const int* __restrict__ cnt, int* bsum){
    __shared__ int sh[256];
    int t = threadIdx.x;
    sh[t] = cnt[blockIdx.x*256 + t];
    __syncthreads();
    #pragma unroll
    for (int off = 128; off > 0; off >>= 1){
        if (t < off) sh[t] += sh[t + off];
        __syncthreads();
    }
    if (t == 0) bsum[blockIdx.x] = sh[0];
}
__global__ void k_scan_b(const int* __restrict__ bsum, int* boff, int* rowstart){
    __shared__ int sh[1024];
    int t = threadIdx.x;
    int v = (t < NBLK) ? bsum[t] : 0;
    sh[t] = v;
    __syncthreads();
    #pragma unroll
    for (int off = 1; off < 1024; off <<= 1){
        int x = (t >= off) ? sh[t - off] : 0;
        __syncthreads();
        sh[t] += x;
        __syncthreads();
    }
    if (t < NBLK) boff[t] = sh[t] - v;
    if (t == 0) rowstart[NTOT] = NE;
}
__global__ void k_scan_c(const int* __restrict__ cnt, const int* __restrict__ boff,
                         int* rowstart, int* cursor){
    __shared__ int sh[256];
    int t = threadIdx.x;
    int i = blockIdx.x*256 + t;
    int v = cnt[i];
    sh[t] = v;
    __syncthreads();
    #pragma unroll
    for (int off = 1; off < 256; off <<= 1){
        int x = (t >= off) ? sh[t - off] : 0;
        __syncthreads();
        sh[t] += x;
        __syncthreads();
    }
    int ex = boff[blockIdx.x] + sh[t] - v;
    rowstart[i] = ex;
    cursor[i]   = ex;
}
__global__ void k_scatter(const int* __restrict__ rows, const int* __restrict__ cols,
                          const float* __restrict__ w, const float* __restrict__ dis,
                          int* cursor, int2* edata){
    int e = blockIdx.x*blockDim.x + threadIdx.x;
    if (e >= NE) return;
    int r = rows[e], c = cols[e];
    float norm = dis[r]*w[e]*dis[c];
    int pos = atomicAdd(&cursor[c], 1);
    edata[pos] = make_int2(r, __float_as_int(norm));
}

// ---------------- split W into tf32 hi/lo planes ----------------
__global__ void k_split_w(const float* __restrict__ W, int n, float* __restrict__ hi, float* __restrict__ lo){
    int i = blockIdx.x*blockDim.x + threadIdx.x;
    if (i < n){
        float v = W[i];
        float h = tf32r(v);
        hi[i] = h; lo[i] = v - h;
    }
}

// ---------------- xw = x @ W1  (K=8), 2 nodes per thread ----------------
__global__ void k_xw1(const float* __restrict__ x, const float* __restrict__ W, float* __restrict__ out){
    __shared__ float Ws[FIN*HD];
    for (int i = threadIdx.x; i < FIN*HD; i += blockDim.x) Ws[i] = W[i];
    __syncthreads();
    int base = (blockIdx.x*blockDim.x + threadIdx.x)*2;
    if (base >= NTOT) return;
    #pragma unroll
    for (int u = 0; u < 2; u++){
        int node = base + u;
        float xr[FIN];
        float4 v0 = *(const float4*)(x + (size_t)node*FIN);
        float4 v1 = *(const float4*)(x + (size_t)node*FIN + 4);
        xr[0]=v0.x; xr[1]=v0.y; xr[2]=v0.z; xr[3]=v0.w;
        xr[4]=v1.x; xr[5]=v1.y; xr[6]=v1.z; xr[7]=v1.w;
        #pragma unroll
        for (int j = 0; j < HD; j += 4){
            float a[4] = {0.f,0.f,0.f,0.f};
            #pragma unroll
            for (int k = 0; k < FIN; k++){
                float4 w4 = *(const float4*)&Ws[k*HD + j];
                fma4(a, xr[k], w4);
            }
            *(float4*)(out + (size_t)node*HD + j) = make_float4(a[0],a[1],a[2],a[3]);
        }
    }
}

// ---------------- aggregation: gather (warp per target node) + fused BN stats ----------------
__global__ void __launch_bounds__(256) k_agg_gather(const float* __restrict__ xw,
                                                    const float* __restrict__ dis,
                                                    const int* __restrict__ rowstart,
                                                    const int2* __restrict__ edata,
                                                    float* __restrict__ agg,
                                                    const float* __restrict__ bias,
                                                    float* __restrict__ stats){
    __shared__ float ss [8][64];
    __shared__ float ss2[8][64];
    const int tid = threadIdx.x;
    const int wrp = tid >> 5;
    const int lane = tid & 31;
    int gw = blockIdx.x*8 + wrp;
    float va = 0.f, vb = 0.f;
    if (gw < NTOT){
        int beg = rowstart[gw], end = rowstart[gw+1];
        float d = dis[gw];
        float2 v0 = *(const float2*)(xw + (size_t)gw*HD + lane*2);
        float sc = d*d;
        float2 acc = make_float2(v0.x*sc, v0.y*sc);
        int j = beg;
        for (; j + 4 <= end; j += 4){
            int2 e0 = edata[j], e1 = edata[j+1], e2 = edata[j+2], e3 = edata[j+3];
            float2 a = *(const float2*)(xw + (size_t)e0.x*HD + lane*2);
            float2 b = *(const float2*)(xw + (size_t)e1.x*HD + lane*2);
            float2 cc = *(const float2*)(xw + (size_t)e2.x*HD + lane*2);
            float2 dd = *(const float2*)(xw + (size_t)e3.x*HD + lane*2);
            float n0 = __int_as_float(e0.y), n1 = __int_as_float(e1.y);
            float n2 = __int_as_float(e2.y), n3 = __int_as_float(e3.y);
            acc.x = fmaf(a.x, n0, acc.x);  acc.y = fmaf(a.y, n0, acc.y);
            acc.x = fmaf(b.x, n1, acc.x);  acc.y = fmaf(b.y, n1, acc.y);
            acc.x = fmaf(cc.x, n2, acc.x); acc.y = fmaf(cc.y, n2, acc.y);
            acc.x = fmaf(dd.x, n3, acc.x); acc.y = fmaf(dd.y, n3, acc.y);
        }
        for (; j < end; j++){
            int2 e0 = edata[j];
            float2 a = *(const float2*)(xw + (size_t)e0.x*HD + lane*2);
            float n0 = __int_as_float(e0.y);
            acc.x = fmaf(a.x, n0, acc.x); acc.y = fmaf(a.y, n0, acc.y);
        }
        *(float2*)(agg + (size_t)gw*HD + lane*2) = acc;
        va = fmaxf(acc.x + bias[lane*2],   0.f);
        vb = fmaxf(acc.y + bias[lane*2+1], 0.f);
    }
    ss [wrp][lane*2]   = va;
    ss [wrp][lane*2+1] = vb;
    ss2[wrp][lane*2]   = va*va;
    ss2[wrp][lane*2+1] = vb*vb;
    __syncthreads();
    if (tid < 64){
        float s = 0.f, s2 = 0.f;
        #pragma unroll
        for (int w = 0; w < 8; w++){ s += ss[w][tid]; s2 += ss2[w][tid]; }
        atomicAdd(&stats[tid], s);
        atomicAdd(&stats[64+tid], s2);
    }
}

__global__ void k_bn_fin(const float* __restrict__ gamma, const float* __restrict__ beta,
                         float* __restrict__ stats){
    int ch = threadIdx.x;
    if (ch < 64){
        const float invN = 1.f/(float)NTOT;
        float m = stats[ch]*invN;
        float var = stats[64+ch]*invN - m*m;
        float sc = gamma[ch]*rsqrtf(var + BNEPS);
        stats[128+ch] = sc;
        stats[192+ch] = beta[ch] - m*sc;
    }
}

// ---------------- xw2 = bn1(agg1) @ W2  (tiled 64x64, f32x2, fused BN) ----------------
__global__ void __launch_bounds__(256) k_xw2g(const float* __restrict__ A, const float* __restrict__ W,
                                              const float* __restrict__ bias, const float* __restrict__ stats,
                                              float* __restrict__ out){
    __shared__ float As[16][64];
    __shared__ float Bs[16][68];
    __shared__ float bnb[64], bns[64], bnh[64];
    const int tid = threadIdx.x;
    if (tid < 64){ bnb[tid] = bias[tid]; bns[tid] = stats[128+tid]; bnh[tid] = stats[192+tid]; }
    __syncthreads();
    const int bm = blockIdx.x*64;
    const int lr = tid >> 2, lk = (tid & 3)*4;
    const int m  = bm + lr;
    const int ty = tid >> 4, tx = tid & 15;
    float2 acc[4][2] = {};
    for (int k0 = 0; k0 < HD; k0 += 16){
        float4 av = *(const float4*)(A + (size_t)m*HD + k0 + lk);
        int cb = k0 + lk;
        av.x = fmaxf(av.x + bnb[cb+0], 0.f)*bns[cb+0] + bnh[cb+0];
        av.y = fmaxf(av.y + bnb[cb+1], 0.f)*bns[cb+1] + bnh[cb+1];
        av.z = fmaxf(av.z + bnb[cb+2], 0.f)*bns[cb+2] + bnh[cb+2];
        av.w = fmaxf(av.w + bnb[cb+3], 0.f)*bns[cb+3] + bnh[cb+3];
        As[lk+0][lr]=av.x; As[lk+1][lr]=av.y; As[lk+2][lr]=av.z; As[lk+3][lr]=av.w;
        int kk = tid >> 4, n4 = (tid & 15)*4;
        float4 bv = *(const float4*)(W + (size_t)(k0+kk)*HD + n4);
        Bs[kk][n4+0]=bv.x; Bs[kk][n4+1]=bv.y; Bs[kk][n4+2]=bv.z; Bs[kk][n4+3]=bv.w;
        __syncthreads();
        #pragma unroll
        for (int q = 0; q < 16; q++){
            float4 a4 = *(const float4*)&As[q][ty*4];
            float4 b4 = *(const float4*)&Bs[q][tx*4];
            float2 bb0 = make_float2(b4.x, b4.y), bb1 = make_float2(b4.z, b4.w);
            float ar[4] = {a4.x, a4.y, a4.z, a4.w};
            #pragma unroll
            for (int i = 0; i < 4; i++){
                float2 ad = dup2(ar[i]);
                acc[i][0] = ffma2(ad, bb0, acc[i][0]);
                acc[i][1] = ffma2(ad, bb1, acc[i][1]);
            }
        }
        __syncthreads();
    }
    #pragma unroll
    for (int i = 0; i < 4; i++){
        int mr = bm + ty*4 + i;
        *(float4*)(out + (size_t)mr*HD + tx*4) =
            make_float4(acc[i][0].x, acc[i][0].y, acc[i][1].x, acc[i][1].y);
    }
}

// ---------------- gate GEMM: out[m][256] = A[m][KD] @ W^T + bias ----------------
// A chunk c+1 is LDG-prefetched into registers while MMA of chunk c runs.
template<int KD, bool GATHER>
__global__ void __launch_bounds__(256, 2)
k_gemm_tc(const float* __restrict__ A0, const float* __restrict__ A1,
          const float* __restrict__ whi, const float* __restrict__ wlo,
          const float* __restrict__ bih, const float* __restrict__ bhh,
          const float* __restrict__ b1, const float* __restrict__ b2,
          const float* __restrict__ stats,
          float* __restrict__ out){
    extern __shared__ float sm[];
    float* bias_sm = sm + 64;           // 256 floats
    float* bnb = sm + 320; float* bns = sm + 448; float* bnh = sm + 576;
    const int tid = threadIdx.x;

    if (tid < 128){
        bias_sm[tid]     = bih[tid]     + bhh[tid];
        bias_sm[128+tid] = bih[128+tid] + bhh[128+tid];
    }
    if (GATHER && tid < 64){
        bnb[tid]    = b1[tid]; bns[tid]    = stats[128+tid]; bnh[tid]    = stats[192+tid];
        bnb[64+tid] = b2[tid]; bns[64+tid] = stats[384+tid]; bnh[64+tid] = stats[448+tid];
    }

#if HAS_TCGEN05
    char* smc = (char*)sm;
    const uint32_t sb = smem_u32(sm);
    const uint32_t mb = sb + 8;
    const int wid = tid >> 5, lane = tid & 31;
    if (wid == 0){
        asm volatile("tcgen05.alloc.cta_group::1.sync.aligned.shared::cta.b32 [%0], %1;"
                     :: "r"(sb), "r"(256u) : "memory");
        asm volatile("tcgen05.relinquish_alloc_permit.cta_group::1.sync.aligned;" ::: "memory");
    }
    if (tid == 0)
        asm volatile("mbarrier.init.shared.b64 [%0], %1;" :: "r"(mb), "r"(1u) : "memory");
    __syncthreads();
    uint32_t tmem;
    asm volatile("ld.shared.b32 %0, [%1];" : "=r"(tmem) : "r"(sb));

    const int bm = blockIdx.x*128;
    const int row = tid >> 1;
    const int j4  = (tid & 1)*4;
    const int m = bm + row;
    size_t aoff;
    if (GATHER){
        int t = m/BNS, s = m - t*BNS;
        int b = s/NNODE, n = s - b*NNODE;
        aoff = (size_t)((b*WIN + t)*NNODE + n)*HD;
    } else {
        aoff = (size_t)m*KD;
    }

    const uint64_t dAH = mk_desc(sb + TC_AHI), dAL = mk_desc(sb + TC_ALO);
    const uint64_t dWH = mk_desc(sb + TC_WHI), dWL = mk_desc(sb + TC_WLO);
    const int NCH = KD/32;
    uint32_t parity = 0;
    const uint32_t arow = (uint32_t)((row>>3)*1024 + (row&7)*128);

    // prefetch buffer: this thread's 4 float4 of the A chunk
    float4 pf[4];
    {
        const float* abase = GATHER ? A0 : A0;
        #pragma unroll
        for (int u = 0; u < 4; u++)
            pf[u] = *(const float4*)(abase + aoff + (j4+u)*4);
    }

    for (int c = 0; c < NCH; c++){
        const int k0 = c*32;
        if (c > 0){ mbar_wait(mb, parity); parity ^= 1; }
        // ---- STS A chunk c from prefetch regs (BN + tf32 split applied here) ----
        #pragma unroll
        for (int u = 0; u < 4; u++){
            int j = j4 + u;
            float4 v = pf[u];
            if (GATHER){
                int k = k0 + j*4;
                v.x = fmaxf(v.x + bnb[k+0], 0.f)*bns[k+0] + bnh[k+0];
                v.y = fmaxf(v.y + bnb[k+1], 0.f)*bns[k+1] + bnh[k+1];
                v.z = fmaxf(v.z + bnb[k+2], 0.f)*bns[k+2] + bnh[k+2];
                v.w = fmaxf(v.w + bnb[k+3], 0.f)*bns[k+3] + bnh[k+3];
            }
            float4 hi, lo;
            hi.x = tf32r(v.x); lo.x = v.x - hi.x;
            hi.y = tf32r(v.y); lo.y = v.y - hi.y;
            hi.z = tf32r(v.z); lo.z = v.z - hi.z;
            hi.w = tf32r(v.w); lo.w = v.w - hi.w;
            uint32_t sw = swz128(arow + j*16);
            *(float4*)(smc + TC_AHI + sw) = hi;
            *(float4*)(smc + TC_ALO + sw) = lo;
        }
        // ---- W chunk c (L2-hot) ----
        for (int idx = tid; idx < 2048; idx += 256){
            int g = idx >> 3, j = idx & 7;
            float4 vh = *(const float4*)(whi + (size_t)g*KD + k0 + j*4);
            float4 vl = *(const float4*)(wlo + (size_t)g*KD + k0 + j*4);
            uint32_t sw = swz128((uint32_t)((g>>3)*1024 + (g&7)*128 + j*16));
            *(float4*)(smc + TC_WHI + sw) = vh;
            *(float4*)(smc + TC_WLO + sw) = vl;
        }
        __syncthreads();
        if (tid == 0){
            asm volatile("fence.proxy.async.shared::cta;" ::: "memory");
            #pragma unroll
            for (int s = 0; s < 4; s++){
                uint64_t oa = (uint64_t)(2*s);
                uint32_t en0 = (c == 0 && s == 0) ? 0u : 1u;
                mma_tf32(tmem, dAH + oa, dWH + oa, en0);
                mma_tf32(tmem, dAH + oa, dWL + oa, 1u);
                mma_tf32(tmem, dAL + oa, dWH + oa, 1u);
            }
            asm volatile("tcgen05.commit.cta_group::1.mbarrier::arrive::one.shared::cluster.b64 [%0];"
                         :: "r"(mb) : "memory");
        }
        // ---- prefetch A chunk c+1 (overlaps the MMA above) ----
        if (c + 1 < NCH){
            const int k1 = (c+1)*32;
            const float* abase = GATHER ? ((k1 < 64) ? A0 : A1) : A0;
            const int koff = GATHER ? (k1 & 63) : k1;
            #pragma unroll
            for (int u = 0; u < 4; u++)
                pf[u] = *(const float4*)(abase + aoff + koff + (j4+u)*4);
        }
    }
    mbar_wait(mb, parity);
    parity ^= 1;

    asm volatile("tcgen05.fence::after_thread_sync;" ::: "memory");
    if (tid < 128){
        int mrow = bm + wid*32 + lane;
        float* op = out + (size_t)mrow*256;
        for (int b = 0; b < 8; b++){
            uint32_t r[32];
            LDTM_X32(r, tmem + b*32);
            asm volatile("tcgen05.wait::ld.sync.aligned;" ::: "memory");
            #pragma unroll
            for (int q = 0; q < 8; q++){
                float4 o;
                o.x = __uint_as_float(r[q*4+0]) + bias_sm[b*32 + q*4+0];
                o.y = __uint_as_float(r[q*4+1]) + bias_sm[b*32 + q*4+1];
                o.z = __uint_as_float(r[q*4+2]) + bias_sm[b*32 + q*4+2];
                o.w = __uint_as_float(r[q*4+3]) + bias_sm[b*32 + q*4+3];
                *(float4*)(op + b*32 + q*4) = o;
            }
        }
    }
    __syncthreads();
    if (tid == 0)
        asm volatile("mbarrier.inval.shared.b64 [%0];" :: "r"(mb) : "memory");
    __syncthreads();
    if (wid == 0)
        asm volatile("tcgen05.dealloc.cta_group::1.sync.aligned.b32 %0, %1;"
                     :: "r"(tmem), "r"(256u) : "memory");
#else
    // -------- FFMA2 fallback --------
    float* As = sm + 1024;                 // [16][68]
    float* Bs = sm + 1024 + 16*68;         // [16][260]
    __syncthreads();
    const int bm = blockIdx.x*128;
    const int lr = tid >> 2, lk = (tid & 3)*4;
    const int ty = tid >> 5, tx = tid & 31;
    for (int mh = 0; mh < 2; mh++){
        const int m = bm + mh*64 + lr;
        size_t aoff;
        if (GATHER){
            int t = m/BNS, s = m - t*BNS;
            int b = s/NNODE, n = s - b*NNODE;
            aoff = (size_t)((b*WIN + t)*NNODE + n)*HD;
        } else aoff = (size_t)m*KD;
        float2 acc[8][4] = {};
        for (int k0 = 0; k0 < KD; k0 += 16){
            int k = k0 + lk;
            const float* abase = GATHER ? ((k < 64) ? A0 : A1) : A0;
            int ko = GATHER ? (k & 63) : k;
            float4 v = *(const float4*)(abase + aoff + ko);
            if (GATHER){
                v.x = fmaxf(v.x + bnb[k+0], 0.f)*bns[k+0] + bnh[k+0];
                v.y = fmaxf(v.y + bnb[k+1], 0.f)*bns[k+1] + bnh[k+1];
                v.z = fmaxf(v.z + bnb[k+2], 0.f)*bns[k+2] + bnh[k+2];
                v.w = fmaxf(v.w + bnb[k+3], 0.f)*bns[k+3] + bnh[k+3];
            }
            As[(lk+0)*68 + lr] = v.x;
            As[(lk+1)*68 + lr] = v.y;
            As[(lk+2)*68 + lr] = v.z;
            As[(lk+3)*68 + lr] = v.w;
            for (int i = tid; i < 1024; i += 256){
                int g = i >> 2, kq = (i & 3)*4;
                float4 vh = *(const float4*)(whi + (size_t)g*KD + k0 + kq);
                float4 vl = *(const float4*)(wlo + (size_t)g*KD + k0 + kq);
                Bs[(kq+0)*260 + g] = vh.x + vl.x;
                Bs[(kq+1)*260 + g] = vh.y + vl.y;
                Bs[(kq+2)*260 + g] = vh.z + vl.z;
                Bs[(kq+3)*260 + g] = vh.w + vl.w;
            }
            __syncthreads();
            #pragma unroll
            for (int kk = 0; kk < 16; kk++){
                float4 a0 = *(const float4*)&As[kk*68 + ty*8];
                float4 a1 = *(const float4*)&As[kk*68 + ty*8 + 4];
                float4 b0 = *(const float4*)&Bs[kk*260 + tx*8];
                float4 b1v = *(const float4*)&Bs[kk*260 + tx*8 + 4];
                float2 bb[4] = {make_float2(b0.x,b0.y), make_float2(b0.z,b0.w),
                                make_float2(b1v.x,b1v.y), make_float2(b1v.z,b1v.w)};
                float ar[8] = {a0.x,a0.y,a0.z,a0.w, a1.x,a1.y,a1.z,a1.w};
                #pragma unroll
                for (int i = 0; i < 8; i++){
                    float2 ad = dup2(ar[i]);
                    #pragma unroll
                    for (int p = 0; p < 4; p++)
                        acc[i][p] = ffma2(ad, bb[p], acc[i][p]);
                }
            }
            __syncthreads();
        }
        #pragma unroll
        for (int i = 0; i < 8; i++){
            int mr = bm + mh*64 + ty*8 + i;
            float* op = out + (size_t)mr*256 + tx*8;
            const float* bz = bias_sm + tx*8;
            *(float4*)(op)   = make_float4(acc[i][0].x+bz[0], acc[i][0].y+bz[1],
                                           acc[i][1].x+bz[2], acc[i][1].y+bz[3]);
            *(float4*)(op+4) = make_float4(acc[i][2].x+bz[4], acc[i][2].y+bz[5],
                                           acc[i][3].x+bz[6], acc[i][3].y+bz[7]);
        }
    }
#endif
}

// ---------------- LSTM: 128 seqs / block, 512 threads, warp-local sync ----------------
template<bool WRITE_Y>
__global__ void __launch_bounds__(512, 1) k_lstm(const float* __restrict__ xproj,
                                                 const float* __restrict__ Whh,
                                                 float* __restrict__ y_out,
                                                 float* __restrict__ hn_out){
    extern __shared__ float sm[];
    float* Ws = sm;
    float* Hs = sm + 16384;
    const int tid = threadIdx.x;
    for (int i = tid; i < 16384; i += 512){ int g = i >> 6, k = i & 63; Ws[k*256 + g] = Whh[i]; }
    for (int i = tid; i < 64*HP; i += 512) Hs[i] = 0.f;
    __syncthreads();
    const int tx = tid & 15;
    const int ty = tid >> 4;
    const int s0 = blockIdx.x*128;
    const int sb = ty*4;
    float c[4][4]  = {};
    float hv[4][4] = {};
    for (int t = 0; t < WIN; t++){
        float2 ai[4][2], af[4][2], ag[4][2], ao[4][2];
        #pragma unroll
        for (int si = 0; si < 4; si++){
            const float* xp = xproj + ((size_t)t*BNS + (s0 + sb + si))*256 + tx*4;
            float4 vi = *(const float4*)(xp);
            float4 vf = *(const float4*)(xp + 64);
            float4 vg = *(const float4*)(xp + 128);
            float4 vo = *(const float4*)(xp + 192);
            ai[si][0]=make_float2(vi.x,vi.y); ai[si][1]=make_float2(vi.z,vi.w);
            af[si][0]=make_float2(vf.x,vf.y); af[si][1]=make_float2(vf.z,vf.w);
            ag[si][0]=make_float2(vg.x,vg.y); ag[si][1]=make_float2(vg.z,vg.w);
            ao[si][0]=make_float2(vo.x,vo.y); ao[si][1]=make_float2(vo.z,vo.w);
        }
        #pragma unroll 4
        for (int k = 0; k < 64; k++){
            float4 h4 = *(const float4*)&Hs[k*HP + sb];
            const float* wr = &Ws[k*256 + tx*4];
            float4 wi4 = *(const float4*)(wr);
            float4 wf4 = *(const float4*)(wr + 64);
            float4 wg4 = *(const float4*)(wr + 128);
            float4 wo4 = *(const float4*)(wr + 192);
            float2 wi0=make_float2(wi4.x,wi4.y), wi1=make_float2(wi4.z,wi4.w);
            float2 wf0=make_float2(wf4.x,wf4.y), wf1=make_float2(wf4.z,wf4.w);
            float2 wg0=make_float2(wg4.x,wg4.y), wg1=make_float2(wg4.z,wg4.w);
            float2 wo0=make_float2(wo4.x,wo4.y), wo1=make_float2(wo4.z,wo4.w);
            float hs[4] = {h4.x, h4.y, h4.z, h4.w};
            #pragma unroll
            for (int si = 0; si < 4; si++){
                float2 hd = dup2(hs[si]);
                ai[si][0]=ffma2(hd,wi0,ai[si][0]); ai[si][1]=ffma2(hd,wi1,ai[si][1]);
                af[si][0]=ffma2(hd,wf0,af[si][0]); af[si][1]=ffma2(hd,wf1,af[si][1]);
                ag[si][0]=ffma2(hd,wg0,ag[si][0]); ag[si][1]=ffma2(hd,wg1,ag[si][1]);
                ao[si][0]=ffma2(hd,wo0,ao[si][0]); ao[si][1]=ffma2(hd,wo1,ao[si][1]);
            }
        }
        __syncwarp();
        #pragma unroll
        for (int si = 0; si < 4; si++){
            float aiv[4]={ai[si][0].x, ai[si][0].y, ai[si][1].x, ai[si][1].y};
            float afv[4]={af[si][0].x, af[si][0].y, af[si][1].x, af[si][1].y};
            float agv[4]={ag[si][0].x, ag[si][0].y, ag[si][1].x, ag[si][1].y};
            float aov[4]={ao[si][0].x, ao[si][0].y, ao[si][1].x, ao[si][1].y};
            #pragma unroll
            for (int ji = 0; ji < 4; ji++){
                float iv = sigf(aiv[ji]);
                float fv = sigf(afv[ji]);
                float gv = tanhfast(agv[ji]);
                float ov = sigf(aov[ji]);
                float cc = fmaf(fv, c[si][ji], iv*gv);
                c[si][ji] = cc;
                hv[si][ji] = ov*tanhfast(cc);
            }
            if (WRITE_Y){
                float4 o = make_float4(hv[si][0], hv[si][1], hv[si][2], hv[si][3]);
                *(float4*)(y_out + ((size_t)t*BNS + s0 + sb + si)*HD + tx*4) = o;
            }
        }
        #pragma unroll
        for (int ji = 0; ji < 4; ji++){
            float4 o = make_float4(hv[0][ji], hv[1][ji], hv[2][ji], hv[3][ji]);
            *(float4*)&Hs[(tx*4 + ji)*HP + sb] = o;
        }
        __syncwarp();
    }
    #pragma unroll
    for (int si = 0; si < 4; si++){
        float4 o = make_float4(hv[si][0], hv[si][1], hv[si][2], hv[si][3]);
        *(float4*)(hn_out + (size_t)(s0 + sb + si)*HD + tx*4) = o;
    }
}

// ---------------- FC head ----------------
__global__ void k_fc(const float* __restrict__ hn1, const float* __restrict__ hn2,
                     const float* __restrict__ inner, const float* __restrict__ x,
                     const float* __restrict__ fc1w, const float* __restrict__ fc1b,
                     const float* __restrict__ fc3w, const float* __restrict__ fc3b,
                     float* __restrict__ out){
    __shared__ float Z[4][232];
    __shared__ float red[4][64];
    const int s0 = blockIdx.x*4;
    const int tid = threadIdx.x;
    for (int idx = tid; idx < 4*FC1IN; idx += 256){
        int sl = idx/FC1IN, k = idx - sl*FC1IN;
        int s = s0 + sl;
        float v;
        if (k < 64)        v = hn1[(size_t)s*HD + k];
        else if (k < 128)  v = hn2[(size_t)s*HD + k - 64];
        else if (k == 128) v = inner[s];
        else {
            int si = k - 129;
            int w = si >> 3, f = si & 7;
            int b = s/NNODE, n = s - b*NNODE;
            v = x[((size_t)(b*WIN + w)*NNODE + n)*FIN + f];
        }
        Z[sl][k] = v;
    }
    __syncthreads();
    const int sl = tid >> 6, j = tid & 63;
    float acc = fc1b[j];
    #pragma unroll 5
    for (int k = 0; k < FC1IN; k++)
        acc = fmaf(Z[sl][k], fc1w[k*HD + j], acc);
    acc = fmaxf(acc, 0.f);
    red[sl][j] = acc*fc3w[j];
    __syncthreads();
    if (tid < 4){
        float ssum = fc3b[0];
        #pragma unroll
        for (int k = 0; k < 64; k++) ssum += red[tid][k];
        out[s0 + tid] = fmaxf(ssum, 0.f);
    }
}

// ---------------- launch ----------------
extern "C" void kernel_launch(void* const* d_in, const int* in_sizes, int n_in,
                              void* d_out, int out_size){
    const int*   adj   = (const int*)  d_in[0];
    const float* w     = (const float*)d_in[1];
    const float* x     = (const float*)d_in[2];
    const float* inner = (const float*)d_in[3];
    const float* W1    = (const float*)d_in[4];
    const float* b1    = (const float*)d_in[5];
    const float* W2    = (const float*)d_in[6];
    const float* b2    = (const float*)d_in[7];
    const float* gm1   = (const float*)d_in[8];
    const float* bt1   = (const float*)d_in[9];
    const float* gm2   = (const float*)d_in[10];
    const float* bt2   = (const float*)d_in[11];
    const float* Wih1  = (const float*)d_in[12];
    const float* Whh1  = (const float*)d_in[13];
    const float* bih1  = (const float*)d_in[14];
    const float* bhh1  = (const float*)d_in[15];
    const float* Wih2  = (const float*)d_in[16];
    const float* Whh2  = (const float*)d_in[17];
    const float* bih2  = (const float*)d_in[18];
    const float* bhh2  = (const float*)d_in[19];
    const float* fc1w  = (const float*)d_in[20];
    const float* fc1b  = (const float*)d_in[21];
    const float* fc3w  = (const float*)d_in[22];
    const float* fc3b  = (const float*)d_in[23];
    float* out = (float*)d_out;

    float *deg,*dis,*xw,*agg1,*agg2,*stats,*xproj,*y1,*hn1,*hn2,*whi1,*wlo1,*whi2,*wlo2;
    int *cnt,*rowstart,*cursor,*bsum; int2 *edata;
    cudaGetSymbolAddress((void**)&deg,   g_deg);
    cudaGetSymbolAddress((void**)&dis,   g_dis);
    cudaGetSymbolAddress((void**)&xw,    g_xw);
    cudaGetSymbolAddress((void**)&agg1,  g_agg1);
    cudaGetSymbolAddress((void**)&agg2,  g_agg2);
    cudaGetSymbolAddress((void**)&stats, g_stats);
    cudaGetSymbolAddress((void**)&xproj, g_xproj);
    cudaGetSymbolAddress((void**)&y1,    g_y1);
    cudaGetSymbolAddress((void**)&hn1,   g_hn1);
    cudaGetSymbolAddress((void**)&hn2,   g_hn2);
    cudaGetSymbolAddress((void**)&whi1,  g_whi1);
    cudaGetSymbolAddress((void**)&wlo1,  g_wlo1);
    cudaGetSymbolAddress((void**)&whi2,  g_whi2);
    cudaGetSymbolAddress((void**)&wlo2,  g_wlo2);
    cudaGetSymbolAddress((void**)&cnt,      g_cnt);
    cudaGetSymbolAddress((void**)&rowstart, g_rowstart);
    cudaGetSymbolAddress((void**)&cursor,   g_cursor);
    cudaGetSymbolAddress((void**)&bsum,     g_bsum);
    cudaGetSymbolAddress((void**)&edata,    g_edata);
    int* boff = bsum + 512;

    cudaFuncSetAttribute(k_lstm<true>,  cudaFuncAttributeMaxDynamicSharedMemorySize, LSTM_SMEM);
    cudaFuncSetAttribute(k_lstm<false>, cudaFuncAttributeMaxDynamicSharedMemorySize, LSTM_SMEM);
    cudaFuncSetAttribute(k_gemm_tc<128,true>,  cudaFuncAttributeMaxDynamicSharedMemorySize, TC_SMEM);
    cudaFuncSetAttribute(k_gemm_tc<64,false>,  cudaFuncAttributeMaxDynamicSharedMemorySize, TC_SMEM);

    // degree + CSR build + weight splits
    k_init     <<<NBLK, 256>>>(deg, cnt);
    k_deg_hist <<<7813, 256>>>(adj + NE, w, deg, cnt);
    k_dis      <<<NBLK, 256>>>(deg, dis);
    k_scan_a   <<<NBLK, 256>>>(cnt, bsum);
    k_scan_b   <<<1, 1024>>>(bsum, boff, rowstart);
    k_scan_c   <<<NBLK, 256>>>(cnt, boff, rowstart, cursor);
    k_scatter  <<<7813, 256>>>(adj, adj + NE, w, dis, cursor, edata);
    k_split_w  <<<128, 256>>>(Wih1, 256*128, whi1, wlo1);
    k_split_w  <<<64, 256>>>(Wih2, 256*64, whi2, wlo2);

    // GCN layer 1 (stats fused into gather)
    k_xw1       <<<375, 256>>>(x, W1, xw);
    k_agg_gather<<<24000, 256>>>(xw, dis, rowstart, edata, agg1, b1, stats);
    k_bn_fin    <<<1, 64>>>(gm1, bt1, stats);

    // GCN layer 2
    k_xw2g      <<<3000, 256>>>(agg1, W2, b1, stats, xw);
    k_agg_gather<<<24000, 256>>>(xw, dis, rowstart, edata, agg2, b2, stats + 256);
    k_bn_fin    <<<1, 64>>>(gm2, bt2, stats + 256);

    // LSTM 1 (tensor-core gate GEMM gathers bn1(agg1)|bn2(agg2))
    k_gemm_tc<128, true><<<1500, 256, TC_SMEM>>>(agg1, agg2, whi1, wlo1, bih1, bhh1, b1, b2, stats, xproj);
    k_lstm<true><<<125, 512, LSTM_SMEM>>>(xproj, Whh1, y1, hn1);

    // LSTM 2
    k_gemm_tc<64, false><<<1500, 256, TC_SMEM>>>(y1, y1, whi2, wlo2, bih2, bhh2, nullptr, nullptr, nullptr, xproj);
    k_lstm<false><<<125, 512, LSTM_SMEM>>>(xproj, Whh2, nullptr, hn2);

    // FC head
    k_fc<<<4000, 256>>>(hn1, hn2, inner, x, fc1w, fc1b, fc3w, fc3b, out);
}

// round 13
// speedup vs baseline: 1.0076x; 1.0076x over previous
#include <cuda_runtime.h>
#include <cstdint>

#define BB     8
#define WIN    12
#define NNODE  2000
#define FIN    8
#define HD     64
#define NTOT   192000          // BB*WIN*NNODE
#define NE     2000000
#define BNS    16000           // BB*NNODE sequences
#define BNEPS  1e-5f
#define FC1IN  225
#define NBLK   750             // NTOT/256
#define HP     132             // LSTM Hs seq pitch
#define LSTM_SMEM ((16384 + 64*HP)*4)

// tc-gemm smem layout (bytes)
#define TC_AHI   4096
#define TC_ALO   20480
#define TC_WHI   36864
#define TC_WLO   69632
#define TC_SMEM  102400
#define TC_IDESC 0x8400910u     // kind::tf32, f32 D, M=128, N=256, K-major both

#if defined(__CUDA_ARCH_FEAT_SM103_ALL) || defined(__CUDA_ARCH_FEAT_SM100_ALL)
#define HAS_TCGEN05 1
#else
#define HAS_TCGEN05 0
#endif

// ---------------- scratch (device globals; allocation-free) ----------------
__device__ float g_deg[NTOT];
__device__ float g_dis[NTOT];
__device__ float g_xw  [NTOT*HD];
__device__ float g_agg1[NTOT*HD];
__device__ float g_agg2[NTOT*HD];
__device__ float g_stats[512];
__device__ float g_xproj[(size_t)WIN*BNS*4*HD];
__device__ float g_y1  [(size_t)WIN*BNS*HD];
__device__ float g_hn1 [BNS*HD];
__device__ float g_hn2 [BNS*HD];
__device__ float g_whi1[256*128];
__device__ float g_wlo1[256*128];
__device__ float g_whi2[256*64];
__device__ float g_wlo2[256*64];
// CSR scratch
__device__ int   g_cnt[NTOT];
__device__ int   g_rowstart[NTOT+1];
__device__ int   g_cursor[NTOT];
__device__ int   g_bsum[1024];
__device__ int2  g_edata[NE];

// ---------------- helpers ----------------
__device__ __forceinline__ float sigf(float x)  { return __fdividef(1.f, 1.f + __expf(-x)); }
__device__ __forceinline__ float tanhfast(float x){ return 1.f - __fdividef(2.f, __expf(2.f*x) + 1.f); }

__device__ __forceinline__ float2 ffma2(float2 a, float2 b, float2 c){
    float2 d;
    asm("fma.rn.f32x2 %0, %1, %2, %3;"
        : "=l"(reinterpret_cast<unsigned long long&>(d))
        : "l"(reinterpret_cast<unsigned long long&>(a)),
          "l"(reinterpret_cast<unsigned long long&>(b)),
          "l"(reinterpret_cast<unsigned long long&>(c)));
    return d;
}
__device__ __forceinline__ float2 dup2(float x){ return make_float2(x, x); }
__device__ __forceinline__ void fma4(float (&a)[4], float h, float4 w){
    a[0]=fmaf(h,w.x,a[0]); a[1]=fmaf(h,w.y,a[1]); a[2]=fmaf(h,w.z,a[2]); a[3]=fmaf(h,w.w,a[3]);
}
__device__ __forceinline__ float tf32r(float x){
    uint32_t u; asm("cvt.rna.tf32.f32 %0, %1;" : "=r"(u) : "f"(x));
    return __uint_as_float(u);
}

#if HAS_TCGEN05
__device__ __forceinline__ uint32_t smem_u32(const void* p){
    uint32_t a;
    asm("{ .reg .u64 t; cvta.to.shared.u64 t, %1; cvt.u32.u64 %0, t; }" : "=r"(a) : "l"(p));
    return a;
}
__device__ __forceinline__ uint32_t swz128(uint32_t off){ return off ^ ((off >> 3) & 0x70); }
__device__ __forceinline__ uint64_t mk_desc(uint32_t addr){
    return ((uint64_t)2 << 61) | ((uint64_t)1 << 46) | ((uint64_t)64 << 32) | ((uint64_t)1 << 16)
         | ((uint64_t)(addr >> 4) & 0x3FFF);
}
__device__ __forceinline__ void mma_tf32(uint32_t d, uint64_t ad, uint64_t bd, uint32_t en){
    asm volatile(
        "{\n\t.reg .pred p;\n\tsetp.ne.u32 p, %5, 0;\n\t"
        "tcgen05.mma.cta_group::1.kind::tf32 [%0], %1, %2, %3, {%4, %4, %4, %4}, p;\n\t}"
        :: "r"(d), "l"(ad), "l"(bd), "r"(TC_IDESC), "r"(0u), "r"(en) : "memory");
}
__device__ __forceinline__ void mbar_wait(uint32_t mb, uint32_t parity){
    asm volatile(
        "{\n\t.reg .pred P1;\n\t"
        "W_%=:\n\t"
        "mbarrier.try_wait.parity.acquire.cta.shared::cta.b64 P1, [%0], %1;\n\t"
        "@!P1 bra W_%=;\n\t}"
        :: "r"(mb), "r"(parity) : "memory");
}
#define LDTM_X32(r, addr) \
    asm volatile("tcgen05.ld.sync.aligned.32x32b.x32.b32 " \
        "{%0,%1,%2,%3,%4,%5,%6,%7,%8,%9,%10,%11,%12,%13,%14,%15," \
        "%16,%17,%18,%19,%20,%21,%22,%23,%24,%25,%26,%27,%28,%29,%30,%31}, [%32];" \
        : "=r"((r)[0]),"=r"((r)[1]),"=r"((r)[2]),"=r"((r)[3]),"=r"((r)[4]),"=r"((r)[5]),"=r"((r)[6]),"=r"((r)[7]), \
          "=r"((r)[8]),"=r"((r)[9]),"=r"((r)[10]),"=r"((r)[11]),"=r"((r)[12]),"=r"((r)[13]),"=r"((r)[14]),"=r"((r)[15]), \
          "=r"((r)[16]),"=r"((r)[17]),"=r"((r)[18]),"=r"((r)[19]),"=r"((r)[20]),"=r"((r)[21]),"=r"((r)[22]),"=r"((r)[23]), \
          "=r"((r)[24]),"=r"((r)[25]),"=r"((r)[26]),"=r"((r)[27]),"=r"((r)[28]),"=r"((r)[29]),"=r"((r)[30]),"=r"((r)[31]) \
        : "r"(addr))
#endif

// ---------------- fused init: deg/cnt/stats + tf32 splits of both Wih ----------------
__global__ void k_initall(float* deg, int* cnt,
                          const float* __restrict__ Wih1, float* __restrict__ whi1, float* __restrict__ wlo1,
                          const float* __restrict__ Wih2, float* __restrict__ whi2, float* __restrict__ wlo2){
    int i = blockIdx.x*blockDim.x + threadIdx.x;
    if (i < NTOT){ deg[i] = 1.0f; cnt[i] = 0; }
    if (i < 512) g_stats[i] = 0.f;
    if (i < 256*128){
        float v = Wih1[i];
        float h = tf32r(v);
        whi1[i] = h; wlo1[i] = v - h;
    }
    if (i < 256*64){
        float v = Wih2[i];
        float h = tf32r(v);
        whi2[i] = h; wlo2[i] = v - h;
    }
}
__global__ void k_deg_hist(const int* __restrict__ col, const float* __restrict__ w,
                           float* deg, int* cnt){
    int e = blockIdx.x*blockDim.x + threadIdx.x;
    if (e < NE){
        int c = col[e];
        atomicAdd(&deg[c], w[e]);
        atomicAdd(&cnt[c], 1);
    }
}
// fused: dis = rsqrt(deg) + per-block cnt sums (same grid shape as old k_scan_a)
__global__ void k_dis_scan(const float* __restrict__ deg, float* dis,
                           const int* __restrict__ cnt, int* bsum){
    __shared__ int sh[256];
    int t = threadIdx.x;
    int i = blockIdx.x*256 + t;
    float d = deg[i];
    dis[i] = (d > 0.f) ? rsqrtf(d) : 0.f;
    sh[t] = cnt[i];
    __syncthreads();
    #pragma unroll
    for (int off = 128; off > 0; off >>= 1){
        if (t < off) sh[t] += sh[t + off];
        __syncthreads();
    }
    if (t == 0) bsum[blockIdx.x] = sh[0];
}
__global__ void k_scan_b(const int* __restrict__ bsum, int* boff, int* rowstart){
    __shared__ int sh[1024];
    int t = threadIdx.x;
    int v = (t < NBLK) ? bsum[t] : 0;
    sh[t] = v;
    __syncthreads();
    #pragma unroll
    for (int off = 1; off < 1024; off <<= 1){
        int x = (t >= off) ? sh[t - off] : 0;
        __syncthreads();
        sh[t] += x;
        __syncthreads();
    }
    if (t < NBLK) boff[t] = sh[t] - v;
    if (t == 0) rowstart[NTOT] = NE;
}
__global__ void k_scan_c(const int* __restrict__ cnt, const int* __restrict__ boff,
                         int* rowstart, int* cursor){
    __shared__ int sh[256];
    int t = threadIdx.x;
    int i = blockIdx.x*256 + t;
    int v = cnt[i];
    sh[t] = v;
    __syncthreads();
    #pragma unroll
    for (int off = 1; off < 256; off <<= 1){
        int x = (t >= off) ? sh[t - off] : 0;
        __syncthreads();
        sh[t] += x;
        __syncthreads();
    }
    int ex = boff[blockIdx.x] + sh[t] - v;
    rowstart[i] = ex;
    cursor[i]   = ex;
}
__global__ void k_scatter(const int* __restrict__ rows, const int* __restrict__ cols,
                          const float* __restrict__ w, const float* __restrict__ dis,
                          int* cursor, int2* edata){
    int e = blockIdx.x*blockDim.x + threadIdx.x;
    if (e >= NE) return;
    int r = rows[e], c = cols[e];
    float norm = dis[r]*w[e]*dis[c];
    int pos = atomicAdd(&cursor[c], 1);
    edata[pos] = make_int2(r, __float_as_int(norm));
}

// ---------------- xw = x @ W1  (K=8), 2 nodes per thread ----------------
__global__ void k_xw1(const float* __restrict__ x, const float* __restrict__ W, float* __restrict__ out){
    __shared__ float Ws[FIN*HD];
    for (int i = threadIdx.x; i < FIN*HD; i += blockDim.x) Ws[i] = W[i];
    __syncthreads();
    int base = (blockIdx.x*blockDim.x + threadIdx.x)*2;
    if (base >= NTOT) return;
    #pragma unroll
    for (int u = 0; u < 2; u++){
        int node = base + u;
        float xr[FIN];
        float4 v0 = *(const float4*)(x + (size_t)node*FIN);
        float4 v1 = *(const float4*)(x + (size_t)node*FIN + 4);
        xr[0]=v0.x; xr[1]=v0.y; xr[2]=v0.z; xr[3]=v0.w;
        xr[4]=v1.x; xr[5]=v1.y; xr[6]=v1.z; xr[7]=v1.w;
        #pragma unroll
        for (int j = 0; j < HD; j += 4){
            float a[4] = {0.f,0.f,0.f,0.f};
            #pragma unroll
            for (int k = 0; k < FIN; k++){
                float4 w4 = *(const float4*)&Ws[k*HD + j];
                fma4(a, xr[k], w4);
            }
            *(float4*)(out + (size_t)node*HD + j) = make_float4(a[0],a[1],a[2],a[3]);
        }
    }
}

// ---------------- aggregation: gather (warp per target node) + fused BN stats ----------------
__global__ void __launch_bounds__(256) k_agg_gather(const float* __restrict__ xw,
                                                    const float* __restrict__ dis,
                                                    const int* __restrict__ rowstart,
                                                    const int2* __restrict__ edata,
                                                    float* __restrict__ agg,
                                                    const float* __restrict__ bias,
                                                    float* __restrict__ stats){
    __shared__ float ss [8][64];
    __shared__ float ss2[8][64];
    const int tid = threadIdx.x;
    const int wrp = tid >> 5;
    const int lane = tid & 31;
    int gw = blockIdx.x*8 + wrp;
    float va = 0.f, vb = 0.f;
    if (gw < NTOT){
        int beg = rowstart[gw], end = rowstart[gw+1];
        float d = dis[gw];
        float2 v0 = *(const float2*)(xw + (size_t)gw*HD + lane*2);
        float sc = d*d;
        float2 acc = make_float2(v0.x*sc, v0.y*sc);
        int j = beg;
        for (; j + 2 <= end; j += 2){
            int2 e0 = edata[j], e1 = edata[j+1];
            float2 a = *(const float2*)(xw + (size_t)e0.x*HD + lane*2);
            float2 b = *(const float2*)(xw + (size_t)e1.x*HD + lane*2);
            float n0 = __int_as_float(e0.y), n1 = __int_as_float(e1.y);
            acc.x = fmaf(a.x, n0, acc.x); acc.y = fmaf(a.y, n0, acc.y);
            acc.x = fmaf(b.x, n1, acc.x); acc.y = fmaf(b.y, n1, acc.y);
        }
        if (j < end){
            int2 e0 = edata[j];
            float2 a = *(const float2*)(xw + (size_t)e0.x*HD + lane*2);
            float n0 = __int_as_float(e0.y);
            acc.x = fmaf(a.x, n0, acc.x); acc.y = fmaf(a.y, n0, acc.y);
        }
        *(float2*)(agg + (size_t)gw*HD + lane*2) = acc;
        va = fmaxf(acc.x + bias[lane*2],   0.f);
        vb = fmaxf(acc.y + bias[lane*2+1], 0.f);
    }
    ss [wrp][lane*2]   = va;
    ss [wrp][lane*2+1] = vb;
    ss2[wrp][lane*2]   = va*va;
    ss2[wrp][lane*2+1] = vb*vb;
    __syncthreads();
    if (tid < 64){
        float s = 0.f, s2 = 0.f;
        #pragma unroll
        for (int w = 0; w < 8; w++){ s += ss[w][tid]; s2 += ss2[w][tid]; }
        atomicAdd(&stats[tid], s);
        atomicAdd(&stats[64+tid], s2);
    }
}

__global__ void k_bn_fin(const float* __restrict__ gamma, const float* __restrict__ beta,
                         float* __restrict__ stats){
    int ch = threadIdx.x;
    if (ch < 64){
        const float invN = 1.f/(float)NTOT;
        float m = stats[ch]*invN;
        float var = stats[64+ch]*invN - m*m;
        float sc = gamma[ch]*rsqrtf(var + BNEPS);
        stats[128+ch] = sc;
        stats[192+ch] = beta[ch] - m*sc;
    }
}

// ---------------- xw2 = bn1(agg1) @ W2  (tiled 64x64, f32x2, fused BN) ----------------
__global__ void __launch_bounds__(256) k_xw2g(const float* __restrict__ A, const float* __restrict__ W,
                                              const float* __restrict__ bias, const float* __restrict__ stats,
                                              float* __restrict__ out){
    __shared__ float As[16][64];
    __shared__ float Bs[16][68];
    __shared__ float bnb[64], bns[64], bnh[64];
    const int tid = threadIdx.x;
    if (tid < 64){ bnb[tid] = bias[tid]; bns[tid] = stats[128+tid]; bnh[tid] = stats[192+tid]; }
    __syncthreads();
    const int bm = blockIdx.x*64;
    const int lr = tid >> 2, lk = (tid & 3)*4;
    const int m  = bm + lr;
    const int ty = tid >> 4, tx = tid & 15;
    float2 acc[4][2] = {};
    for (int k0 = 0; k0 < HD; k0 += 16){
        float4 av = *(const float4*)(A + (size_t)m*HD + k0 + lk);
        int cb = k0 + lk;
        av.x = fmaxf(av.x + bnb[cb+0], 0.f)*bns[cb+0] + bnh[cb+0];
        av.y = fmaxf(av.y + bnb[cb+1], 0.f)*bns[cb+1] + bnh[cb+1];
        av.z = fmaxf(av.z + bnb[cb+2], 0.f)*bns[cb+2] + bnh[cb+2];
        av.w = fmaxf(av.w + bnb[cb+3], 0.f)*bns[cb+3] + bnh[cb+3];
        As[lk+0][lr]=av.x; As[lk+1][lr]=av.y; As[lk+2][lr]=av.z; As[lk+3][lr]=av.w;
        int kk = tid >> 4, n4 = (tid & 15)*4;
        float4 bv = *(const float4*)(W + (size_t)(k0+kk)*HD + n4);
        Bs[kk][n4+0]=bv.x; Bs[kk][n4+1]=bv.y; Bs[kk][n4+2]=bv.z; Bs[kk][n4+3]=bv.w;
        __syncthreads();
        #pragma unroll
        for (int q = 0; q < 16; q++){
            float4 a4 = *(const float4*)&As[q][ty*4];
            float4 b4 = *(const float4*)&Bs[q][tx*4];
            float2 bb0 = make_float2(b4.x, b4.y), bb1 = make_float2(b4.z, b4.w);
            float ar[4] = {a4.x, a4.y, a4.z, a4.w};
            #pragma unroll
            for (int i = 0; i < 4; i++){
                float2 ad = dup2(ar[i]);
                acc[i][0] = ffma2(ad, bb0, acc[i][0]);
                acc[i][1] = ffma2(ad, bb1, acc[i][1]);
            }
        }
        __syncthreads();
    }
    #pragma unroll
    for (int i = 0; i < 4; i++){
        int mr = bm + ty*4 + i;
        *(float4*)(out + (size_t)mr*HD + tx*4) =
            make_float4(acc[i][0].x, acc[i][0].y, acc[i][1].x, acc[i][1].y);
    }
}

// ---------------- gate GEMM: out[m][256] = A[m][KD] @ W^T + bias ----------------
template<int KD, bool GATHER>
__global__ void __launch_bounds__(256, 2)
k_gemm_tc(const float* __restrict__ A0, const float* __restrict__ A1,
          const float* __restrict__ whi, const float* __restrict__ wlo,
          const float* __restrict__ bih, const float* __restrict__ bhh,
          const float* __restrict__ b1, const float* __restrict__ b2,
          const float* __restrict__ stats,
          float* __restrict__ out){
    extern __shared__ float sm[];
    float* bias_sm = sm + 64;           // 256 floats
    float* bnb = sm + 320; float* bns = sm + 448; float* bnh = sm + 576;
    const int tid = threadIdx.x;

    if (tid < 128){
        bias_sm[tid]     = bih[tid]     + bhh[tid];
        bias_sm[128+tid] = bih[128+tid] + bhh[128+tid];
    }
    if (GATHER && tid < 64){
        bnb[tid]    = b1[tid]; bns[tid]    = stats[128+tid]; bnh[tid]    = stats[192+tid];
        bnb[64+tid] = b2[tid]; bns[64+tid] = stats[384+tid]; bnh[64+tid] = stats[448+tid];
    }

#if HAS_TCGEN05
    char* smc = (char*)sm;
    const uint32_t sb = smem_u32(sm);
    const uint32_t mb = sb + 8;
    const int wid = tid >> 5, lane = tid & 31;
    if (wid == 0){
        asm volatile("tcgen05.alloc.cta_group::1.sync.aligned.shared::cta.b32 [%0], %1;"
                     :: "r"(sb), "r"(256u) : "memory");
        asm volatile("tcgen05.relinquish_alloc_permit.cta_group::1.sync.aligned;" ::: "memory");
    }
    if (tid == 0)
        asm volatile("mbarrier.init.shared.b64 [%0], %1;" :: "r"(mb), "r"(1u) : "memory");
    __syncthreads();
    uint32_t tmem;
    asm volatile("ld.shared.b32 %0, [%1];" : "=r"(tmem) : "r"(sb));

    const int bm = blockIdx.x*128;
    const int row = tid >> 1;
    const int j4  = (tid & 1)*4;
    const int m = bm + row;
    size_t aoff;
    if (GATHER){
        int t = m/BNS, s = m - t*BNS;
        int b = s/NNODE, n = s - b*NNODE;
        aoff = (size_t)((b*WIN + t)*NNODE + n)*HD;
    } else {
        aoff = (size_t)m*KD;
    }

    const uint64_t dAH = mk_desc(sb + TC_AHI), dAL = mk_desc(sb + TC_ALO);
    const uint64_t dWH = mk_desc(sb + TC_WHI), dWL = mk_desc(sb + TC_WLO);
    const int NCH = KD/32;
    uint32_t parity = 0;
    const uint32_t arow = (uint32_t)((row>>3)*1024 + (row&7)*128);

    for (int c = 0; c < NCH; c++){
        const int k0 = c*32;
        const float* abase = GATHER ? ((k0 < 64) ? A0 : A1) : A0;
        const int koff = GATHER ? (k0 & 63) : k0;
        #pragma unroll
        for (int u = 0; u < 4; u++){
            int j = j4 + u;
            float4 v = *(const float4*)(abase + aoff + koff + j*4);
            if (GATHER){
                int k = k0 + j*4;
                v.x = fmaxf(v.x + bnb[k+0], 0.f)*bns[k+0] + bnh[k+0];
                v.y = fmaxf(v.y + bnb[k+1], 0.f)*bns[k+1] + bnh[k+1];
                v.z = fmaxf(v.z + bnb[k+2], 0.f)*bns[k+2] + bnh[k+2];
                v.w = fmaxf(v.w + bnb[k+3], 0.f)*bns[k+3] + bnh[k+3];
            }
            float4 hi, lo;
            hi.x = tf32r(v.x); lo.x = v.x - hi.x;
            hi.y = tf32r(v.y); lo.y = v.y - hi.y;
            hi.z = tf32r(v.z); lo.z = v.z - hi.z;
            hi.w = tf32r(v.w); lo.w = v.w - hi.w;
            uint32_t sw = swz128(arow + j*16);
            *(float4*)(smc + TC_AHI + sw) = hi;
            *(float4*)(smc + TC_ALO + sw) = lo;
        }
        for (int idx = tid; idx < 2048; idx += 256){
            int g = idx >> 3, j = idx & 7;
            float4 vh = *(const float4*)(whi + (size_t)g*KD + k0 + j*4);
            float4 vl = *(const float4*)(wlo + (size_t)g*KD + k0 + j*4);
            uint32_t sw = swz128((uint32_t)((g>>3)*1024 + (g&7)*128 + j*16));
            *(float4*)(smc + TC_WHI + sw) = vh;
            *(float4*)(smc + TC_WLO + sw) = vl;
        }
        __syncthreads();
        if (tid == 0){
            asm volatile("fence.proxy.async.shared::cta;" ::: "memory");
            #pragma unroll
            for (int s = 0; s < 4; s++){
                uint64_t oa = (uint64_t)(2*s);
                uint32_t en0 = (c == 0 && s == 0) ? 0u : 1u;
                mma_tf32(tmem, dAH + oa, dWH + oa, en0);
                mma_tf32(tmem, dAH + oa, dWL + oa, 1u);
                mma_tf32(tmem, dAL + oa, dWH + oa, 1u);
            }
            asm volatile("tcgen05.commit.cta_group::1.mbarrier::arrive::one.shared::cluster.b64 [%0];"
                         :: "r"(mb) : "memory");
        }
        mbar_wait(mb, parity);
        parity ^= 1;
    }

    asm volatile("tcgen05.fence::after_thread_sync;" ::: "memory");
    {
        // all 8 warps: subpartition = wid&3 (rows), column half = wid>>2
        int mrow = bm + (wid & 3)*32 + lane;
        int cb   = (wid >> 2)*4;            // column blocks [cb, cb+4)
        float* op = out + (size_t)mrow*256;
        for (int b = cb; b < cb + 4; b++){
            uint32_t r[32];
            LDTM_X32(r, tmem + b*32);
            asm volatile("tcgen05.wait::ld.sync.aligned;" ::: "memory");
            #pragma unroll
            for (int q = 0; q < 8; q++){
                float4 o;
                o.x = __uint_as_float(r[q*4+0]) + bias_sm[b*32 + q*4+0];
                o.y = __uint_as_float(r[q*4+1]) + bias_sm[b*32 + q*4+1];
                o.z = __uint_as_float(r[q*4+2]) + bias_sm[b*32 + q*4+2];
                o.w = __uint_as_float(r[q*4+3]) + bias_sm[b*32 + q*4+3];
                *(float4*)(op + b*32 + q*4) = o;
            }
        }
    }
    __syncthreads();
    if (tid == 0)
        asm volatile("mbarrier.inval.shared.b64 [%0];" :: "r"(mb) : "memory");
    __syncthreads();
    if (wid == 0)
        asm volatile("tcgen05.dealloc.cta_group::1.sync.aligned.b32 %0, %1;"
                     :: "r"(tmem), "r"(256u) : "memory");
#else
    // -------- FFMA2 fallback --------
    float* As = sm + 1024;                 // [16][68]
    float* Bs = sm + 1024 + 16*68;         // [16][260]
    __syncthreads();
    const int bm = blockIdx.x*128;
    const int lr = tid >> 2, lk = (tid & 3)*4;
    const int ty = tid >> 5, tx = tid & 31;
    for (int mh = 0; mh < 2; mh++){
        const int m = bm + mh*64 + lr;
        size_t aoff;
        if (GATHER){
            int t = m/BNS, s = m - t*BNS;
            int b = s/NNODE, n = s - b*NNODE;
            aoff = (size_t)((b*WIN + t)*NNODE + n)*HD;
        } else aoff = (size_t)m*KD;
        float2 acc[8][4] = {};
        for (int k0 = 0; k0 < KD; k0 += 16){
            int k = k0 + lk;
            const float* abase = GATHER ? ((k < 64) ? A0 : A1) : A0;
            int ko = GATHER ? (k & 63) : k;
            float4 v = *(const float4*)(abase + aoff + ko);
            if (GATHER){
                v.x = fmaxf(v.x + bnb[k+0], 0.f)*bns[k+0] + bnh[k+0];
                v.y = fmaxf(v.y + bnb[k+1], 0.f)*bns[k+1] + bnh[k+1];
                v.z = fmaxf(v.z + bnb[k+2], 0.f)*bns[k+2] + bnh[k+2];
                v.w = fmaxf(v.w + bnb[k+3], 0.f)*bns[k+3] + bnh[k+3];
            }
            As[(lk+0)*68 + lr] = v.x;
            As[(lk+1)*68 + lr] = v.y;
            As[(lk+2)*68 + lr] = v.z;
            As[(lk+3)*68 + lr] = v.w;
            for (int i = tid; i < 1024; i += 256){
                int g = i >> 2, kq = (i & 3)*4;
                float4 vh = *(const float4*)(whi + (size_t)g*KD + k0 + kq);
                float4 vl = *(const float4*)(wlo + (size_t)g*KD + k0 + kq);
                Bs[(kq+0)*260 + g] = vh.x + vl.x;
                Bs[(kq+1)*260 + g] = vh.y + vl.y;
                Bs[(kq+2)*260 + g] = vh.z + vl.z;
                Bs[(kq+3)*260 + g] = vh.w + vl.w;
            }
            __syncthreads();
            #pragma unroll
            for (int kk = 0; kk < 16; kk++){
                float4 a0 = *(const float4*)&As[kk*68 + ty*8];
                float4 a1 = *(const float4*)&As[kk*68 + ty*8 + 4];
                float4 b0 = *(const float4*)&Bs[kk*260 + tx*8];
                float4 b1v = *(const float4*)&Bs[kk*260 + tx*8 + 4];
                float2 bb[4] = {make_float2(b0.x,b0.y), make_float2(b0.z,b0.w),
                                make_float2(b1v.x,b1v.y), make_float2(b1v.z,b1v.w)};
                float ar[8] = {a0.x,a0.y,a0.z,a0.w, a1.x,a1.y,a1.z,a1.w};
                #pragma unroll
                for (int i = 0; i < 8; i++){
                    float2 ad = dup2(ar[i]);
                    #pragma unroll
                    for (int p = 0; p < 4; p++)
                        acc[i][p] = ffma2(ad, bb[p], acc[i][p]);
                }
            }
            __syncthreads();
        }
        #pragma unroll
        for (int i = 0; i < 8; i++){
            int mr = bm + mh*64 + ty*8 + i;
            float* op = out + (size_t)mr*256 + tx*8;
            const float* bz = bias_sm + tx*8;
            *(float4*)(op)   = make_float4(acc[i][0].x+bz[0], acc[i][0].y+bz[1],
                                           acc[i][1].x+bz[2], acc[i][1].y+bz[3]);
            *(float4*)(op+4) = make_float4(acc[i][2].x+bz[4], acc[i][2].y+bz[5],
                                           acc[i][3].x+bz[6], acc[i][3].y+bz[7]);
        }
    }
#endif
}

// ---------------- LSTM: 128 seqs / block, 512 threads, warp-local sync ----------------
template<bool WRITE_Y>
__global__ void __launch_bounds__(512, 1) k_lstm(const float* __restrict__ xproj,
                                                 const float* __restrict__ Whh,
                                                 float* __restrict__ y_out,
                                                 float* __restrict__ hn_out){
    extern __shared__ float sm[];
    float* Ws = sm;
    float* Hs = sm + 16384;
    const int tid = threadIdx.x;
    for (int i = tid; i < 16384; i += 512){ int g = i >> 6, k = i & 63; Ws[k*256 + g] = Whh[i]; }
    for (int i = tid; i < 64*HP; i += 512) Hs[i] = 0.f;
    __syncthreads();
    const int tx = tid & 15;
    const int ty = tid >> 4;
    const int s0 = blockIdx.x*128;
    const int sb = ty*4;
    float c[4][4]  = {};
    float hv[4][4] = {};
    for (int t = 0; t < WIN; t++){
        float2 ai[4][2], af[4][2], ag[4][2], ao[4][2];
        #pragma unroll
        for (int si = 0; si < 4; si++){
            const float* xp = xproj + ((size_t)t*BNS + (s0 + sb + si))*256 + tx*4;
            float4 vi = *(const float4*)(xp);
            float4 vf = *(const float4*)(xp + 64);
            float4 vg = *(const float4*)(xp + 128);
            float4 vo = *(const float4*)(xp + 192);
            ai[si][0]=make_float2(vi.x,vi.y); ai[si][1]=make_float2(vi.z,vi.w);
            af[si][0]=make_float2(vf.x,vf.y); af[si][1]=make_float2(vf.z,vf.w);
            ag[si][0]=make_float2(vg.x,vg.y); ag[si][1]=make_float2(vg.z,vg.w);
            ao[si][0]=make_float2(vo.x,vo.y); ao[si][1]=make_float2(vo.z,vo.w);
        }
        #pragma unroll 4
        for (int k = 0; k < 64; k++){
            float4 h4 = *(const float4*)&Hs[k*HP + sb];
            const float* wr = &Ws[k*256 + tx*4];
            float4 wi4 = *(const float4*)(wr);
            float4 wf4 = *(const float4*)(wr + 64);
            float4 wg4 = *(const float4*)(wr + 128);
            float4 wo4 = *(const float4*)(wr + 192);
            float2 wi0=make_float2(wi4.x,wi4.y), wi1=make_float2(wi4.z,wi4.w);
            float2 wf0=make_float2(wf4.x,wf4.y), wf1=make_float2(wf4.z,wf4.w);
            float2 wg0=make_float2(wg4.x,wg4.y), wg1=make_float2(wg4.z,wg4.w);
            float2 wo0=make_float2(wo4.x,wo4.y), wo1=make_float2(wo4.z,wo4.w);
            float hs[4] = {h4.x, h4.y, h4.z, h4.w};
            #pragma unroll
            for (int si = 0; si < 4; si++){
                float2 hd = dup2(hs[si]);
                ai[si][0]=ffma2(hd,wi0,ai[si][0]); ai[si][1]=ffma2(hd,wi1,ai[si][1]);
                af[si][0]=ffma2(hd,wf0,af[si][0]); af[si][1]=ffma2(hd,wf1,af[si][1]);
                ag[si][0]=ffma2(hd,wg0,ag[si][0]); ag[si][1]=ffma2(hd,wg1,ag[si][1]);
                ao[si][0]=ffma2(hd,wo0,ao[si][0]); ao[si][1]=ffma2(hd,wo1,ao[si][1]);
            }
        }
        __syncwarp();
        #pragma unroll
        for (int si = 0; si < 4; si++){
            float aiv[4]={ai[si][0].x, ai[si][0].y, ai[si][1].x, ai[si][1].y};
            float afv[4]={af[si][0].x, af[si][0].y, af[si][1].x, af[si][1].y};
            float agv[4]={ag[si][0].x, ag[si][0].y, ag[si][1].x, ag[si][1].y};
            float aov[4]={ao[si][0].x, ao[si][0].y, ao[si][1].x, ao[si][1].y};
            #pragma unroll
            for (int ji = 0; ji < 4; ji++){
                float iv = sigf(aiv[ji]);
                float fv = sigf(afv[ji]);
                float gv = tanhfast(agv[ji]);
                float ov = sigf(aov[ji]);
                float cc = fmaf(fv, c[si][ji], iv*gv);
                c[si][ji] = cc;
                hv[si][ji] = ov*tanhfast(cc);
            }
            if (WRITE_Y){
                float4 o = make_float4(hv[si][0], hv[si][1], hv[si][2], hv[si][3]);
                *(float4*)(y_out + ((size_t)t*BNS + s0 + sb + si)*HD + tx*4) = o;
            }
        }
        #pragma unroll
        for (int ji = 0; ji < 4; ji++){
            float4 o = make_float4(hv[0][ji], hv[1][ji], hv[2][ji], hv[3][ji]);
            *(float4*)&Hs[(tx*4 + ji)*HP + sb] = o;
        }
        __syncwarp();
    }
    #pragma unroll
    for (int si = 0; si < 4; si++){
        float4 o = make_float4(hv[si][0], hv[si][1], hv[si][2], hv[si][3]);
        *(float4*)(hn_out + (size_t)(s0 + sb + si)*HD + tx*4) = o;
    }
}

// ---------------- FC head ----------------
__global__ void k_fc(const float* __restrict__ hn1, const float* __restrict__ hn2,
                     const float* __restrict__ inner, const float* __restrict__ x,
                     const float* __restrict__ fc1w, const float* __restrict__ fc1b,
                     const float* __restrict__ fc3w, const float* __restrict__ fc3b,
                     float* __restrict__ out){
    __shared__ float Z[4][232];
    __shared__ float red[4][64];
    const int s0 = blockIdx.x*4;
    const int tid = threadIdx.x;
    for (int idx = tid; idx < 4*FC1IN; idx += 256){
        int sl = idx/FC1IN, k = idx - sl*FC1IN;
        int s = s0 + sl;
        float v;
        if (k < 64)        v = hn1[(size_t)s*HD + k];
        else if (k < 128)  v = hn2[(size_t)s*HD + k - 64];
        else if (k == 128) v = inner[s];
        else {
            int si = k - 129;
            int w = si >> 3, f = si & 7;
            int b = s/NNODE, n = s - b*NNODE;
            v = x[((size_t)(b*WIN + w)*NNODE + n)*FIN + f];
        }
        Z[sl][k] = v;
    }
    __syncthreads();
    const int sl = tid >> 6, j = tid & 63;
    float acc = fc1b[j];
    #pragma unroll 5
    for (int k = 0; k < FC1IN; k++)
        acc = fmaf(Z[sl][k], fc1w[k*HD + j], acc);
    acc = fmaxf(acc, 0.f);
    red[sl][j] = acc*fc3w[j];
    __syncthreads();
    if (tid < 4){
        float ssum = fc3b[0];
        #pragma unroll
        for (int k = 0; k < 64; k++) ssum += red[tid][k];
        out[s0 + tid] = fmaxf(ssum, 0.f);
    }
}

// ---------------- launch ----------------
extern "C" void kernel_launch(void* const* d_in, const int* in_sizes, int n_in,
                              void* d_out, int out_size){
    const int*   adj   = (const int*)  d_in[0];
    const float* w     = (const float*)d_in[1];
    const float* x     = (const float*)d_in[2];
    const float* inner = (const float*)d_in[3];
    const float* W1    = (const float*)d_in[4];
    const float* b1    = (const float*)d_in[5];
    const float* W2    = (const float*)d_in[6];
    const float* b2    = (const float*)d_in[7];
    const float* gm1   = (const float*)d_in[8];
    const float* bt1   = (const float*)d_in[9];
    const float* gm2   = (const float*)d_in[10];
    const float* bt2   = (const float*)d_in[11];
    const float* Wih1  = (const float*)d_in[12];
    const float* Whh1  = (const float*)d_in[13];
    const float* bih1  = (const float*)d_in[14];
    const float* bhh1  = (const float*)d_in[15];
    const float* Wih2  = (const float*)d_in[16];
    const float* Whh2  = (const float*)d_in[17];
    const float* bih2  = (const float*)d_in[18];
    const float* bhh2  = (const float*)d_in[19];
    const float* fc1w  = (const float*)d_in[20];
    const float* fc1b  = (const float*)d_in[21];
    const float* fc3w  = (const float*)d_in[22];
    const float* fc3b  = (const float*)d_in[23];
    float* out = (float*)d_out;

    float *deg,*dis,*xw,*agg1,*agg2,*stats,*xproj,*y1,*hn1,*hn2,*whi1,*wlo1,*whi2,*wlo2;
    int *cnt,*rowstart,*cursor,*bsum; int2 *edata;
    cudaGetSymbolAddress((void**)&deg,   g_deg);
    cudaGetSymbolAddress((void**)&dis,   g_dis);
    cudaGetSymbolAddress((void**)&xw,    g_xw);
    cudaGetSymbolAddress((void**)&agg1,  g_agg1);
    cudaGetSymbolAddress((void**)&agg2,  g_agg2);
    cudaGetSymbolAddress((void**)&stats, g_stats);
    cudaGetSymbolAddress((void**)&xproj, g_xproj);
    cudaGetSymbolAddress((void**)&y1,    g_y1);
    cudaGetSymbolAddress((void**)&hn1,   g_hn1);
    cudaGetSymbolAddress((void**)&hn2,   g_hn2);
    cudaGetSymbolAddress((void**)&whi1,  g_whi1);
    cudaGetSymbolAddress((void**)&wlo1,  g_wlo1);
    cudaGetSymbolAddress((void**)&whi2,  g_whi2);
    cudaGetSymbolAddress((void**)&wlo2,  g_wlo2);
    cudaGetSymbolAddress((void**)&cnt,      g_cnt);
    cudaGetSymbolAddress((void**)&rowstart, g_rowstart);
    cudaGetSymbolAddress((void**)&cursor,   g_cursor);
    cudaGetSymbolAddress((void**)&bsum,     g_bsum);
    cudaGetSymbolAddress((void**)&edata,    g_edata);
    int* boff = bsum + 512;

    cudaFuncSetAttribute(k_lstm<true>,  cudaFuncAttributeMaxDynamicSharedMemorySize, LSTM_SMEM);
    cudaFuncSetAttribute(k_lstm<false>, cudaFuncAttributeMaxDynamicSharedMemorySize, LSTM_SMEM);
    cudaFuncSetAttribute(k_gemm_tc<128,true>,  cudaFuncAttributeMaxDynamicSharedMemorySize, TC_SMEM);
    cudaFuncSetAttribute(k_gemm_tc<64,false>,  cudaFuncAttributeMaxDynamicSharedMemorySize, TC_SMEM);

    // fused init (deg/cnt/stats + weight splits) + degree + CSR build
    k_initall  <<<NBLK, 256>>>(deg, cnt, Wih1, whi1, wlo1, Wih2, whi2, wlo2);
    k_deg_hist <<<7813, 256>>>(adj + NE, w, deg, cnt);
    k_dis_scan <<<NBLK, 256>>>(deg, dis, cnt, bsum);
    k_scan_b   <<<1, 1024>>>(bsum, boff, rowstart);
    k_scan_c   <<<NBLK, 256>>>(cnt, boff, rowstart, cursor);
    k_scatter  <<<7813, 256>>>(adj, adj + NE, w, dis, cursor, edata);

    // GCN layer 1 (stats fused into gather)
    k_xw1       <<<375, 256>>>(x, W1, xw);
    k_agg_gather<<<24000, 256>>>(xw, dis, rowstart, edata, agg1, b1, stats);
    k_bn_fin    <<<1, 64>>>(gm1, bt1, stats);

    // GCN layer 2
    k_xw2g      <<<3000, 256>>>(agg1, W2, b1, stats, xw);
    k_agg_gather<<<24000, 256>>>(xw, dis, rowstart, edata, agg2, b2, stats + 256);
    k_bn_fin    <<<1, 64>>>(gm2, bt2, stats + 256);

    // LSTM 1 (tensor-core gate GEMM gathers bn1(agg1)|bn2(agg2))
    k_gemm_tc<128, true><<<1500, 256, TC_SMEM>>>(agg1, agg2, whi1, wlo1, bih1, bhh1, b1, b2, stats, xproj);
    k_lstm<true><<<125, 512, LSTM_SMEM>>>(xproj, Whh1, y1, hn1);

    // LSTM 2
    k_gemm_tc<64, false><<<1500, 256, TC_SMEM>>>(y1, y1, whi2, wlo2, bih2, bhh2, nullptr, nullptr, nullptr, xproj);
    k_lstm<false><<<125, 512, LSTM_SMEM>>>(xproj, Whh2, nullptr, hn2);

    // FC head
    k_fc<<<4000, 256>>>(hn1, hn2, inner, x, fc1w, fc1b, fc3w, fc3b, out);
}

// round 14
// speedup vs baseline: 1.1059x; 1.0976x over previous
#include <cuda_runtime.h>
#include <cstdint>

#define BB     8
#define WIN    12
#define NNODE  2000
#define FIN    8
#define HD     64
#define NTOT   192000          // BB*WIN*NNODE
#define NE     2000000
#define BNS    16000           // BB*NNODE sequences
#define BNEPS  1e-5f
#define FC1IN  225
#define NBLK   750             // NTOT/256

// tc-gemm smem layout (bytes)
#define TC_AHI   4096
#define TC_ALO   20480
#define TC_WHI   36864
#define TC_WLO   69632
#define TC_SMEM  102400
#define TC_IDESC 0x8400910u     // kind::tf32, f32 D, M=128, N=256, K-major both

// tc-lstm smem layout (bytes): header | h chunks (2 chunk x 2 plane x 16KB) | W chunks (2x2x32KB)
#define LT_H     1024
#define LT_W     (1024 + 4*16384)     // 66560
#define LT_SMEM  (66560 + 4*32768)    // 197632  (FFMA fallback uses first 99328)
#define HP       132                  // fallback Hs pitch

#if defined(__CUDA_ARCH_FEAT_SM103_ALL) || defined(__CUDA_ARCH_FEAT_SM100_ALL)
#define HAS_TCGEN05 1
#else
#define HAS_TCGEN05 0
#endif

// ---------------- scratch (device globals; allocation-free) ----------------
__device__ float g_deg[NTOT];
__device__ float g_dis[NTOT];
__device__ float g_xw  [NTOT*HD];
__device__ float g_agg1[NTOT*HD];
__device__ float g_agg2[NTOT*HD];
__device__ float g_stats[512];
__device__ float g_xproj[(size_t)WIN*BNS*4*HD];
__device__ float g_y1  [(size_t)WIN*BNS*HD];
__device__ float g_hn1 [BNS*HD];
__device__ float g_hn2 [BNS*HD];
__device__ float g_whi1[256*128];
__device__ float g_wlo1[256*128];
__device__ float g_whi2[256*64];
__device__ float g_wlo2[256*64];
__device__ float g_hhi1[256*64];
__device__ float g_hlo1[256*64];
__device__ float g_hhi2[256*64];
__device__ float g_hlo2[256*64];
// CSR scratch
__device__ int   g_cnt[NTOT];
__device__ int   g_rowstart[NTOT+1];
__device__ int   g_cursor[NTOT];
__device__ int   g_bsum[1024];
__device__ int2  g_edata[NE];

// ---------------- helpers ----------------
__device__ __forceinline__ float sigf(float x)  { return __fdividef(1.f, 1.f + __expf(-x)); }
__device__ __forceinline__ float tanhfast(float x){ return 1.f - __fdividef(2.f, __expf(2.f*x) + 1.f); }

__device__ __forceinline__ float2 ffma2(float2 a, float2 b, float2 c){
    float2 d;
    asm("fma.rn.f32x2 %0, %1, %2, %3;"
        : "=l"(reinterpret_cast<unsigned long long&>(d))
        : "l"(reinterpret_cast<unsigned long long&>(a)),
          "l"(reinterpret_cast<unsigned long long&>(b)),
          "l"(reinterpret_cast<unsigned long long&>(c)));
    return d;
}
__device__ __forceinline__ float2 dup2(float x){ return make_float2(x, x); }
__device__ __forceinline__ void fma4(float (&a)[4], float h, float4 w){
    a[0]=fmaf(h,w.x,a[0]); a[1]=fmaf(h,w.y,a[1]); a[2]=fmaf(h,w.z,a[2]); a[3]=fmaf(h,w.w,a[3]);
}
__device__ __forceinline__ float tf32r(float x){
    uint32_t u; asm("cvt.rna.tf32.f32 %0, %1;" : "=r"(u) : "f"(x));
    return __uint_as_float(u);
}

#if HAS_TCGEN05
__device__ __forceinline__ uint32_t smem_u32(const void* p){
    uint32_t a;
    asm("{ .reg .u64 t; cvta.to.shared.u64 t, %1; cvt.u32.u64 %0, t; }" : "=r"(a) : "l"(p));
    return a;
}
__device__ __forceinline__ uint32_t swz128(uint32_t off){ return off ^ ((off >> 3) & 0x70); }
__device__ __forceinline__ uint64_t mk_desc(uint32_t addr){
    return ((uint64_t)2 << 61) | ((uint64_t)1 << 46) | ((uint64_t)64 << 32) | ((uint64_t)1 << 16)
         | ((uint64_t)(addr >> 4) & 0x3FFF);
}
__device__ __forceinline__ void mma_tf32(uint32_t d, uint64_t ad, uint64_t bd, uint32_t en){
    asm volatile(
        "{\n\t.reg .pred p;\n\tsetp.ne.u32 p, %5, 0;\n\t"
        "tcgen05.mma.cta_group::1.kind::tf32 [%0], %1, %2, %3, {%4, %4, %4, %4}, p;\n\t}"
        :: "r"(d), "l"(ad), "l"(bd), "r"(TC_IDESC), "r"(0u), "r"(en) : "memory");
}
__device__ __forceinline__ void mbar_wait(uint32_t mb, uint32_t parity){
    asm volatile(
        "{\n\t.reg .pred P1;\n\t"
        "W_%=:\n\t"
        "mbarrier.try_wait.parity.acquire.cta.shared::cta.b64 P1, [%0], %1;\n\t"
        "@!P1 bra W_%=;\n\t}"
        :: "r"(mb), "r"(parity) : "memory");
}
#define LDTM_X32(r, addr) \
    asm volatile("tcgen05.ld.sync.aligned.32x32b.x32.b32 " \
        "{%0,%1,%2,%3,%4,%5,%6,%7,%8,%9,%10,%11,%12,%13,%14,%15," \
        "%16,%17,%18,%19,%20,%21,%22,%23,%24,%25,%26,%27,%28,%29,%30,%31}, [%32];" \
        : "=r"((r)[0]),"=r"((r)[1]),"=r"((r)[2]),"=r"((r)[3]),"=r"((r)[4]),"=r"((r)[5]),"=r"((r)[6]),"=r"((r)[7]), \
          "=r"((r)[8]),"=r"((r)[9]),"=r"((r)[10]),"=r"((r)[11]),"=r"((r)[12]),"=r"((r)[13]),"=r"((r)[14]),"=r"((r)[15]), \
          "=r"((r)[16]),"=r"((r)[17]),"=r"((r)[18]),"=r"((r)[19]),"=r"((r)[20]),"=r"((r)[21]),"=r"((r)[22]),"=r"((r)[23]), \
          "=r"((r)[24]),"=r"((r)[25]),"=r"((r)[26]),"=r"((r)[27]),"=r"((r)[28]),"=r"((r)[29]),"=r"((r)[30]),"=r"((r)[31]) \
        : "r"(addr))
#define LDTM_X16(r, addr) \
    asm volatile("tcgen05.ld.sync.aligned.32x32b.x16.b32 " \
        "{%0,%1,%2,%3,%4,%5,%6,%7,%8,%9,%10,%11,%12,%13,%14,%15}, [%16];" \
        : "=r"((r)[0]),"=r"((r)[1]),"=r"((r)[2]),"=r"((r)[3]),"=r"((r)[4]),"=r"((r)[5]),"=r"((r)[6]),"=r"((r)[7]), \
          "=r"((r)[8]),"=r"((r)[9]),"=r"((r)[10]),"=r"((r)[11]),"=r"((r)[12]),"=r"((r)[13]),"=r"((r)[14]),"=r"((r)[15]) \
        : "r"(addr))
#endif

// ---------------- fused init: deg/cnt/stats + tf32 splits of all W ----------------
__global__ void k_initall(float* deg, int* cnt,
                          const float* __restrict__ Wih1, float* __restrict__ whi1, float* __restrict__ wlo1,
                          const float* __restrict__ Wih2, float* __restrict__ whi2, float* __restrict__ wlo2,
                          const float* __restrict__ Whh1, float* __restrict__ hhi1, float* __restrict__ hlo1,
                          const float* __restrict__ Whh2, float* __restrict__ hhi2, float* __restrict__ hlo2){
    int i = blockIdx.x*blockDim.x + threadIdx.x;
    if (i < NTOT){ deg[i] = 1.0f; cnt[i] = 0; }
    if (i < 512) g_stats[i] = 0.f;
    if (i < 256*128){
        float v = Wih1[i]; float h = tf32r(v);
        whi1[i] = h; wlo1[i] = v - h;
    }
    if (i < 256*64){
        float v = Wih2[i]; float h = tf32r(v);
        whi2[i] = h; wlo2[i] = v - h;
        float v1 = Whh1[i]; float h1 = tf32r(v1);
        hhi1[i] = h1; hlo1[i] = v1 - h1;
        float v2 = Whh2[i]; float h2 = tf32r(v2);
        hhi2[i] = h2; hlo2[i] = v2 - h2;
    }
}
__global__ void k_deg_hist(const int* __restrict__ col, const float* __restrict__ w,
                           float* deg, int* cnt){
    int e = blockIdx.x*blockDim.x + threadIdx.x;
    if (e < NE){
        int c = col[e];
        atomicAdd(&deg[c], w[e]);
        atomicAdd(&cnt[c], 1);
    }
}
__global__ void k_dis_scan(const float* __restrict__ deg, float* dis,
                           const int* __restrict__ cnt, int* bsum){
    __shared__ int sh[256];
    int t = threadIdx.x;
    int i = blockIdx.x*256 + t;
    float d = deg[i];
    dis[i] = (d > 0.f) ? rsqrtf(d) : 0.f;
    sh[t] = cnt[i];
    __syncthreads();
    #pragma unroll
    for (int off = 128; off > 0; off >>= 1){
        if (t < off) sh[t] += sh[t + off];
        __syncthreads();
    }
    if (t == 0) bsum[blockIdx.x] = sh[0];
}
__global__ void k_scan_b(const int* __restrict__ bsum, int* boff, int* rowstart){
    __shared__ int sh[1024];
    int t = threadIdx.x;
    int v = (t < NBLK) ? bsum[t] : 0;
    sh[t] = v;
    __syncthreads();
    #pragma unroll
    for (int off = 1; off < 1024; off <<= 1){
        int x = (t >= off) ? sh[t - off] : 0;
        __syncthreads();
        sh[t] += x;
        __syncthreads();
    }
    if (t < NBLK) boff[t] = sh[t] - v;
    if (t == 0) rowstart[NTOT] = NE;
}
__global__ void k_scan_c(const int* __restrict__ cnt, const int* __restrict__ boff,
                         int* rowstart, int* cursor){
    __shared__ int sh[256];
    int t = threadIdx.x;
    int i = blockIdx.x*256 + t;
    int v = cnt[i];
    sh[t] = v;
    __syncthreads();
    #pragma unroll
    for (int off = 1; off < 256; off <<= 1){
        int x = (t >= off) ? sh[t - off] : 0;
        __syncthreads();
        sh[t] += x;
        __syncthreads();
    }
    int ex = boff[blockIdx.x] + sh[t] - v;
    rowstart[i] = ex;
    cursor[i]   = ex;
}
__global__ void k_scatter(const int* __restrict__ rows, const int* __restrict__ cols,
                          const float* __restrict__ w, const float* __restrict__ dis,
                          int* cursor, int2* edata){
    int e = blockIdx.x*blockDim.x + threadIdx.x;
    if (e >= NE) return;
    int r = rows[e], c = cols[e];
    float norm = dis[r]*w[e]*dis[c];
    int pos = atomicAdd(&cursor[c], 1);
    edata[pos] = make_int2(r, __float_as_int(norm));
}

// ---------------- xw = x @ W1  (K=8), 2 nodes per thread ----------------
__global__ void k_xw1(const float* __restrict__ x, const float* __restrict__ W, float* __restrict__ out){
    __shared__ float Ws[FIN*HD];
    for (int i = threadIdx.x; i < FIN*HD; i += blockDim.x) Ws[i] = W[i];
    __syncthreads();
    int base = (blockIdx.x*blockDim.x + threadIdx.x)*2;
    if (base >= NTOT) return;
    #pragma unroll
    for (int u = 0; u < 2; u++){
        int node = base + u;
        float xr[FIN];
        float4 v0 = *(const float4*)(x + (size_t)node*FIN);
        float4 v1 = *(const float4*)(x + (size_t)node*FIN + 4);
        xr[0]=v0.x; xr[1]=v0.y; xr[2]=v0.z; xr[3]=v0.w;
        xr[4]=v1.x; xr[5]=v1.y; xr[6]=v1.z; xr[7]=v1.w;
        #pragma unroll
        for (int j = 0; j < HD; j += 4){
            float a[4] = {0.f,0.f,0.f,0.f};
            #pragma unroll
            for (int k = 0; k < FIN; k++){
                float4 w4 = *(const float4*)&Ws[k*HD + j];
                fma4(a, xr[k], w4);
            }
            *(float4*)(out + (size_t)node*HD + j) = make_float4(a[0],a[1],a[2],a[3]);
        }
    }
}

// ---------------- aggregation: gather (warp per target node) + fused BN stats ----------------
__global__ void __launch_bounds__(256) k_agg_gather(const float* __restrict__ xw,
                                                    const float* __restrict__ dis,
                                                    const int* __restrict__ rowstart,
                                                    const int2* __restrict__ edata,
                                                    float* __restrict__ agg,
                                                    const float* __restrict__ bias,
                                                    float* __restrict__ stats){
    __shared__ float ss [8][64];
    __shared__ float ss2[8][64];
    const int tid = threadIdx.x;
    const int wrp = tid >> 5;
    const int lane = tid & 31;
    int gw = blockIdx.x*8 + wrp;
    float va = 0.f, vb = 0.f;
    if (gw < NTOT){
        int beg = rowstart[gw], end = rowstart[gw+1];
        float d = dis[gw];
        float2 v0 = *(const float2*)(xw + (size_t)gw*HD + lane*2);
        float sc = d*d;
        float2 acc = make_float2(v0.x*sc, v0.y*sc);
        int j = beg;
        for (; j + 2 <= end; j += 2){
            int2 e0 = edata[j], e1 = edata[j+1];
            float2 a = *(const float2*)(xw + (size_t)e0.x*HD + lane*2);
            float2 b = *(const float2*)(xw + (size_t)e1.x*HD + lane*2);
            float n0 = __int_as_float(e0.y), n1 = __int_as_float(e1.y);
            acc.x = fmaf(a.x, n0, acc.x); acc.y = fmaf(a.y, n0, acc.y);
            acc.x = fmaf(b.x, n1, acc.x); acc.y = fmaf(b.y, n1, acc.y);
        }
        if (j < end){
            int2 e0 = edata[j];
            float2 a = *(const float2*)(xw + (size_t)e0.x*HD + lane*2);
            float n0 = __int_as_float(e0.y);
            acc.x = fmaf(a.x, n0, acc.x); acc.y = fmaf(a.y, n0, acc.y);
        }
        *(float2*)(agg + (size_t)gw*HD + lane*2) = acc;
        va = fmaxf(acc.x + bias[lane*2],   0.f);
        vb = fmaxf(acc.y + bias[lane*2+1], 0.f);
    }
    ss [wrp][lane*2]   = va;
    ss [wrp][lane*2+1] = vb;
    ss2[wrp][lane*2]   = va*va;
    ss2[wrp][lane*2+1] = vb*vb;
    __syncthreads();
    if (tid < 64){
        float s = 0.f, s2 = 0.f;
        #pragma unroll
        for (int w = 0; w < 8; w++){ s += ss[w][tid]; s2 += ss2[w][tid]; }
        atomicAdd(&stats[tid], s);
        atomicAdd(&stats[64+tid], s2);
    }
}

__global__ void k_bn_fin(const float* __restrict__ gamma, const float* __restrict__ beta,
                         float* __restrict__ stats){
    int ch = threadIdx.x;
    if (ch < 64){
        const float invN = 1.f/(float)NTOT;
        float m = stats[ch]*invN;
        float var = stats[64+ch]*invN - m*m;
        float sc = gamma[ch]*rsqrtf(var + BNEPS);
        stats[128+ch] = sc;
        stats[192+ch] = beta[ch] - m*sc;
    }
}

// ---------------- xw2 = bn1(agg1) @ W2  (tiled 64x64, f32x2, fused BN) ----------------
__global__ void __launch_bounds__(256) k_xw2g(const float* __restrict__ A, const float* __restrict__ W,
                                              const float* __restrict__ bias, const float* __restrict__ stats,
                                              float* __restrict__ out){
    __shared__ float As[16][64];
    __shared__ float Bs[16][68];
    __shared__ float bnb[64], bns[64], bnh[64];
    const int tid = threadIdx.x;
    if (tid < 64){ bnb[tid] = bias[tid]; bns[tid] = stats[128+tid]; bnh[tid] = stats[192+tid]; }
    __syncthreads();
    const int bm = blockIdx.x*64;
    const int lr = tid >> 2, lk = (tid & 3)*4;
    const int m  = bm + lr;
    const int ty = tid >> 4, tx = tid & 15;
    float2 acc[4][2] = {};
    for (int k0 = 0; k0 < HD; k0 += 16){
        float4 av = *(const float4*)(A + (size_t)m*HD + k0 + lk);
        int cb = k0 + lk;
        av.x = fmaxf(av.x + bnb[cb+0], 0.f)*bns[cb+0] + bnh[cb+0];
        av.y = fmaxf(av.y + bnb[cb+1], 0.f)*bns[cb+1] + bnh[cb+1];
        av.z = fmaxf(av.z + bnb[cb+2], 0.f)*bns[cb+2] + bnh[cb+2];
        av.w = fmaxf(av.w + bnb[cb+3], 0.f)*bns[cb+3] + bnh[cb+3];
        As[lk+0][lr]=av.x; As[lk+1][lr]=av.y; As[lk+2][lr]=av.z; As[lk+3][lr]=av.w;
        int kk = tid >> 4, n4 = (tid & 15)*4;
        float4 bv = *(const float4*)(W + (size_t)(k0+kk)*HD + n4);
        Bs[kk][n4+0]=bv.x; Bs[kk][n4+1]=bv.y; Bs[kk][n4+2]=bv.z; Bs[kk][n4+3]=bv.w;
        __syncthreads();
        #pragma unroll
        for (int q = 0; q < 16; q++){
            float4 a4 = *(const float4*)&As[q][ty*4];
            float4 b4 = *(const float4*)&Bs[q][tx*4];
            float2 bb0 = make_float2(b4.x, b4.y), bb1 = make_float2(b4.z, b4.w);
            float ar[4] = {a4.x, a4.y, a4.z, a4.w};
            #pragma unroll
            for (int i = 0; i < 4; i++){
                float2 ad = dup2(ar[i]);
                acc[i][0] = ffma2(ad, bb0, acc[i][0]);
                acc[i][1] = ffma2(ad, bb1, acc[i][1]);
            }
        }
        __syncthreads();
    }
    #pragma unroll
    for (int i = 0; i < 4; i++){
        int mr = bm + ty*4 + i;
        *(float4*)(out + (size_t)mr*HD + tx*4) =
            make_float4(acc[i][0].x, acc[i][0].y, acc[i][1].x, acc[i][1].y);
    }
}

// ---------------- gate GEMM: out[m][256] = A[m][KD] @ W^T + bias ----------------
template<int KD, bool GATHER>
__global__ void __launch_bounds__(256, 2)
k_gemm_tc(const float* __restrict__ A0, const float* __restrict__ A1,
          const float* __restrict__ whi, const float* __restrict__ wlo,
          const float* __restrict__ bih, const float* __restrict__ bhh,
          const float* __restrict__ b1, const float* __restrict__ b2,
          const float* __restrict__ stats,
          float* __restrict__ out){
    extern __shared__ float sm[];
    float* bias_sm = sm + 64;           // 256 floats
    float* bnb = sm + 320; float* bns = sm + 448; float* bnh = sm + 576;
    const int tid = threadIdx.x;

    if (tid < 128){
        bias_sm[tid]     = bih[tid]     + bhh[tid];
        bias_sm[128+tid] = bih[128+tid] + bhh[128+tid];
    }
    if (GATHER && tid < 64){
        bnb[tid]    = b1[tid]; bns[tid]    = stats[128+tid]; bnh[tid]    = stats[192+tid];
        bnb[64+tid] = b2[tid]; bns[64+tid] = stats[384+tid]; bnh[64+tid] = stats[448+tid];
    }

#if HAS_TCGEN05
    char* smc = (char*)sm;
    const uint32_t sb = smem_u32(sm);
    const uint32_t mb = sb + 8;
    const int wid = tid >> 5, lane = tid & 31;
    if (wid == 0){
        asm volatile("tcgen05.alloc.cta_group::1.sync.aligned.shared::cta.b32 [%0], %1;"
                     :: "r"(sb), "r"(256u) : "memory");
        asm volatile("tcgen05.relinquish_alloc_permit.cta_group::1.sync.aligned;" ::: "memory");
    }
    if (tid == 0)
        asm volatile("mbarrier.init.shared.b64 [%0], %1;" :: "r"(mb), "r"(1u) : "memory");
    __syncthreads();
    uint32_t tmem;
    asm volatile("ld.shared.b32 %0, [%1];" : "=r"(tmem) : "r"(sb));

    const int bm = blockIdx.x*128;
    const int row = tid >> 1;
    const int j4  = (tid & 1)*4;
    const int m = bm + row;
    size_t aoff;
    if (GATHER){
        int t = m/BNS, s = m - t*BNS;
        int b = s/NNODE, n = s - b*NNODE;
        aoff = (size_t)((b*WIN + t)*NNODE + n)*HD;
    } else {
        aoff = (size_t)m*KD;
    }

    const uint64_t dAH = mk_desc(sb + TC_AHI), dAL = mk_desc(sb + TC_ALO);
    const uint64_t dWH = mk_desc(sb + TC_WHI), dWL = mk_desc(sb + TC_WLO);
    const int NCH = KD/32;
    uint32_t parity = 0;
    const uint32_t arow = (uint32_t)((row>>3)*1024 + (row&7)*128);

    for (int c = 0; c < NCH; c++){
        const int k0 = c*32;
        const float* abase = GATHER ? ((k0 < 64) ? A0 : A1) : A0;
        const int koff = GATHER ? (k0 & 63) : k0;
        #pragma unroll
        for (int u = 0; u < 4; u++){
            int j = j4 + u;
            float4 v = *(const float4*)(abase + aoff + koff + j*4);
            if (GATHER){
                int k = k0 + j*4;
                v.x = fmaxf(v.x + bnb[k+0], 0.f)*bns[k+0] + bnh[k+0];
                v.y = fmaxf(v.y + bnb[k+1], 0.f)*bns[k+1] + bnh[k+1];
                v.z = fmaxf(v.z + bnb[k+2], 0.f)*bns[k+2] + bnh[k+2];
                v.w = fmaxf(v.w + bnb[k+3], 0.f)*bns[k+3] + bnh[k+3];
            }
            float4 hi, lo;
            hi.x = tf32r(v.x); lo.x = v.x - hi.x;
            hi.y = tf32r(v.y); lo.y = v.y - hi.y;
            hi.z = tf32r(v.z); lo.z = v.z - hi.z;
            hi.w = tf32r(v.w); lo.w = v.w - hi.w;
            uint32_t sw = swz128(arow + j*16);
            *(float4*)(smc + TC_AHI + sw) = hi;
            *(float4*)(smc + TC_ALO + sw) = lo;
        }
        for (int idx = tid; idx < 2048; idx += 256){
            int g = idx >> 3, j = idx & 7;
            float4 vh = *(const float4*)(whi + (size_t)g*KD + k0 + j*4);
            float4 vl = *(const float4*)(wlo + (size_t)g*KD + k0 + j*4);
            uint32_t sw = swz128((uint32_t)((g>>3)*1024 + (g&7)*128 + j*16));
            *(float4*)(smc + TC_WHI + sw) = vh;
            *(float4*)(smc + TC_WLO + sw) = vl;
        }
        __syncthreads();
        if (tid == 0){
            asm volatile("fence.proxy.async.shared::cta;" ::: "memory");
            #pragma unroll
            for (int s = 0; s < 4; s++){
                uint64_t oa = (uint64_t)(2*s);
                uint32_t en0 = (c == 0 && s == 0) ? 0u : 1u;
                mma_tf32(tmem, dAH + oa, dWH + oa, en0);
                mma_tf32(tmem, dAH + oa, dWL + oa, 1u);
                mma_tf32(tmem, dAL + oa, dWH + oa, 1u);
            }
            asm volatile("tcgen05.commit.cta_group::1.mbarrier::arrive::one.shared::cluster.b64 [%0];"
                         :: "r"(mb) : "memory");
        }
        mbar_wait(mb, parity);
        parity ^= 1;
    }

    asm volatile("tcgen05.fence::after_thread_sync;" ::: "memory");
    {
        int mrow = bm + (wid & 3)*32 + lane;
        int cb   = (wid >> 2)*4;
        float* op = out + (size_t)mrow*256;
        for (int b = cb; b < cb + 4; b++){
            uint32_t r[32];
            LDTM_X32(r, tmem + b*32);
            asm volatile("tcgen05.wait::ld.sync.aligned;" ::: "memory");
            #pragma unroll
            for (int q = 0; q < 8; q++){
                float4 o;
                o.x = __uint_as_float(r[q*4+0]) + bias_sm[b*32 + q*4+0];
                o.y = __uint_as_float(r[q*4+1]) + bias_sm[b*32 + q*4+1];
                o.z = __uint_as_float(r[q*4+2]) + bias_sm[b*32 + q*4+2];
                o.w = __uint_as_float(r[q*4+3]) + bias_sm[b*32 + q*4+3];
                *(float4*)(op + b*32 + q*4) = o;
            }
        }
    }
    __syncthreads();
    if (tid == 0)
        asm volatile("mbarrier.inval.shared.b64 [%0];" :: "r"(mb) : "memory");
    __syncthreads();
    if (wid == 0)
        asm volatile("tcgen05.dealloc.cta_group::1.sync.aligned.b32 %0, %1;"
                     :: "r"(tmem), "r"(256u) : "memory");
#else
    // -------- FFMA2 fallback --------
    float* As = sm + 1024;                 // [16][68]
    float* Bs = sm + 1024 + 16*68;         // [16][260]
    __syncthreads();
    const int bm = blockIdx.x*128;
    const int lr = tid >> 2, lk = (tid & 3)*4;
    const int ty = tid >> 5, tx = tid & 31;
    for (int mh = 0; mh < 2; mh++){
        const int m = bm + mh*64 + lr;
        size_t aoff;
        if (GATHER){
            int t = m/BNS, s = m - t*BNS;
            int b = s/NNODE, n = s - b*NNODE;
            aoff = (size_t)((b*WIN + t)*NNODE + n)*HD;
        } else aoff = (size_t)m*KD;
        float2 acc[8][4] = {};
        for (int k0 = 0; k0 < KD; k0 += 16){
            int k = k0 + lk;
            const float* abase = GATHER ? ((k < 64) ? A0 : A1) : A0;
            int ko = GATHER ? (k & 63) : k;
            float4 v = *(const float4*)(abase + aoff + ko);
            if (GATHER){
                v.x = fmaxf(v.x + bnb[k+0], 0.f)*bns[k+0] + bnh[k+0];
                v.y = fmaxf(v.y + bnb[k+1], 0.f)*bns[k+1] + bnh[k+1];
                v.z = fmaxf(v.z + bnb[k+2], 0.f)*bns[k+2] + bnh[k+2];
                v.w = fmaxf(v.w + bnb[k+3], 0.f)*bns[k+3] + bnh[k+3];
            }
            As[(lk+0)*68 + lr] = v.x;
            As[(lk+1)*68 + lr] = v.y;
            As[(lk+2)*68 + lr] = v.z;
            As[(lk+3)*68 + lr] = v.w;
            for (int i = tid; i < 1024; i += 256){
                int g = i >> 2, kq = (i & 3)*4;
                float4 vh = *(const float4*)(whi + (size_t)g*KD + k0 + kq);
                float4 vl = *(const float4*)(wlo + (size_t)g*KD + k0 + kq);
                Bs[(kq+0)*260 + g] = vh.x + vl.x;
                Bs[(kq+1)*260 + g] = vh.y + vl.y;
                Bs[(kq+2)*260 + g] = vh.z + vl.z;
                Bs[(kq+3)*260 + g] = vh.w + vl.w;
            }
            __syncthreads();
            #pragma unroll
            for (int kk = 0; kk < 16; kk++){
                float4 a0 = *(const float4*)&As[kk*68 + ty*8];
                float4 a1 = *(const float4*)&As[kk*68 + ty*8 + 4];
                float4 b0 = *(const float4*)&Bs[kk*260 + tx*8];
                float4 b1v = *(const float4*)&Bs[kk*260 + tx*8 + 4];
                float2 bb[4] = {make_float2(b0.x,b0.y), make_float2(b0.z,b0.w),
                                make_float2(b1v.x,b1v.y), make_float2(b1v.z,b1v.w)};
                float ar[8] = {a0.x,a0.y,a0.z,a0.w, a1.x,a1.y,a1.z,a1.w};
                #pragma unroll
                for (int i = 0; i < 8; i++){
                    float2 ad = dup2(ar[i]);
                    #pragma unroll
                    for (int p = 0; p < 4; p++)
                        acc[i][p] = ffma2(ad, bb[p], acc[i][p]);
                }
            }
            __syncthreads();
        }
        #pragma unroll
        for (int i = 0; i < 8; i++){
            int mr = bm + mh*64 + ty*8 + i;
            float* op = out + (size_t)mr*256 + tx*8;
            const float* bz = bias_sm + tx*8;
            *(float4*)(op)   = make_float4(acc[i][0].x+bz[0], acc[i][0].y+bz[1],
                                           acc[i][1].x+bz[2], acc[i][1].y+bz[3]);
            *(float4*)(op+4) = make_float4(acc[i][2].x+bz[4], acc[i][2].y+bz[5],
                                           acc[i][3].x+bz[6], acc[i][3].y+bz[7]);
        }
    }
#endif
}

// ---------------- LSTM: 128 seqs / block, 512 threads ----------------
// TC path: Whh in smem (hi/lo, staged once), per-t tcgen05 recurrence GEMM with
// fresh TMEM accumulate; xproj added in registers; cell math + h hi/lo STS.
template<bool WRITE_Y>
__global__ void __launch_bounds__(512, 1) k_lstm(const float* __restrict__ xproj,
                                                 const float* __restrict__ whh_hi,
                                                 const float* __restrict__ whh_lo,
                                                 const float* __restrict__ Whh_raw,
                                                 float* __restrict__ y_out,
                                                 float* __restrict__ hn_out){
    extern __shared__ float sm[];
    const int tid = threadIdx.x;
#if HAS_TCGEN05
    char* smc = (char*)sm;
    const uint32_t sb = smem_u32(sm);
    const uint32_t mb = sb + 8;
    const int wid = tid >> 5, lane = tid & 31;
    // stage Whh chunks (2 K-chunks x 2 planes, 256 g-rows x 32 k each)
    for (int idx = tid; idx < 4096; idx += 512){
        int c = idx >> 11;
        int r = idx & 2047;
        int g = r >> 3, j = r & 7;
        uint32_t sw = swz128((uint32_t)((g>>3)*1024 + (g&7)*128 + j*16));
        *(float4*)(smc + LT_W + (c*2+0)*32768 + sw) = *(const float4*)(whh_hi + g*64 + c*32 + j*4);
        *(float4*)(smc + LT_W + (c*2+1)*32768 + sw) = *(const float4*)(whh_lo + g*64 + c*32 + j*4);
    }
    if (wid == 0){
        asm volatile("tcgen05.alloc.cta_group::1.sync.aligned.shared::cta.b32 [%0], %1;"
                     :: "r"(sb), "r"(256u) : "memory");
        asm volatile("tcgen05.relinquish_alloc_permit.cta_group::1.sync.aligned;" ::: "memory");
    }
    if (tid == 0)
        asm volatile("mbarrier.init.shared.b64 [%0], %1;" :: "r"(mb), "r"(1u) : "memory");
    __syncthreads();
    uint32_t tmem;
    asm volatile("ld.shared.b32 %0, [%1];" : "=r"(tmem) : "r"(sb));

    uint64_t dH[2][2], dW[2][2];
    #pragma unroll
    for (int c = 0; c < 2; c++)
        #pragma unroll
        for (int p = 0; p < 2; p++){
            dH[c][p] = mk_desc(sb + LT_H + (uint32_t)(c*2+p)*16384);
            dW[c][p] = mk_desc(sb + LT_W + (uint32_t)(c*2+p)*32768);
        }

    const int sp  = wid & 3;           // subpartition (rows)
    const int seq = sp*32 + lane;      // 0..127
    const int j0  = (wid >> 2)*16;     // 0,16,32,48
    const int s0  = blockIdx.x*128;
    const int ch  = j0 >> 5;           // h chunk
    const int kw  = j0 & 31;           // k within chunk
    const uint32_t hrow = (uint32_t)((seq>>3)*1024 + (seq&7)*128);
    float cst[16];
    #pragma unroll
    for (int i = 0; i < 16; i++) cst[i] = 0.f;
    uint32_t parity = 0;

    for (int t = 0; t < WIN; t++){
        if (t > 0){
            __syncthreads();                      // all h STS done
            if (tid == 0){
                asm volatile("fence.proxy.async.shared::cta;" ::: "memory");
                bool first = true;
                #pragma unroll
                for (int c = 0; c < 2; c++){
                    #pragma unroll
                    for (int s = 0; s < 4; s++){
                        uint64_t oa = (uint64_t)(2*s);
                        mma_tf32(tmem, dH[c][0] + oa, dW[c][0] + oa, first ? 0u : 1u);
                        first = false;
                        mma_tf32(tmem, dH[c][0] + oa, dW[c][1] + oa, 1u);
                        mma_tf32(tmem, dH[c][1] + oa, dW[c][0] + oa, 1u);
                    }
                }
                asm volatile("tcgen05.commit.cta_group::1.mbarrier::arrive::one.shared::cluster.b64 [%0];"
                             :: "r"(mb) : "memory");
            }
        }
        // xproj (overlaps MMA)
        const float* xp = xproj + ((size_t)t*BNS + s0 + seq)*256 + j0;
        float gi[16], gf[16], gg[16], go[16];
        #pragma unroll
        for (int q = 0; q < 4; q++){
            float4 v;
            v = *(const float4*)(xp + q*4);        gi[q*4]=v.x; gi[q*4+1]=v.y; gi[q*4+2]=v.z; gi[q*4+3]=v.w;
            v = *(const float4*)(xp + 64 + q*4);   gf[q*4]=v.x; gf[q*4+1]=v.y; gf[q*4+2]=v.z; gf[q*4+3]=v.w;
            v = *(const float4*)(xp + 128 + q*4);  gg[q*4]=v.x; gg[q*4+1]=v.y; gg[q*4+2]=v.z; gg[q*4+3]=v.w;
            v = *(const float4*)(xp + 192 + q*4);  go[q*4]=v.x; go[q*4+1]=v.y; go[q*4+2]=v.z; go[q*4+3]=v.w;
        }
        if (t > 0){
            mbar_wait(mb, parity);
            parity ^= 1;
            asm volatile("tcgen05.fence::after_thread_sync;" ::: "memory");
            uint32_t ri[16], rf[16], rg[16], ro[16];
            LDTM_X16(ri, tmem + j0);
            LDTM_X16(rf, tmem + 64 + j0);
            LDTM_X16(rg, tmem + 128 + j0);
            LDTM_X16(ro, tmem + 192 + j0);
            asm volatile("tcgen05.wait::ld.sync.aligned;" ::: "memory");
            #pragma unroll
            for (int i = 0; i < 16; i++){
                gi[i] += __uint_as_float(ri[i]);
                gf[i] += __uint_as_float(rf[i]);
                gg[i] += __uint_as_float(rg[i]);
                go[i] += __uint_as_float(ro[i]);
            }
            asm volatile("tcgen05.fence::before_thread_sync;" ::: "memory");
        }
        float hv[16];
        #pragma unroll
        for (int i = 0; i < 16; i++){
            float iv = sigf(gi[i]);
            float fv = sigf(gf[i]);
            float gv = tanhfast(gg[i]);
            float ov = sigf(go[i]);
            float cc = fmaf(fv, cst[i], iv*gv);
            cst[i] = cc;
            hv[i] = ov*tanhfast(cc);
        }
        if (WRITE_Y){
            float* yp = y_out + ((size_t)t*BNS + s0 + seq)*HD + j0;
            #pragma unroll
            for (int q = 0; q < 4; q++)
                *(float4*)(yp + q*4) = make_float4(hv[q*4], hv[q*4+1], hv[q*4+2], hv[q*4+3]);
        }
        if (t == WIN-1){
            float* hp = hn_out + (size_t)(s0 + seq)*HD + j0;
            #pragma unroll
            for (int q = 0; q < 4; q++)
                *(float4*)(hp + q*4) = make_float4(hv[q*4], hv[q*4+1], hv[q*4+2], hv[q*4+3]);
        }
        // h -> smem (hi/lo planes)
        #pragma unroll
        for (int q = 0; q < 4; q++){
            float4 hi, lo;
            hi.x = tf32r(hv[q*4+0]); lo.x = hv[q*4+0] - hi.x;
            hi.y = tf32r(hv[q*4+1]); lo.y = hv[q*4+1] - hi.y;
            hi.z = tf32r(hv[q*4+2]); lo.z = hv[q*4+2] - hi.z;
            hi.w = tf32r(hv[q*4+3]); lo.w = hv[q*4+3] - hi.w;
            uint32_t sw = swz128(hrow + (uint32_t)(kw/4 + q)*16);
            *(float4*)(smc + LT_H + (ch*2+0)*16384 + sw) = hi;
            *(float4*)(smc + LT_H + (ch*2+1)*16384 + sw) = lo;
        }
    }
    __syncthreads();
    if (tid == 0)
        asm volatile("mbarrier.inval.shared.b64 [%0];" :: "r"(mb) : "memory");
    __syncthreads();
    if (wid == 0)
        asm volatile("tcgen05.dealloc.cta_group::1.sync.aligned.b32 %0, %1;"
                     :: "r"(tmem), "r"(256u) : "memory");
#else
    // -------- FFMA2 fallback (previous k_lstm) --------
    float* Ws = sm;
    float* Hs = sm + 16384;
    for (int i = tid; i < 16384; i += 512){ int g = i >> 6, k = i & 63; Ws[k*256 + g] = Whh_raw[i]; }
    for (int i = tid; i < 64*HP; i += 512) Hs[i] = 0.f;
    __syncthreads();
    const int tx = tid & 15;
    const int ty = tid >> 4;
    const int s0 = blockIdx.x*128;
    const int sb2 = ty*4;
    float c[4][4]  = {};
    float hv[4][4] = {};
    for (int t = 0; t < WIN; t++){
        float2 ai[4][2], af[4][2], ag[4][2], ao[4][2];
        #pragma unroll
        for (int si = 0; si < 4; si++){
            const float* xp = xproj + ((size_t)t*BNS + (s0 + sb2 + si))*256 + tx*4;
            float4 vi = *(const float4*)(xp);
            float4 vf = *(const float4*)(xp + 64);
            float4 vg = *(const float4*)(xp + 128);
            float4 vo = *(const float4*)(xp + 192);
            ai[si][0]=make_float2(vi.x,vi.y); ai[si][1]=make_float2(vi.z,vi.w);
            af[si][0]=make_float2(vf.x,vf.y); af[si][1]=make_float2(vf.z,vf.w);
            ag[si][0]=make_float2(vg.x,vg.y); ag[si][1]=make_float2(vg.z,vg.w);
            ao[si][0]=make_float2(vo.x,vo.y); ao[si][1]=make_float2(vo.z,vo.w);
        }
        #pragma unroll 4
        for (int k = 0; k < 64; k++){
            float4 h4 = *(const float4*)&Hs[k*HP + sb2];
            const float* wr = &Ws[k*256 + tx*4];
            float4 wi4 = *(const float4*)(wr);
            float4 wf4 = *(const float4*)(wr + 64);
            float4 wg4 = *(const float4*)(wr + 128);
            float4 wo4 = *(const float4*)(wr + 192);
            float2 wi0=make_float2(wi4.x,wi4.y), wi1=make_float2(wi4.z,wi4.w);
            float2 wf0=make_float2(wf4.x,wf4.y), wf1=make_float2(wf4.z,wf4.w);
            float2 wg0=make_float2(wg4.x,wg4.y), wg1=make_float2(wg4.z,wg4.w);
            float2 wo0=make_float2(wo4.x,wo4.y), wo1=make_float2(wo4.z,wo4.w);
            float hs[4] = {h4.x, h4.y, h4.z, h4.w};
            #pragma unroll
            for (int si = 0; si < 4; si++){
                float2 hd = dup2(hs[si]);
                ai[si][0]=ffma2(hd,wi0,ai[si][0]); ai[si][1]=ffma2(hd,wi1,ai[si][1]);
                af[si][0]=ffma2(hd,wf0,af[si][0]); af[si][1]=ffma2(hd,wf1,af[si][1]);
                ag[si][0]=ffma2(hd,wg0,ag[si][0]); ag[si][1]=ffma2(hd,wg1,ag[si][1]);
                ao[si][0]=ffma2(hd,wo0,ao[si][0]); ao[si][1]=ffma2(hd,wo1,ao[si][1]);
            }
        }
        __syncwarp();
        #pragma unroll
        for (int si = 0; si < 4; si++){
            float aiv[4]={ai[si][0].x, ai[si][0].y, ai[si][1].x, ai[si][1].y};
            float afv[4]={af[si][0].x, af[si][0].y, af[si][1].x, af[si][1].y};
            float agv[4]={ag[si][0].x, ag[si][0].y, ag[si][1].x, ag[si][1].y};
            float aov[4]={ao[si][0].x, ao[si][0].y, ao[si][1].x, ao[si][1].y};
            #pragma unroll
            for (int ji = 0; ji < 4; ji++){
                float iv = sigf(aiv[ji]);
                float fv = sigf(afv[ji]);
                float gv = tanhfast(agv[ji]);
                float ov = sigf(aov[ji]);
                float cc = fmaf(fv, c[si][ji], iv*gv);
                c[si][ji] = cc;
                hv[si][ji] = ov*tanhfast(cc);
            }
            if (WRITE_Y){
                float4 o = make_float4(hv[si][0], hv[si][1], hv[si][2], hv[si][3]);
                *(float4*)(y_out + ((size_t)t*BNS + s0 + sb2 + si)*HD + tx*4) = o;
            }
        }
        #pragma unroll
        for (int ji = 0; ji < 4; ji++){
            float4 o = make_float4(hv[0][ji], hv[1][ji], hv[2][ji], hv[3][ji]);
            *(float4*)&Hs[(tx*4 + ji)*HP + sb2] = o;
        }
        __syncwarp();
    }
    #pragma unroll
    for (int si = 0; si < 4; si++){
        float4 o = make_float4(hv[si][0], hv[si][1], hv[si][2], hv[si][3]);
        *(float4*)(hn_out + (size_t)(s0 + sb2 + si)*HD + tx*4) = o;
    }
#endif
}

// ---------------- FC head ----------------
__global__ void k_fc(const float* __restrict__ hn1, const float* __restrict__ hn2,
                     const float* __restrict__ inner, const float* __restrict__ x,
                     const float* __restrict__ fc1w, const float* __restrict__ fc1b,
                     const float* __restrict__ fc3w, const float* __restrict__ fc3b,
                     float* __restrict__ out){
    __shared__ float Z[4][232];
    __shared__ float red[4][64];
    const int s0 = blockIdx.x*4;
    const int tid = threadIdx.x;
    for (int idx = tid; idx < 4*FC1IN; idx += 256){
        int sl = idx/FC1IN, k = idx - sl*FC1IN;
        int s = s0 + sl;
        float v;
        if (k < 64)        v = hn1[(size_t)s*HD + k];
        else if (k < 128)  v = hn2[(size_t)s*HD + k - 64];
        else if (k == 128) v = inner[s];
        else {
            int si = k - 129;
            int w = si >> 3, f = si & 7;
            int b = s/NNODE, n = s - b*NNODE;
            v = x[((size_t)(b*WIN + w)*NNODE + n)*FIN + f];
        }
        Z[sl][k] = v;
    }
    __syncthreads();
    const int sl = tid >> 6, j = tid & 63;
    float acc = fc1b[j];
    #pragma unroll 5
    for (int k = 0; k < FC1IN; k++)
        acc = fmaf(Z[sl][k], fc1w[k*HD + j], acc);
    acc = fmaxf(acc, 0.f);
    red[sl][j] = acc*fc3w[j];
    __syncthreads();
    if (tid < 4){
        float ssum = fc3b[0];
        #pragma unroll
        for (int k = 0; k < 64; k++) ssum += red[tid][k];
        out[s0 + tid] = fmaxf(ssum, 0.f);
    }
}

// ---------------- launch ----------------
extern "C" void kernel_launch(void* const* d_in, const int* in_sizes, int n_in,
                              void* d_out, int out_size){
    const int*   adj   = (const int*)  d_in[0];
    const float* w     = (const float*)d_in[1];
    const float* x     = (const float*)d_in[2];
    const float* inner = (const float*)d_in[3];
    const float* W1    = (const float*)d_in[4];
    const float* b1    = (const float*)d_in[5];
    const float* W2    = (const float*)d_in[6];
    const float* b2    = (const float*)d_in[7];
    const float* gm1   = (const float*)d_in[8];
    const float* bt1   = (const float*)d_in[9];
    const float* gm2   = (const float*)d_in[10];
    const float* bt2   = (const float*)d_in[11];
    const float* Wih1  = (const float*)d_in[12];
    const float* Whh1  = (const float*)d_in[13];
    const float* bih1  = (const float*)d_in[14];
    const float* bhh1  = (const float*)d_in[15];
    const float* Wih2  = (const float*)d_in[16];
    const float* Whh2  = (const float*)d_in[17];
    const float* bih2  = (const float*)d_in[18];
    const float* bhh2  = (const float*)d_in[19];
    const float* fc1w  = (const float*)d_in[20];
    const float* fc1b  = (const float*)d_in[21];
    const float* fc3w  = (const float*)d_in[22];
    const float* fc3b  = (const float*)d_in[23];
    float* out = (float*)d_out;

    float *deg,*dis,*xw,*agg1,*agg2,*stats,*xproj,*y1,*hn1,*hn2;
    float *whi1,*wlo1,*whi2,*wlo2,*hhi1,*hlo1,*hhi2,*hlo2;
    int *cnt,*rowstart,*cursor,*bsum; int2 *edata;
    cudaGetSymbolAddress((void**)&deg,   g_deg);
    cudaGetSymbolAddress((void**)&dis,   g_dis);
    cudaGetSymbolAddress((void**)&xw,    g_xw);
    cudaGetSymbolAddress((void**)&agg1,  g_agg1);
    cudaGetSymbolAddress((void**)&agg2,  g_agg2);
    cudaGetSymbolAddress((void**)&stats, g_stats);
    cudaGetSymbolAddress((void**)&xproj, g_xproj);
    cudaGetSymbolAddress((void**)&y1,    g_y1);
    cudaGetSymbolAddress((void**)&hn1,   g_hn1);
    cudaGetSymbolAddress((void**)&hn2,   g_hn2);
    cudaGetSymbolAddress((void**)&whi1,  g_whi1);
    cudaGetSymbolAddress((void**)&wlo1,  g_wlo1);
    cudaGetSymbolAddress((void**)&whi2,  g_whi2);
    cudaGetSymbolAddress((void**)&wlo2,  g_wlo2);
    cudaGetSymbolAddress((void**)&hhi1,  g_hhi1);
    cudaGetSymbolAddress((void**)&hlo1,  g_hlo1);
    cudaGetSymbolAddress((void**)&hhi2,  g_hhi2);
    cudaGetSymbolAddress((void**)&hlo2,  g_hlo2);
    cudaGetSymbolAddress((void**)&cnt,      g_cnt);
    cudaGetSymbolAddress((void**)&rowstart, g_rowstart);
    cudaGetSymbolAddress((void**)&cursor,   g_cursor);
    cudaGetSymbolAddress((void**)&bsum,     g_bsum);
    cudaGetSymbolAddress((void**)&edata,    g_edata);
    int* boff = bsum + 512;

    cudaFuncSetAttribute(k_lstm<true>,  cudaFuncAttributeMaxDynamicSharedMemorySize, LT_SMEM);
    cudaFuncSetAttribute(k_lstm<false>, cudaFuncAttributeMaxDynamicSharedMemorySize, LT_SMEM);
    cudaFuncSetAttribute(k_gemm_tc<128,true>,  cudaFuncAttributeMaxDynamicSharedMemorySize, TC_SMEM);
    cudaFuncSetAttribute(k_gemm_tc<64,false>,  cudaFuncAttributeMaxDynamicSharedMemorySize, TC_SMEM);

    // fused init (deg/cnt/stats + weight splits) + degree + CSR build
    k_initall  <<<NBLK, 256>>>(deg, cnt, Wih1, whi1, wlo1, Wih2, whi2, wlo2,
                               Whh1, hhi1, hlo1, Whh2, hhi2, hlo2);
    k_deg_hist <<<7813, 256>>>(adj + NE, w, deg, cnt);
    k_dis_scan <<<NBLK, 256>>>(deg, dis, cnt, bsum);
    k_scan_b   <<<1, 1024>>>(bsum, boff, rowstart);
    k_scan_c   <<<NBLK, 256>>>(cnt, boff, rowstart, cursor);
    k_scatter  <<<7813, 256>>>(adj, adj + NE, w, dis, cursor, edata);

    // GCN layer 1 (stats fused into gather)
    k_xw1       <<<375, 256>>>(x, W1, xw);
    k_agg_gather<<<24000, 256>>>(xw, dis, rowstart, edata, agg1, b1, stats);
    k_bn_fin    <<<1, 64>>>(gm1, bt1, stats);

    // GCN layer 2
    k_xw2g      <<<3000, 256>>>(agg1, W2, b1, stats, xw);
    k_agg_gather<<<24000, 256>>>(xw, dis, rowstart, edata, agg2, b2, stats + 256);
    k_bn_fin    <<<1, 64>>>(gm2, bt2, stats + 256);

    // LSTM 1 (TC gate GEMM gathers bn1(agg1)|bn2(agg2); TC recurrence)
    k_gemm_tc<128, true><<<1500, 256, TC_SMEM>>>(agg1, agg2, whi1, wlo1, bih1, bhh1, b1, b2, stats, xproj);
    k_lstm<true><<<125, 512, LT_SMEM>>>(xproj, hhi1, hlo1, Whh1, y1, hn1);

    // LSTM 2
    k_gemm_tc<64, false><<<1500, 256, TC_SMEM>>>(y1, y1, whi2, wlo2, bih2, bhh2, nullptr, nullptr, nullptr, xproj);
    k_lstm<false><<<125, 512, LT_SMEM>>>(xproj, hhi2, hlo2, Whh2, nullptr, hn2);

    // FC head
    k_fc<<<4000, 256>>>(hn1, hn2, inner, x, fc1w, fc1b, fc3w, fc3b, out);
}

// round 15
// speedup vs baseline: 1.1159x; 1.0090x over previous
#include <cuda_runtime.h>
#include <cstdint>

#define BB     8
#define WIN    12
#define NNODE  2000
#define FIN    8
#define HD     64
#define NTOT   192000          // BB*WIN*NNODE
#define NE     2000000
#define BNS    16000           // BB*NNODE sequences
#define BNEPS  1e-5f
#define FC1IN  225
#define NBLK   750             // NTOT/256

// tc-gemm smem layout (bytes)
#define TC_AHI   4096
#define TC_ALO   20480
#define TC_WHI   36864
#define TC_WLO   69632
#define TC_SMEM  102400
#define TC_IDESC 0x8400910u     // kind::tf32, f32 D, M=128, N=256, K-major both

// tc-lstm smem layout (bytes)
#define LT_H     1024
#define LT_W     (1024 + 4*16384)     // 66560
#define LT_SMEM  (66560 + 4*32768)    // 197632
#define HP       132                  // fallback Hs pitch

#if defined(__CUDA_ARCH_FEAT_SM103_ALL) || defined(__CUDA_ARCH_FEAT_SM100_ALL)
#define HAS_TCGEN05 1
#else
#define HAS_TCGEN05 0
#endif

// ---------------- scratch (device globals; allocation-free) ----------------
__device__ float g_deg[NTOT];
__device__ float g_dis[NTOT];
__device__ float g_xw  [NTOT*HD];
__device__ float g_agg1[NTOT*HD];
__device__ float g_agg2[NTOT*HD];
__device__ float g_stats[512];
__device__ float g_xproj[(size_t)WIN*BNS*4*HD];
__device__ float g_y1  [(size_t)WIN*BNS*HD];
__device__ float g_hn1 [BNS*HD];
__device__ float g_hn2 [BNS*HD];
__device__ float g_whi1[256*128];
__device__ float g_wlo1[256*128];
__device__ float g_whi2[256*64];
__device__ float g_wlo2[256*64];
__device__ float g_hhi1[256*64];
__device__ float g_hlo1[256*64];
__device__ float g_hhi2[256*64];
__device__ float g_hlo2[256*64];
// CSR scratch
__device__ int   g_cnt[NTOT];
__device__ int   g_rowstart[NTOT+1];
__device__ int   g_cursor[NTOT];
__device__ int   g_bsum[1024];
__device__ int2  g_edata[NE];

// ---------------- helpers ----------------
__device__ __forceinline__ float sigf(float x)  { return __fdividef(1.f, 1.f + __expf(-x)); }
__device__ __forceinline__ float tanhfast(float x){ return 1.f - __fdividef(2.f, __expf(2.f*x) + 1.f); }

__device__ __forceinline__ float2 ffma2(float2 a, float2 b, float2 c){
    float2 d;
    asm("fma.rn.f32x2 %0, %1, %2, %3;"
        : "=l"(reinterpret_cast<unsigned long long&>(d))
        : "l"(reinterpret_cast<unsigned long long&>(a)),
          "l"(reinterpret_cast<unsigned long long&>(b)),
          "l"(reinterpret_cast<unsigned long long&>(c)));
    return d;
}
__device__ __forceinline__ float2 dup2(float x){ return make_float2(x, x); }
__device__ __forceinline__ void fma4(float (&a)[4], float h, float4 w){
    a[0]=fmaf(h,w.x,a[0]); a[1]=fmaf(h,w.y,a[1]); a[2]=fmaf(h,w.z,a[2]); a[3]=fmaf(h,w.w,a[3]);
}
__device__ __forceinline__ float tf32r(float x){
    uint32_t u; asm("cvt.rna.tf32.f32 %0, %1;" : "=r"(u) : "f"(x));
    return __uint_as_float(u);
}

#if HAS_TCGEN05
__device__ __forceinline__ uint32_t smem_u32(const void* p){
    uint32_t a;
    asm("{ .reg .u64 t; cvta.to.shared.u64 t, %1; cvt.u32.u64 %0, t; }" : "=r"(a) : "l"(p));
    return a;
}
__device__ __forceinline__ uint32_t swz128(uint32_t off){ return off ^ ((off >> 3) & 0x70); }
__device__ __forceinline__ uint64_t mk_desc(uint32_t addr){
    return ((uint64_t)2 << 61) | ((uint64_t)1 << 46) | ((uint64_t)64 << 32) | ((uint64_t)1 << 16)
         | ((uint64_t)(addr >> 4) & 0x3FFF);
}
__device__ __forceinline__ void mma_tf32(uint32_t d, uint64_t ad, uint64_t bd, uint32_t en){
    asm volatile(
        "{\n\t.reg .pred p;\n\tsetp.ne.u32 p, %5, 0;\n\t"
        "tcgen05.mma.cta_group::1.kind::tf32 [%0], %1, %2, %3, {%4, %4, %4, %4}, p;\n\t}"
        :: "r"(d), "l"(ad), "l"(bd), "r"(TC_IDESC), "r"(0u), "r"(en) : "memory");
}
__device__ __forceinline__ void mbar_wait(uint32_t mb, uint32_t parity){
    asm volatile(
        "{\n\t.reg .pred P1;\n\t"
        "W_%=:\n\t"
        "mbarrier.try_wait.parity.acquire.cta.shared::cta.b64 P1, [%0], %1;\n\t"
        "@!P1 bra W_%=;\n\t}"
        :: "r"(mb), "r"(parity) : "memory");
}
#define LDTM_X32(r, addr) \
    asm volatile("tcgen05.ld.sync.aligned.32x32b.x32.b32 " \
        "{%0,%1,%2,%3,%4,%5,%6,%7,%8,%9,%10,%11,%12,%13,%14,%15," \
        "%16,%17,%18,%19,%20,%21,%22,%23,%24,%25,%26,%27,%28,%29,%30,%31}, [%32];" \
        : "=r"((r)[0]),"=r"((r)[1]),"=r"((r)[2]),"=r"((r)[3]),"=r"((r)[4]),"=r"((r)[5]),"=r"((r)[6]),"=r"((r)[7]), \
          "=r"((r)[8]),"=r"((r)[9]),"=r"((r)[10]),"=r"((r)[11]),"=r"((r)[12]),"=r"((r)[13]),"=r"((r)[14]),"=r"((r)[15]), \
          "=r"((r)[16]),"=r"((r)[17]),"=r"((r)[18]),"=r"((r)[19]),"=r"((r)[20]),"=r"((r)[21]),"=r"((r)[22]),"=r"((r)[23]), \
          "=r"((r)[24]),"=r"((r)[25]),"=r"((r)[26]),"=r"((r)[27]),"=r"((r)[28]),"=r"((r)[29]),"=r"((r)[30]),"=r"((r)[31]) \
        : "r"(addr))
#define LDTM_X16(r, addr) \
    asm volatile("tcgen05.ld.sync.aligned.32x32b.x16.b32 " \
        "{%0,%1,%2,%3,%4,%5,%6,%7,%8,%9,%10,%11,%12,%13,%14,%15}, [%16];" \
        : "=r"((r)[0]),"=r"((r)[1]),"=r"((r)[2]),"=r"((r)[3]),"=r"((r)[4]),"=r"((r)[5]),"=r"((r)[6]),"=r"((r)[7]), \
          "=r"((r)[8]),"=r"((r)[9]),"=r"((r)[10]),"=r"((r)[11]),"=r"((r)[12]),"=r"((r)[13]),"=r"((r)[14]),"=r"((r)[15]) \
        : "r"(addr))
#endif

// ---------------- fused init ----------------
__global__ void k_initall(float* deg, int* cnt,
                          const float* __restrict__ Wih1, float* __restrict__ whi1, float* __restrict__ wlo1,
                          const float* __restrict__ Wih2, float* __restrict__ whi2, float* __restrict__ wlo2,
                          const float* __restrict__ Whh1, float* __restrict__ hhi1, float* __restrict__ hlo1,
                          const float* __restrict__ Whh2, float* __restrict__ hhi2, float* __restrict__ hlo2){
    int i = blockIdx.x*blockDim.x + threadIdx.x;
    if (i < NTOT){ deg[i] = 1.0f; cnt[i] = 0; }
    if (i < 512) g_stats[i] = 0.f;
    if (i < 256*128){
        float v = Wih1[i]; float h = tf32r(v);
        whi1[i] = h; wlo1[i] = v - h;
    }
    if (i < 256*64){
        float v = Wih2[i]; float h = tf32r(v);
        whi2[i] = h; wlo2[i] = v - h;
        float v1 = Whh1[i]; float h1 = tf32r(v1);
        hhi1[i] = h1; hlo1[i] = v1 - h1;
        float v2 = Whh2[i]; float h2 = tf32r(v2);
        hhi2[i] = h2; hlo2[i] = v2 - h2;
    }
}
__global__ void k_deg_hist(const int* __restrict__ col, const float* __restrict__ w,
                           float* deg, int* cnt){
    int e = blockIdx.x*blockDim.x + threadIdx.x;
    if (e < NE){
        int c = col[e];
        atomicAdd(&deg[c], w[e]);
        atomicAdd(&cnt[c], 1);
    }
}
__global__ void k_dis_scan(const float* __restrict__ deg, float* dis,
                           const int* __restrict__ cnt, int* bsum){
    __shared__ int sh[256];
    int t = threadIdx.x;
    int i = blockIdx.x*256 + t;
    float d = deg[i];
    dis[i] = (d > 0.f) ? rsqrtf(d) : 0.f;
    sh[t] = cnt[i];
    __syncthreads();
    #pragma unroll
    for (int off = 128; off > 0; off >>= 1){
        if (t < off) sh[t] += sh[t + off];
        __syncthreads();
    }
    if (t == 0) bsum[blockIdx.x] = sh[0];
}
__global__ void k_scan_b(const int* __restrict__ bsum, int* boff, int* rowstart){
    __shared__ int sh[1024];
    int t = threadIdx.x;
    int v = (t < NBLK) ? bsum[t] : 0;
    sh[t] = v;
    __syncthreads();
    #pragma unroll
    for (int off = 1; off < 1024; off <<= 1){
        int x = (t >= off) ? sh[t - off] : 0;
        __syncthreads();
        sh[t] += x;
        __syncthreads();
    }
    if (t < NBLK) boff[t] = sh[t] - v;
    if (t == 0) rowstart[NTOT] = NE;
}
__global__ void k_scan_c(const int* __restrict__ cnt, const int* __restrict__ boff,
                         int* rowstart, int* cursor){
    __shared__ int sh[256];
    int t = threadIdx.x;
    int i = blockIdx.x*256 + t;
    int v = cnt[i];
    sh[t] = v;
    __syncthreads();
    #pragma unroll
    for (int off = 1; off < 256; off <<= 1){
        int x = (t >= off) ? sh[t - off] : 0;
        __syncthreads();
        sh[t] += x;
        __syncthreads();
    }
    int ex = boff[blockIdx.x] + sh[t] - v;
    rowstart[i] = ex;
    cursor[i]   = ex;
}
__global__ void k_scatter(const int* __restrict__ rows, const int* __restrict__ cols,
                          const float* __restrict__ w, const float* __restrict__ dis,
                          int* cursor, int2* edata){
    int e = blockIdx.x*blockDim.x + threadIdx.x;
    if (e >= NE) return;
    int r = rows[e], c = cols[e];
    float norm = dis[r]*w[e]*dis[c];
    int pos = atomicAdd(&cursor[c], 1);
    edata[pos] = make_int2(r, __float_as_int(norm));
}

// ---------------- xw = x @ W1  (K=8), 2 nodes per thread ----------------
__global__ void k_xw1(const float* __restrict__ x, const float* __restrict__ W, float* __restrict__ out){
    __shared__ float Ws[FIN*HD];
    for (int i = threadIdx.x; i < FIN*HD; i += blockDim.x) Ws[i] = W[i];
    __syncthreads();
    int base = (blockIdx.x*blockDim.x + threadIdx.x)*2;
    if (base >= NTOT) return;
    #pragma unroll
    for (int u = 0; u < 2; u++){
        int node = base + u;
        float xr[FIN];
        float4 v0 = *(const float4*)(x + (size_t)node*FIN);
        float4 v1 = *(const float4*)(x + (size_t)node*FIN + 4);
        xr[0]=v0.x; xr[1]=v0.y; xr[2]=v0.z; xr[3]=v0.w;
        xr[4]=v1.x; xr[5]=v1.y; xr[6]=v1.z; xr[7]=v1.w;
        #pragma unroll
        for (int j = 0; j < HD; j += 4){
            float a[4] = {0.f,0.f,0.f,0.f};
            #pragma unroll
            for (int k = 0; k < FIN; k++){
                float4 w4 = *(const float4*)&Ws[k*HD + j];
                fma4(a, xr[k], w4);
            }
            *(float4*)(out + (size_t)node*HD + j) = make_float4(a[0],a[1],a[2],a[3]);
        }
    }
}

// ---------------- aggregation: gather + fused BN stats ----------------
__global__ void __launch_bounds__(256) k_agg_gather(const float* __restrict__ xw,
                                                    const float* __restrict__ dis,
                                                    const int* __restrict__ rowstart,
                                                    const int2* __restrict__ edata,
                                                    float* __restrict__ agg,
                                                    const float* __restrict__ bias,
                                                    float* __restrict__ stats){
    __shared__ float ss [8][64];
    __shared__ float ss2[8][64];
    const int tid = threadIdx.x;
    const int wrp = tid >> 5;
    const int lane = tid & 31;
    int gw = blockIdx.x*8 + wrp;
    float va = 0.f, vb = 0.f;
    if (gw < NTOT){
        int beg = rowstart[gw], end = rowstart[gw+1];
        float d = dis[gw];
        float2 v0 = *(const float2*)(xw + (size_t)gw*HD + lane*2);
        float sc = d*d;
        float2 acc = make_float2(v0.x*sc, v0.y*sc);
        int j = beg;
        for (; j + 2 <= end; j += 2){
            int2 e0 = edata[j], e1 = edata[j+1];
            float2 a = *(const float2*)(xw + (size_t)e0.x*HD + lane*2);
            float2 b = *(const float2*)(xw + (size_t)e1.x*HD + lane*2);
            float n0 = __int_as_float(e0.y), n1 = __int_as_float(e1.y);
            acc.x = fmaf(a.x, n0, acc.x); acc.y = fmaf(a.y, n0, acc.y);
            acc.x = fmaf(b.x, n1, acc.x); acc.y = fmaf(b.y, n1, acc.y);
        }
        if (j < end){
            int2 e0 = edata[j];
            float2 a = *(const float2*)(xw + (size_t)e0.x*HD + lane*2);
            float n0 = __int_as_float(e0.y);
            acc.x = fmaf(a.x, n0, acc.x); acc.y = fmaf(a.y, n0, acc.y);
        }
        *(float2*)(agg + (size_t)gw*HD + lane*2) = acc;
        va = fmaxf(acc.x + bias[lane*2],   0.f);
        vb = fmaxf(acc.y + bias[lane*2+1], 0.f);
    }
    ss [wrp][lane*2]   = va;
    ss [wrp][lane*2+1] = vb;
    ss2[wrp][lane*2]   = va*va;
    ss2[wrp][lane*2+1] = vb*vb;
    __syncthreads();
    if (tid < 64){
        float s = 0.f, s2 = 0.f;
        #pragma unroll
        for (int w = 0; w < 8; w++){ s += ss[w][tid]; s2 += ss2[w][tid]; }
        atomicAdd(&stats[tid], s);
        atomicAdd(&stats[64+tid], s2);
    }
}

__global__ void k_bn_fin(const float* __restrict__ gamma, const float* __restrict__ beta,
                         float* __restrict__ stats){
    int ch = threadIdx.x;
    if (ch < 64){
        const float invN = 1.f/(float)NTOT;
        float m = stats[ch]*invN;
        float var = stats[64+ch]*invN - m*m;
        float sc = gamma[ch]*rsqrtf(var + BNEPS);
        stats[128+ch] = sc;
        stats[192+ch] = beta[ch] - m*sc;
    }
}

// ---------------- xw2 = bn1(agg1) @ W2  (tiled 64x64, f32x2, fused BN) ----------------
__global__ void __launch_bounds__(256) k_xw2g(const float* __restrict__ A, const float* __restrict__ W,
                                              const float* __restrict__ bias, const float* __restrict__ stats,
                                              float* __restrict__ out){
    __shared__ float As[16][64];
    __shared__ float Bs[16][68];
    __shared__ float bnb[64], bns[64], bnh[64];
    const int tid = threadIdx.x;
    if (tid < 64){ bnb[tid] = bias[tid]; bns[tid] = stats[128+tid]; bnh[tid] = stats[192+tid]; }
    __syncthreads();
    const int bm = blockIdx.x*64;
    const int lr = tid >> 2, lk = (tid & 3)*4;
    const int m  = bm + lr;
    const int ty = tid >> 4, tx = tid & 15;
    float2 acc[4][2] = {};
    for (int k0 = 0; k0 < HD; k0 += 16){
        float4 av = *(const float4*)(A + (size_t)m*HD + k0 + lk);
        int cb = k0 + lk;
        av.x = fmaxf(av.x + bnb[cb+0], 0.f)*bns[cb+0] + bnh[cb+0];
        av.y = fmaxf(av.y + bnb[cb+1], 0.f)*bns[cb+1] + bnh[cb+1];
        av.z = fmaxf(av.z + bnb[cb+2], 0.f)*bns[cb+2] + bnh[cb+2];
        av.w = fmaxf(av.w + bnb[cb+3], 0.f)*bns[cb+3] + bnh[cb+3];
        As[lk+0][lr]=av.x; As[lk+1][lr]=av.y; As[lk+2][lr]=av.z; As[lk+3][lr]=av.w;
        int kk = tid >> 4, n4 = (tid & 15)*4;
        float4 bv = *(const float4*)(W + (size_t)(k0+kk)*HD + n4);
        Bs[kk][n4+0]=bv.x; Bs[kk][n4+1]=bv.y; Bs[kk][n4+2]=bv.z; Bs[kk][n4+3]=bv.w;
        __syncthreads();
        #pragma unroll
        for (int q = 0; q < 16; q++){
            float4 a4 = *(const float4*)&As[q][ty*4];
            float4 b4 = *(const float4*)&Bs[q][tx*4];
            float2 bb0 = make_float2(b4.x, b4.y), bb1 = make_float2(b4.z, b4.w);
            float ar[4] = {a4.x, a4.y, a4.z, a4.w};
            #pragma unroll
            for (int i = 0; i < 4; i++){
                float2 ad = dup2(ar[i]);
                acc[i][0] = ffma2(ad, bb0, acc[i][0]);
                acc[i][1] = ffma2(ad, bb1, acc[i][1]);
            }
        }
        __syncthreads();
    }
    #pragma unroll
    for (int i = 0; i < 4; i++){
        int mr = bm + ty*4 + i;
        *(float4*)(out + (size_t)mr*HD + tx*4) =
            make_float4(acc[i][0].x, acc[i][0].y, acc[i][1].x, acc[i][1].y);
    }
}

// ---------------- gate GEMM: out[m][256] = A[m][KD] @ W^T + bias ----------------
// A chunk c+1 LDG-prefetched into registers while chunk c's MMA runs.
template<int KD, bool GATHER>
__global__ void __launch_bounds__(256, 2)
k_gemm_tc(const float* __restrict__ A0, const float* __restrict__ A1,
          const float* __restrict__ whi, const float* __restrict__ wlo,
          const float* __restrict__ bih, const float* __restrict__ bhh,
          const float* __restrict__ b1, const float* __restrict__ b2,
          const float* __restrict__ stats,
          float* __restrict__ out){
    extern __shared__ float sm[];
    float* bias_sm = sm + 64;           // 256 floats
    float* bnb = sm + 320; float* bns = sm + 448; float* bnh = sm + 576;
    const int tid = threadIdx.x;

    if (tid < 128){
        bias_sm[tid]     = bih[tid]     + bhh[tid];
        bias_sm[128+tid] = bih[128+tid] + bhh[128+tid];
    }
    if (GATHER && tid < 64){
        bnb[tid]    = b1[tid]; bns[tid]    = stats[128+tid]; bnh[tid]    = stats[192+tid];
        bnb[64+tid] = b2[tid]; bns[64+tid] = stats[384+tid]; bnh[64+tid] = stats[448+tid];
    }

#if HAS_TCGEN05
    char* smc = (char*)sm;
    const uint32_t sb = smem_u32(sm);
    const uint32_t mb = sb + 8;
    const int wid = tid >> 5, lane = tid & 31;
    if (wid == 0){
        asm volatile("tcgen05.alloc.cta_group::1.sync.aligned.shared::cta.b32 [%0], %1;"
                     :: "r"(sb), "r"(256u) : "memory");
        asm volatile("tcgen05.relinquish_alloc_permit.cta_group::1.sync.aligned;" ::: "memory");
    }
    if (tid == 0)
        asm volatile("mbarrier.init.shared.b64 [%0], %1;" :: "r"(mb), "r"(1u) : "memory");
    __syncthreads();
    uint32_t tmem;
    asm volatile("ld.shared.b32 %0, [%1];" : "=r"(tmem) : "r"(sb));

    const int bm = blockIdx.x*128;
    const int row = tid >> 1;
    const int j4  = (tid & 1)*4;
    const int m = bm + row;
    size_t aoff;
    if (GATHER){
        int t = m/BNS, s = m - t*BNS;
        int b = s/NNODE, n = s - b*NNODE;
        aoff = (size_t)((b*WIN + t)*NNODE + n)*HD;
    } else {
        aoff = (size_t)m*KD;
    }

    const uint64_t dAH = mk_desc(sb + TC_AHI), dAL = mk_desc(sb + TC_ALO);
    const uint64_t dWH = mk_desc(sb + TC_WHI), dWL = mk_desc(sb + TC_WLO);
    const int NCH = KD/32;
    uint32_t parity = 0;
    const uint32_t arow = (uint32_t)((row>>3)*1024 + (row&7)*128);

    // prefetch chunk 0
    float4 pf[4];
    #pragma unroll
    for (int u = 0; u < 4; u++)
        pf[u] = *(const float4*)(A0 + aoff + (j4+u)*4);

    for (int c = 0; c < NCH; c++){
        const int k0 = c*32;
        if (c > 0){ mbar_wait(mb, parity); parity ^= 1; }
        // ---- STS A chunk c from prefetch regs (BN + tf32 split) ----
        #pragma unroll
        for (int u = 0; u < 4; u++){
            int j = j4 + u;
            float4 v = pf[u];
            if (GATHER){
                int k = k0 + j*4;
                v.x = fmaxf(v.x + bnb[k+0], 0.f)*bns[k+0] + bnh[k+0];
                v.y = fmaxf(v.y + bnb[k+1], 0.f)*bns[k+1] + bnh[k+1];
                v.z = fmaxf(v.z + bnb[k+2], 0.f)*bns[k+2] + bnh[k+2];
                v.w = fmaxf(v.w + bnb[k+3], 0.f)*bns[k+3] + bnh[k+3];
            }
            float4 hi, lo;
            hi.x = tf32r(v.x); lo.x = v.x - hi.x;
            hi.y = tf32r(v.y); lo.y = v.y - hi.y;
            hi.z = tf32r(v.z); lo.z = v.z - hi.z;
            hi.w = tf32r(v.w); lo.w = v.w - hi.w;
            uint32_t sw = swz128(arow + j*16);
            *(float4*)(smc + TC_AHI + sw) = hi;
            *(float4*)(smc + TC_ALO + sw) = lo;
        }
        // ---- W chunk c (L2-hot) ----
        for (int idx = tid; idx < 2048; idx += 256){
            int g = idx >> 3, j = idx & 7;
            float4 vh = *(const float4*)(whi + (size_t)g*KD + k0 + j*4);
            float4 vl = *(const float4*)(wlo + (size_t)g*KD + k0 + j*4);
            uint32_t sw = swz128((uint32_t)((g>>3)*1024 + (g&7)*128 + j*16));
            *(float4*)(smc + TC_WHI + sw) = vh;
            *(float4*)(smc + TC_WLO + sw) = vl;
        }
        __syncthreads();
        if (tid == 0){
            asm volatile("fence.proxy.async.shared::cta;" ::: "memory");
            #pragma unroll
            for (int s = 0; s < 4; s++){
                uint64_t oa = (uint64_t)(2*s);
                uint32_t en0 = (c == 0 && s == 0) ? 0u : 1u;
                mma_tf32(tmem, dAH + oa, dWH + oa, en0);
                mma_tf32(tmem, dAH + oa, dWL + oa, 1u);
                mma_tf32(tmem, dAL + oa, dWH + oa, 1u);
            }
            asm volatile("tcgen05.commit.cta_group::1.mbarrier::arrive::one.shared::cluster.b64 [%0];"
                         :: "r"(mb) : "memory");
        }
        // ---- prefetch A chunk c+1 (overlaps MMA) ----
        if (c + 1 < NCH){
            const int k1 = (c+1)*32;
            const float* abase = GATHER ? ((k1 < 64) ? A0 : A1) : A0;
            const int koff = GATHER ? (k1 & 63) : k1;
            #pragma unroll
            for (int u = 0; u < 4; u++)
                pf[u] = *(const float4*)(abase + aoff + koff + (j4+u)*4);
        }
    }
    mbar_wait(mb, parity);
    parity ^= 1;

    asm volatile("tcgen05.fence::after_thread_sync;" ::: "memory");
    {
        int mrow = bm + (wid & 3)*32 + lane;
        int cb   = (wid >> 2)*4;
        float* op = out + (size_t)mrow*256;
        for (int b = cb; b < cb + 4; b++){
            uint32_t r[32];
            LDTM_X32(r, tmem + b*32);
            asm volatile("tcgen05.wait::ld.sync.aligned;" ::: "memory");
            #pragma unroll
            for (int q = 0; q < 8; q++){
                float4 o;
                o.x = __uint_as_float(r[q*4+0]) + bias_sm[b*32 + q*4+0];
                o.y = __uint_as_float(r[q*4+1]) + bias_sm[b*32 + q*4+1];
                o.z = __uint_as_float(r[q*4+2]) + bias_sm[b*32 + q*4+2];
                o.w = __uint_as_float(r[q*4+3]) + bias_sm[b*32 + q*4+3];
                *(float4*)(op + b*32 + q*4) = o;
            }
        }
    }
    __syncthreads();
    if (tid == 0)
        asm volatile("mbarrier.inval.shared.b64 [%0];" :: "r"(mb) : "memory");
    __syncthreads();
    if (wid == 0)
        asm volatile("tcgen05.dealloc.cta_group::1.sync.aligned.b32 %0, %1;"
                     :: "r"(tmem), "r"(256u) : "memory");
#else
    // -------- FFMA2 fallback --------
    float* As = sm + 1024;                 // [16][68]
    float* Bs = sm + 1024 + 16*68;         // [16][260]
    __syncthreads();
    const int bm = blockIdx.x*128;
    const int lr = tid >> 2, lk = (tid & 3)*4;
    const int ty = tid >> 5, tx = tid & 31;
    for (int mh = 0; mh < 2; mh++){
        const int m = bm + mh*64 + lr;
        size_t aoff;
        if (GATHER){
            int t = m/BNS, s = m - t*BNS;
            int b = s/NNODE, n = s - b*NNODE;
            aoff = (size_t)((b*WIN + t)*NNODE + n)*HD;
        } else aoff = (size_t)m*KD;
        float2 acc[8][4] = {};
        for (int k0 = 0; k0 < KD; k0 += 16){
            int k = k0 + lk;
            const float* abase = GATHER ? ((k < 64) ? A0 : A1) : A0;
            int ko = GATHER ? (k & 63) : k;
            float4 v = *(const float4*)(abase + aoff + ko);
            if (GATHER){
                v.x = fmaxf(v.x + bnb[k+0], 0.f)*bns[k+0] + bnh[k+0];
                v.y = fmaxf(v.y + bnb[k+1], 0.f)*bns[k+1] + bnh[k+1];
                v.z = fmaxf(v.z + bnb[k+2], 0.f)*bns[k+2] + bnh[k+2];
                v.w = fmaxf(v.w + bnb[k+3], 0.f)*bns[k+3] + bnh[k+3];
            }
            As[(lk+0)*68 + lr] = v.x;
            As[(lk+1)*68 + lr] = v.y;
            As[(lk+2)*68 + lr] = v.z;
            As[(lk+3)*68 + lr] = v.w;
            for (int i = tid; i < 1024; i += 256){
                int g = i >> 2, kq = (i & 3)*4;
                float4 vh = *(const float4*)(whi + (size_t)g*KD + k0 + kq);
                float4 vl = *(const float4*)(wlo + (size_t)g*KD + k0 + kq);
                Bs[(kq+0)*260 + g] = vh.x + vl.x;
                Bs[(kq+1)*260 + g] = vh.y + vl.y;
                Bs[(kq+2)*260 + g] = vh.z + vl.z;
                Bs[(kq+3)*260 + g] = vh.w + vl.w;
            }
            __syncthreads();
            #pragma unroll
            for (int kk = 0; kk < 16; kk++){
                float4 a0 = *(const float4*)&As[kk*68 + ty*8];
                float4 a1 = *(const float4*)&As[kk*68 + ty*8 + 4];
                float4 b0 = *(const float4*)&Bs[kk*260 + tx*8];
                float4 b1v = *(const float4*)&Bs[kk*260 + tx*8 + 4];
                float2 bb[4] = {make_float2(b0.x,b0.y), make_float2(b0.z,b0.w),
                                make_float2(b1v.x,b1v.y), make_float2(b1v.z,b1v.w)};
                float ar[8] = {a0.x,a0.y,a0.z,a0.w, a1.x,a1.y,a1.z,a1.w};
                #pragma unroll
                for (int i = 0; i < 8; i++){
                    float2 ad = dup2(ar[i]);
                    #pragma unroll
                    for (int p = 0; p < 4; p++)
                        acc[i][p] = ffma2(ad, bb[p], acc[i][p]);
                }
            }
            __syncthreads();
        }
        #pragma unroll
        for (int i = 0; i < 8; i++){
            int mr = bm + mh*64 + ty*8 + i;
            float* op = out + (size_t)mr*256 + tx*8;
            const float* bz = bias_sm + tx*8;
            *(float4*)(op)   = make_float4(acc[i][0].x+bz[0], acc[i][0].y+bz[1],
                                           acc[i][1].x+bz[2], acc[i][1].y+bz[3]);
            *(float4*)(op+4) = make_float4(acc[i][2].x+bz[4], acc[i][2].y+bz[5],
                                           acc[i][3].x+bz[6], acc[i][3].y+bz[7]);
        }
    }
#endif
}

// ---------------- LSTM: 128 seqs / block, 512 threads, TC recurrence ----------------
template<bool WRITE_Y>
__global__ void __launch_bounds__(512, 1) k_lstm(const float* __restrict__ xproj,
                                                 const float* __restrict__ whh_hi,
                                                 const float* __restrict__ whh_lo,
                                                 const float* __restrict__ Whh_raw,
                                                 float* __restrict__ y_out,
                                                 float* __restrict__ hn_out){
    extern __shared__ float sm[];
    const int tid = threadIdx.x;
#if HAS_TCGEN05
    char* smc = (char*)sm;
    const uint32_t sb = smem_u32(sm);
    const uint32_t mb = sb + 8;
    const int wid = tid >> 5, lane = tid & 31;
    for (int idx = tid; idx < 4096; idx += 512){
        int c = idx >> 11;
        int r = idx & 2047;
        int g = r >> 3, j = r & 7;
        uint32_t sw = swz128((uint32_t)((g>>3)*1024 + (g&7)*128 + j*16));
        *(float4*)(smc + LT_W + (c*2+0)*32768 + sw) = *(const float4*)(whh_hi + g*64 + c*32 + j*4);
        *(float4*)(smc + LT_W + (c*2+1)*32768 + sw) = *(const float4*)(whh_lo + g*64 + c*32 + j*4);
    }
    if (wid == 0){
        asm volatile("tcgen05.alloc.cta_group::1.sync.aligned.shared::cta.b32 [%0], %1;"
                     :: "r"(sb), "r"(256u) : "memory");
        asm volatile("tcgen05.relinquish_alloc_permit.cta_group::1.sync.aligned;" ::: "memory");
    }
    if (tid == 0)
        asm volatile("mbarrier.init.shared.b64 [%0], %1;" :: "r"(mb), "r"(1u) : "memory");
    __syncthreads();
    uint32_t tmem;
    asm volatile("ld.shared.b32 %0, [%1];" : "=r"(tmem) : "r"(sb));

    uint64_t dH[2][2], dW[2][2];
    #pragma unroll
    for (int c = 0; c < 2; c++)
        #pragma unroll
        for (int p = 0; p < 2; p++){
            dH[c][p] = mk_desc(sb + LT_H + (uint32_t)(c*2+p)*16384);
            dW[c][p] = mk_desc(sb + LT_W + (uint32_t)(c*2+p)*32768);
        }

    const int sp  = wid & 3;
    const int seq = sp*32 + lane;
    const int j0  = (wid >> 2)*16;
    const int s0  = blockIdx.x*128;
    const int ch  = j0 >> 5;
    const int kw  = j0 & 31;
    const uint32_t hrow = (uint32_t)((seq>>3)*1024 + (seq&7)*128);
    float cst[16];
    #pragma unroll
    for (int i = 0; i < 16; i++) cst[i] = 0.f;
    uint32_t parity = 0;

    for (int t = 0; t < WIN; t++){
        if (t > 0){
            __syncthreads();
            if (tid == 0){
                asm volatile("fence.proxy.async.shared::cta;" ::: "memory");
                bool first = true;
                #pragma unroll
                for (int c = 0; c < 2; c++){
                    #pragma unroll
                    for (int s = 0; s < 4; s++){
                        uint64_t oa = (uint64_t)(2*s);
                        mma_tf32(tmem, dH[c][0] + oa, dW[c][0] + oa, first ? 0u : 1u);
                        first = false;
                        mma_tf32(tmem, dH[c][0] + oa, dW[c][1] + oa, 1u);
                        mma_tf32(tmem, dH[c][1] + oa, dW[c][0] + oa, 1u);
                    }
                }
                asm volatile("tcgen05.commit.cta_group::1.mbarrier::arrive::one.shared::cluster.b64 [%0];"
                             :: "r"(mb) : "memory");
            }
        }
        const float* xp = xproj + ((size_t)t*BNS + s0 + seq)*256 + j0;
        float gi[16], gf[16], gg[16], go[16];
        #pragma unroll
        for (int q = 0; q < 4; q++){
            float4 v;
            v = *(const float4*)(xp + q*4);        gi[q*4]=v.x; gi[q*4+1]=v.y; gi[q*4+2]=v.z; gi[q*4+3]=v.w;
            v = *(const float4*)(xp + 64 + q*4);   gf[q*4]=v.x; gf[q*4+1]=v.y; gf[q*4+2]=v.z; gf[q*4+3]=v.w;
            v = *(const float4*)(xp + 128 + q*4);  gg[q*4]=v.x; gg[q*4+1]=v.y; gg[q*4+2]=v.z; gg[q*4+3]=v.w;
            v = *(const float4*)(xp + 192 + q*4);  go[q*4]=v.x; go[q*4+1]=v.y; go[q*4+2]=v.z; go[q*4+3]=v.w;
        }
        if (t > 0){
            mbar_wait(mb, parity);
            parity ^= 1;
            asm volatile("tcgen05.fence::after_thread_sync;" ::: "memory");
            uint32_t ri[16], rf[16], rg[16], ro[16];
            LDTM_X16(ri, tmem + j0);
            LDTM_X16(rf, tmem + 64 + j0);
            LDTM_X16(rg, tmem + 128 + j0);
            LDTM_X16(ro, tmem + 192 + j0);
            asm volatile("tcgen05.wait::ld.sync.aligned;" ::: "memory");
            #pragma unroll
            for (int i = 0; i < 16; i++){
                gi[i] += __uint_as_float(ri[i]);
                gf[i] += __uint_as_float(rf[i]);
                gg[i] += __uint_as_float(rg[i]);
                go[i] += __uint_as_float(ro[i]);
            }
            asm volatile("tcgen05.fence::before_thread_sync;" ::: "memory");
        }
        float hv[16];
        #pragma unroll
        for (int i = 0; i < 16; i++){
            float iv = sigf(gi[i]);
            float fv = sigf(gf[i]);
            float gv = tanhfast(gg[i]);
            float ov = sigf(go[i]);
            float cc = fmaf(fv, cst[i], iv*gv);
            cst[i] = cc;
            hv[i] = ov*tanhfast(cc);
        }
        if (WRITE_Y){
            float* yp = y_out + ((size_t)t*BNS + s0 + seq)*HD + j0;
            #pragma unroll
            for (int q = 0; q < 4; q++)
                *(float4*)(yp + q*4) = make_float4(hv[q*4], hv[q*4+1], hv[q*4+2], hv[q*4+3]);
        }
        if (t == WIN-1){
            float* hp = hn_out + (size_t)(s0 + seq)*HD + j0;
            #pragma unroll
            for (int q = 0; q < 4; q++)
                *(float4*)(hp + q*4) = make_float4(hv[q*4], hv[q*4+1], hv[q*4+2], hv[q*4+3]);
        }
        #pragma unroll
        for (int q = 0; q < 4; q++){
            float4 hi, lo;
            hi.x = tf32r(hv[q*4+0]); lo.x = hv[q*4+0] - hi.x;
            hi.y = tf32r(hv[q*4+1]); lo.y = hv[q*4+1] - hi.y;
            hi.z = tf32r(hv[q*4+2]); lo.z = hv[q*4+2] - hi.z;
            hi.w = tf32r(hv[q*4+3]); lo.w = hv[q*4+3] - hi.w;
            uint32_t sw = swz128(hrow + (uint32_t)(kw/4 + q)*16);
            *(float4*)(smc + LT_H + (ch*2+0)*16384 + sw) = hi;
            *(float4*)(smc + LT_H + (ch*2+1)*16384 + sw) = lo;
        }
    }
    __syncthreads();
    if (tid == 0)
        asm volatile("mbarrier.inval.shared.b64 [%0];" :: "r"(mb) : "memory");
    __syncthreads();
    if (wid == 0)
        asm volatile("tcgen05.dealloc.cta_group::1.sync.aligned.b32 %0, %1;"
                     :: "r"(tmem), "r"(256u) : "memory");
#else
    // -------- FFMA2 fallback --------
    float* Ws = sm;
    float* Hs = sm + 16384;
    for (int i = tid; i < 16384; i += 512){ int g = i >> 6, k = i & 63; Ws[k*256 + g] = Whh_raw[i]; }
    for (int i = tid; i < 64*HP; i += 512) Hs[i] = 0.f;
    __syncthreads();
    const int tx = tid & 15;
    const int ty = tid >> 4;
    const int s0 = blockIdx.x*128;
    const int sb2 = ty*4;
    float c[4][4]  = {};
    float hv[4][4] = {};
    for (int t = 0; t < WIN; t++){
        float2 ai[4][2], af[4][2], ag[4][2], ao[4][2];
        #pragma unroll
        for (int si = 0; si < 4; si++){
            const float* xp = xproj + ((size_t)t*BNS + (s0 + sb2 + si))*256 + tx*4;
            float4 vi = *(const float4*)(xp);
            float4 vf = *(const float4*)(xp + 64);
            float4 vg = *(const float4*)(xp + 128);
            float4 vo = *(const float4*)(xp + 192);
            ai[si][0]=make_float2(vi.x,vi.y); ai[si][1]=make_float2(vi.z,vi.w);
            af[si][0]=make_float2(vf.x,vf.y); af[si][1]=make_float2(vf.z,vf.w);
            ag[si][0]=make_float2(vg.x,vg.y); ag[si][1]=make_float2(vg.z,vg.w);
            ao[si][0]=make_float2(vo.x,vo.y); ao[si][1]=make_float2(vo.z,vo.w);
        }
        #pragma unroll 4
        for (int k = 0; k < 64; k++){
            float4 h4 = *(const float4*)&Hs[k*HP + sb2];
            const float* wr = &Ws[k*256 + tx*4];
            float4 wi4 = *(const float4*)(wr);
            float4 wf4 = *(const float4*)(wr + 64);
            float4 wg4 = *(const float4*)(wr + 128);
            float4 wo4 = *(const float4*)(wr + 192);
            float2 wi0=make_float2(wi4.x,wi4.y), wi1=make_float2(wi4.z,wi4.w);
            float2 wf0=make_float2(wf4.x,wf4.y), wf1=make_float2(wf4.z,wf4.w);
            float2 wg0=make_float2(wg4.x,wg4.y), wg1=make_float2(wg4.z,wg4.w);
            float2 wo0=make_float2(wo4.x,wo4.y), wo1=make_float2(wo4.z,wo4.w);
            float hs[4] = {h4.x, h4.y, h4.z, h4.w};
            #pragma unroll
            for (int si = 0; si < 4; si++){
                float2 hd = dup2(hs[si]);
                ai[si][0]=ffma2(hd,wi0,ai[si][0]); ai[si][1]=ffma2(hd,wi1,ai[si][1]);
                af[si][0]=ffma2(hd,wf0,af[si][0]); af[si][1]=ffma2(hd,wf1,af[si][1]);
                ag[si][0]=ffma2(hd,wg0,ag[si][0]); ag[si][1]=ffma2(hd,wg1,ag[si][1]);
                ao[si][0]=ffma2(hd,wo0,ao[si][0]); ao[si][1]=ffma2(hd,wo1,ao[si][1]);
            }
        }
        __syncwarp();
        #pragma unroll
        for (int si = 0; si < 4; si++){
            float aiv[4]={ai[si][0].x, ai[si][0].y, ai[si][1].x, ai[si][1].y};
            float afv[4]={af[si][0].x, af[si][0].y, af[si][1].x, af[si][1].y};
            float agv[4]={ag[si][0].x, ag[si][0].y, ag[si][1].x, ag[si][1].y};
            float aov[4]={ao[si][0].x, ao[si][0].y, ao[si][1].x, ao[si][1].y};
            #pragma unroll
            for (int ji = 0; ji < 4; ji++){
                float iv = sigf(aiv[ji]);
                float fv = sigf(afv[ji]);
                float gv = tanhfast(agv[ji]);
                float ov = sigf(aov[ji]);
                float cc = fmaf(fv, c[si][ji], iv*gv);
                c[si][ji] = cc;
                hv[si][ji] = ov*tanhfast(cc);
            }
            if (WRITE_Y){
                float4 o = make_float4(hv[si][0], hv[si][1], hv[si][2], hv[si][3]);
                *(float4*)(y_out + ((size_t)t*BNS + s0 + sb2 + si)*HD + tx*4) = o;
            }
        }
        #pragma unroll
        for (int ji = 0; ji < 4; ji++){
            float4 o = make_float4(hv[0][ji], hv[1][ji], hv[2][ji], hv[3][ji]);
            *(float4*)&Hs[(tx*4 + ji)*HP + sb2] = o;
        }
        __syncwarp();
    }
    #pragma unroll
    for (int si = 0; si < 4; si++){
        float4 o = make_float4(hv[si][0], hv[si][1], hv[si][2], hv[si][3]);
        *(float4*)(hn_out + (size_t)(s0 + sb2 + si)*HD + tx*4) = o;
    }
#endif
}

// ---------------- FC head ----------------
__global__ void k_fc(const float* __restrict__ hn1, const float* __restrict__ hn2,
                     const float* __restrict__ inner, const float* __restrict__ x,
                     const float* __restrict__ fc1w, const float* __restrict__ fc1b,
                     const float* __restrict__ fc3w, const float* __restrict__ fc3b,
                     float* __restrict__ out){
    __shared__ float Z[4][232];
    __shared__ float red[4][64];
    const int s0 = blockIdx.x*4;
    const int tid = threadIdx.x;
    for (int idx = tid; idx < 4*FC1IN; idx += 256){
        int sl = idx/FC1IN, k = idx - sl*FC1IN;
        int s = s0 + sl;
        float v;
        if (k < 64)        v = hn1[(size_t)s*HD + k];
        else if (k < 128)  v = hn2[(size_t)s*HD + k - 64];
        else if (k == 128) v = inner[s];
        else {
            int si = k - 129;
            int w = si >> 3, f = si & 7;
            int b = s/NNODE, n = s - b*NNODE;
            v = x[((size_t)(b*WIN + w)*NNODE + n)*FIN + f];
        }
        Z[sl][k] = v;
    }
    __syncthreads();
    const int sl = tid >> 6, j = tid & 63;
    float acc = fc1b[j];
    #pragma unroll 5
    for (int k = 0; k < FC1IN; k++)
        acc = fmaf(Z[sl][k], fc1w[k*HD + j], acc);
    acc = fmaxf(acc, 0.f);
    red[sl][j] = acc*fc3w[j];
    __syncthreads();
    if (tid < 4){
        float ssum = fc3b[0];
        #pragma unroll
        for (int k = 0; k < 64; k++) ssum += red[tid][k];
        out[s0 + tid] = fmaxf(ssum, 0.f);
    }
}

// ---------------- launch ----------------
extern "C" void kernel_launch(void* const* d_in, const int* in_sizes, int n_in,
                              void* d_out, int out_size){
    const int*   adj   = (const int*)  d_in[0];
    const float* w     = (const float*)d_in[1];
    const float* x     = (const float*)d_in[2];
    const float* inner = (const float*)d_in[3];
    const float* W1    = (const float*)d_in[4];
    const float* b1    = (const float*)d_in[5];
    const float* W2    = (const float*)d_in[6];
    const float* b2    = (const float*)d_in[7];
    const float* gm1   = (const float*)d_in[8];
    const float* bt1   = (const float*)d_in[9];
    const float* gm2   = (const float*)d_in[10];
    const float* bt2   = (const float*)d_in[11];
    const float* Wih1  = (const float*)d_in[12];
    const float* Whh1  = (const float*)d_in[13];
    const float* bih1  = (const float*)d_in[14];
    const float* bhh1  = (const float*)d_in[15];
    const float* Wih2  = (const float*)d_in[16];
    const float* Whh2  = (const float*)d_in[17];
    const float* bih2  = (const float*)d_in[18];
    const float* bhh2  = (const float*)d_in[19];
    const float* fc1w  = (const float*)d_in[20];
    const float* fc1b  = (const float*)d_in[21];
    const float* fc3w  = (const float*)d_in[22];
    const float* fc3b  = (const float*)d_in[23];
    float* out = (float*)d_out;

    float *deg,*dis,*xw,*agg1,*agg2,*stats,*xproj,*y1,*hn1,*hn2;
    float *whi1,*wlo1,*whi2,*wlo2,*hhi1,*hlo1,*hhi2,*hlo2;
    int *cnt,*rowstart,*cursor,*bsum; int2 *edata;
    cudaGetSymbolAddress((void**)&deg,   g_deg);
    cudaGetSymbolAddress((void**)&dis,   g_dis);
    cudaGetSymbolAddress((void**)&xw,    g_xw);
    cudaGetSymbolAddress((void**)&agg1,  g_agg1);
    cudaGetSymbolAddress((void**)&agg2,  g_agg2);
    cudaGetSymbolAddress((void**)&stats, g_stats);
    cudaGetSymbolAddress((void**)&xproj, g_xproj);
    cudaGetSymbolAddress((void**)&y1,    g_y1);
    cudaGetSymbolAddress((void**)&hn1,   g_hn1);
    cudaGetSymbolAddress((void**)&hn2,   g_hn2);
    cudaGetSymbolAddress((void**)&whi1,  g_whi1);
    cudaGetSymbolAddress((void**)&wlo1,  g_wlo1);
    cudaGetSymbolAddress((void**)&whi2,  g_whi2);
    cudaGetSymbolAddress((void**)&wlo2,  g_wlo2);
    cudaGetSymbolAddress((void**)&hhi1,  g_hhi1);
    cudaGetSymbolAddress((void**)&hlo1,  g_hlo1);
    cudaGetSymbolAddress((void**)&hhi2,  g_hhi2);
    cudaGetSymbolAddress((void**)&hlo2,  g_hlo2);
    cudaGetSymbolAddress((void**)&cnt,      g_cnt);
    cudaGetSymbolAddress((void**)&rowstart, g_rowstart);
    cudaGetSymbolAddress((void**)&cursor,   g_cursor);
    cudaGetSymbolAddress((void**)&bsum,     g_bsum);
    cudaGetSymbolAddress((void**)&edata,    g_edata);
    int* boff = bsum + 512;

    cudaFuncSetAttribute(k_lstm<true>,  cudaFuncAttributeMaxDynamicSharedMemorySize, LT_SMEM);
    cudaFuncSetAttribute(k_lstm<false>, cudaFuncAttributeMaxDynamicSharedMemorySize, LT_SMEM);
    cudaFuncSetAttribute(k_gemm_tc<128,true>,  cudaFuncAttributeMaxDynamicSharedMemorySize, TC_SMEM);
    cudaFuncSetAttribute(k_gemm_tc<64,false>,  cudaFuncAttributeMaxDynamicSharedMemorySize, TC_SMEM);

    // fused init + degree + CSR build
    k_initall  <<<NBLK, 256>>>(deg, cnt, Wih1, whi1, wlo1, Wih2, whi2, wlo2,
                               Whh1, hhi1, hlo1, Whh2, hhi2, hlo2);
    k_deg_hist <<<7813, 256>>>(adj + NE, w, deg, cnt);
    k_dis_scan <<<NBLK, 256>>>(deg, dis, cnt, bsum);
    k_scan_b   <<<1, 1024>>>(bsum, boff, rowstart);
    k_scan_c   <<<NBLK, 256>>>(cnt, boff, rowstart, cursor);
    k_scatter  <<<7813, 256>>>(adj, adj + NE, w, dis, cursor, edata);

    // GCN layer 1 (stats fused into gather)
    k_xw1       <<<375, 256>>>(x, W1, xw);
    k_agg_gather<<<24000, 256>>>(xw, dis, rowstart, edata, agg1, b1, stats);
    k_bn_fin    <<<1, 64>>>(gm1, bt1, stats);

    // GCN layer 2
    k_xw2g      <<<3000, 256>>>(agg1, W2, b1, stats, xw);
    k_agg_gather<<<24000, 256>>>(xw, dis, rowstart, edata, agg2, b2, stats + 256);
    k_bn_fin    <<<1, 64>>>(gm2, bt2, stats + 256);

    // LSTM 1 (TC gate GEMM; TC recurrence)
    k_gemm_tc<128, true><<<1500, 256, TC_SMEM>>>(agg1, agg2, whi1, wlo1, bih1, bhh1, b1, b2, stats, xproj);
    k_lstm<true><<<125, 512, LT_SMEM>>>(xproj, hhi1, hlo1, Whh1, y1, hn1);

    // LSTM 2
    k_gemm_tc<64, false><<<1500, 256, TC_SMEM>>>(y1, y1, whi2, wlo2, bih2, bhh2, nullptr, nullptr, nullptr, xproj);
    k_lstm<false><<<125, 512, LT_SMEM>>>(xproj, hhi2, hlo2, Whh2, nullptr, hn2);

    // FC head
    k_fc<<<4000, 256>>>(hn1, hn2, inner, x, fc1w, fc1b, fc3w, fc3b, out);
}

// round 16
// speedup vs baseline: 1.1420x; 1.0234x over previous
#include <cuda_runtime.h>
#include <cstdint>

#define BB     8
#define WIN    12
#define NNODE  2000
#define FIN    8
#define HD     64
#define NTOT   192000          // BB*WIN*NNODE
#define NE     2000000
#define BNS    16000           // BB*NNODE sequences
#define BNEPS  1e-5f
#define FC1IN  225
#define NBLK   750             // NTOT/256

// tc-gemm smem layout (bytes)
#define TC_AHI   4096
#define TC_ALO   20480
#define TC_WHI   36864
#define TC_WLO   69632
#define TC_SMEM  102400
#define TC_IDESC 0x8400910u     // kind::tf32, f32 D, M=128, N=256, K-major both

// tc-lstm smem layout (bytes)
#define LT_H     1024
#define LT_W     (1024 + 4*16384)     // 66560
#define LT_SMEM  (66560 + 4*32768)    // 197632
#define HP       132                  // fallback Hs pitch

#if defined(__CUDA_ARCH_FEAT_SM103_ALL) || defined(__CUDA_ARCH_FEAT_SM100_ALL)
#define HAS_TCGEN05 1
#else
#define HAS_TCGEN05 0
#endif

// ---------------- scratch (device globals; allocation-free) ----------------
__device__ float g_deg[NTOT];
__device__ float g_dis[NTOT];
__device__ float g_xw  [NTOT*HD];
__device__ float g_agg1[NTOT*HD];
__device__ float g_agg2[NTOT*HD];
__device__ float g_stats[512];
__device__ float g_xproj[(size_t)WIN*BNS*4*HD];
__device__ float g_y1  [(size_t)WIN*BNS*HD];
__device__ float g_hn1 [BNS*HD];
__device__ float g_hn2 [BNS*HD];
__device__ float g_whi1[256*128];
__device__ float g_wlo1[256*128];
__device__ float g_whi2[256*64];
__device__ float g_wlo2[256*64];
__device__ float g_hhi1[256*64];
__device__ float g_hlo1[256*64];
__device__ float g_hhi2[256*64];
__device__ float g_hlo2[256*64];
// CSR scratch
__device__ int   g_cnt[NTOT];
__device__ int   g_rowstart[NTOT+1];
__device__ int   g_cursor[NTOT];
__device__ int   g_bsum[1024];
__device__ int2  g_edata[NE];

// ---------------- helpers ----------------
__device__ __forceinline__ float sigf(float x)  { return __fdividef(1.f, 1.f + __expf(-x)); }
__device__ __forceinline__ float tanhfast(float x){ return 1.f - __fdividef(2.f, __expf(2.f*x) + 1.f); }

__device__ __forceinline__ float2 ffma2(float2 a, float2 b, float2 c){
    float2 d;
    asm("fma.rn.f32x2 %0, %1, %2, %3;"
        : "=l"(reinterpret_cast<unsigned long long&>(d))
        : "l"(reinterpret_cast<unsigned long long&>(a)),
          "l"(reinterpret_cast<unsigned long long&>(b)),
          "l"(reinterpret_cast<unsigned long long&>(c)));
    return d;
}
__device__ __forceinline__ float2 dup2(float x){ return make_float2(x, x); }
__device__ __forceinline__ void fma4(float (&a)[4], float h, float4 w){
    a[0]=fmaf(h,w.x,a[0]); a[1]=fmaf(h,w.y,a[1]); a[2]=fmaf(h,w.z,a[2]); a[3]=fmaf(h,w.w,a[3]);
}
__device__ __forceinline__ float tf32r(float x){
    uint32_t u; asm("cvt.rna.tf32.f32 %0, %1;" : "=r"(u) : "f"(x));
    return __uint_as_float(u);
}

#if HAS_TCGEN05
__device__ __forceinline__ uint32_t smem_u32(const void* p){
    uint32_t a;
    asm("{ .reg .u64 t; cvta.to.shared.u64 t, %1; cvt.u32.u64 %0, t; }" : "=r"(a) : "l"(p));
    return a;
}
__device__ __forceinline__ uint32_t swz128(uint32_t off){ return off ^ ((off >> 3) & 0x70); }
__device__ __forceinline__ uint64_t mk_desc(uint32_t addr){
    return ((uint64_t)2 << 61) | ((uint64_t)1 << 46) | ((uint64_t)64 << 32) | ((uint64_t)1 << 16)
         | ((uint64_t)(addr >> 4) & 0x3FFF);
}
__device__ __forceinline__ void mma_tf32(uint32_t d, uint64_t ad, uint64_t bd, uint32_t en){
    asm volatile(
        "{\n\t.reg .pred p;\n\tsetp.ne.u32 p, %5, 0;\n\t"
        "tcgen05.mma.cta_group::1.kind::tf32 [%0], %1, %2, %3, {%4, %4, %4, %4}, p;\n\t}"
        :: "r"(d), "l"(ad), "l"(bd), "r"(TC_IDESC), "r"(0u), "r"(en) : "memory");
}
__device__ __forceinline__ void mbar_wait(uint32_t mb, uint32_t parity){
    asm volatile(
        "{\n\t.reg .pred P1;\n\t"
        "W_%=:\n\t"
        "mbarrier.try_wait.parity.acquire.cta.shared::cta.b64 P1, [%0], %1;\n\t"
        "@!P1 bra W_%=;\n\t}"
        :: "r"(mb), "r"(parity) : "memory");
}
#define LDTM_X32(r, addr) \
    asm volatile("tcgen05.ld.sync.aligned.32x32b.x32.b32 " \
        "{%0,%1,%2,%3,%4,%5,%6,%7,%8,%9,%10,%11,%12,%13,%14,%15," \
        "%16,%17,%18,%19,%20,%21,%22,%23,%24,%25,%26,%27,%28,%29,%30,%31}, [%32];" \
        : "=r"((r)[0]),"=r"((r)[1]),"=r"((r)[2]),"=r"((r)[3]),"=r"((r)[4]),"=r"((r)[5]),"=r"((r)[6]),"=r"((r)[7]), \
          "=r"((r)[8]),"=r"((r)[9]),"=r"((r)[10]),"=r"((r)[11]),"=r"((r)[12]),"=r"((r)[13]),"=r"((r)[14]),"=r"((r)[15]), \
          "=r"((r)[16]),"=r"((r)[17]),"=r"((r)[18]),"=r"((r)[19]),"=r"((r)[20]),"=r"((r)[21]),"=r"((r)[22]),"=r"((r)[23]), \
          "=r"((r)[24]),"=r"((r)[25]),"=r"((r)[26]),"=r"((r)[27]),"=r"((r)[28]),"=r"((r)[29]),"=r"((r)[30]),"=r"((r)[31]) \
        : "r"(addr))
#define LDTM_X16(r, addr) \
    asm volatile("tcgen05.ld.sync.aligned.32x32b.x16.b32 " \
        "{%0,%1,%2,%3,%4,%5,%6,%7,%8,%9,%10,%11,%12,%13,%14,%15}, [%16];" \
        : "=r"((r)[0]),"=r"((r)[1]),"=r"((r)[2]),"=r"((r)[3]),"=r"((r)[4]),"=r"((r)[5]),"=r"((r)[6]),"=r"((r)[7]), \
          "=r"((r)[8]),"=r"((r)[9]),"=r"((r)[10]),"=r"((r)[11]),"=r"((r)[12]),"=r"((r)[13]),"=r"((r)[14]),"=r"((r)[15]) \
        : "r"(addr))
#endif

// ---------------- fused init ----------------
__global__ void k_initall(float* deg, int* cnt,
                          const float* __restrict__ Wih1, float* __restrict__ whi1, float* __restrict__ wlo1,
                          const float* __restrict__ Wih2, float* __restrict__ whi2, float* __restrict__ wlo2,
                          const float* __restrict__ Whh1, float* __restrict__ hhi1, float* __restrict__ hlo1,
                          const float* __restrict__ Whh2, float* __restrict__ hhi2, float* __restrict__ hlo2){
    int i = blockIdx.x*blockDim.x + threadIdx.x;
    if (i < NTOT){ deg[i] = 1.0f; cnt[i] = 0; }
    if (i < 512) g_stats[i] = 0.f;
    if (i < 256*128){
        float v = Wih1[i]; float h = tf32r(v);
        whi1[i] = h; wlo1[i] = v - h;
    }
    if (i < 256*64){
        float v = Wih2[i]; float h = tf32r(v);
        whi2[i] = h; wlo2[i] = v - h;
        float v1 = Whh1[i]; float h1 = tf32r(v1);
        hhi1[i] = h1; hlo1[i] = v1 - h1;
        float v2 = Whh2[i]; float h2 = tf32r(v2);
        hhi2[i] = h2; hlo2[i] = v2 - h2;
    }
}
__global__ void k_deg_hist(const int* __restrict__ col, const float* __restrict__ w,
                           float* deg, int* cnt){
    int e = blockIdx.x*blockDim.x + threadIdx.x;
    if (e < NE){
        int c = col[e];
        atomicAdd(&deg[c], w[e]);
        atomicAdd(&cnt[c], 1);
    }
}
__global__ void k_dis_scan(const float* __restrict__ deg, float* dis,
                           const int* __restrict__ cnt, int* bsum){
    __shared__ int sh[256];
    int t = threadIdx.x;
    int i = blockIdx.x*256 + t;
    float d = deg[i];
    dis[i] = (d > 0.f) ? rsqrtf(d) : 0.f;
    sh[t] = cnt[i];
    __syncthreads();
    #pragma unroll
    for (int off = 128; off > 0; off >>= 1){
        if (t < off) sh[t] += sh[t + off];
        __syncthreads();
    }
    if (t == 0) bsum[blockIdx.x] = sh[0];
}
__global__ void k_scan_b(const int* __restrict__ bsum, int* boff, int* rowstart){
    __shared__ int sh[1024];
    int t = threadIdx.x;
    int v = (t < NBLK) ? bsum[t] : 0;
    sh[t] = v;
    __syncthreads();
    #pragma unroll
    for (int off = 1; off < 1024; off <<= 1){
        int x = (t >= off) ? sh[t - off] : 0;
        __syncthreads();
        sh[t] += x;
        __syncthreads();
    }
    if (t < NBLK) boff[t] = sh[t] - v;
    if (t == 0) rowstart[NTOT] = NE;
}
__global__ void k_scan_c(const int* __restrict__ cnt, const int* __restrict__ boff,
                         int* rowstart, int* cursor){
    __shared__ int sh[256];
    int t = threadIdx.x;
    int i = blockIdx.x*256 + t;
    int v = cnt[i];
    sh[t] = v;
    __syncthreads();
    #pragma unroll
    for (int off = 1; off < 256; off <<= 1){
        int x = (t >= off) ? sh[t - off] : 0;
        __syncthreads();
        sh[t] += x;
        __syncthreads();
    }
    int ex = boff[blockIdx.x] + sh[t] - v;
    rowstart[i] = ex;
    cursor[i]   = ex;
}
__global__ void k_scatter(const int* __restrict__ rows, const int* __restrict__ cols,
                          const float* __restrict__ w, const float* __restrict__ dis,
                          int* cursor, int2* edata){
    int e = blockIdx.x*blockDim.x + threadIdx.x;
    if (e >= NE) return;
    int r = rows[e], c = cols[e];
    float norm = dis[r]*w[e]*dis[c];
    int pos = atomicAdd(&cursor[c], 1);
    edata[pos] = make_int2(r, __float_as_int(norm));
}

// ---------------- xw = x @ W1  (K=8), 2 nodes per thread ----------------
__global__ void k_xw1(const float* __restrict__ x, const float* __restrict__ W, float* __restrict__ out){
    __shared__ float Ws[FIN*HD];
    for (int i = threadIdx.x; i < FIN*HD; i += blockDim.x) Ws[i] = W[i];
    __syncthreads();
    int base = (blockIdx.x*blockDim.x + threadIdx.x)*2;
    if (base >= NTOT) return;
    #pragma unroll
    for (int u = 0; u < 2; u++){
        int node = base + u;
        float xr[FIN];
        float4 v0 = *(const float4*)(x + (size_t)node*FIN);
        float4 v1 = *(const float4*)(x + (size_t)node*FIN + 4);
        xr[0]=v0.x; xr[1]=v0.y; xr[2]=v0.z; xr[3]=v0.w;
        xr[4]=v1.x; xr[5]=v1.y; xr[6]=v1.z; xr[7]=v1.w;
        #pragma unroll
        for (int j = 0; j < HD; j += 4){
            float a[4] = {0.f,0.f,0.f,0.f};
            #pragma unroll
            for (int k = 0; k < FIN; k++){
                float4 w4 = *(const float4*)&Ws[k*HD + j];
                fma4(a, xr[k], w4);
            }
            *(float4*)(out + (size_t)node*HD + j) = make_float4(a[0],a[1],a[2],a[3]);
        }
    }
}

// ---------------- aggregation: gather + fused BN stats ----------------
__global__ void __launch_bounds__(256) k_agg_gather(const float* __restrict__ xw,
                                                    const float* __restrict__ dis,
                                                    const int* __restrict__ rowstart,
                                                    const int2* __restrict__ edata,
                                                    float* __restrict__ agg,
                                                    const float* __restrict__ bias,
                                                    float* __restrict__ stats){
    __shared__ float ss [8][64];
    __shared__ float ss2[8][64];
    const int tid = threadIdx.x;
    const int wrp = tid >> 5;
    const int lane = tid & 31;
    int gw = blockIdx.x*8 + wrp;
    float va = 0.f, vb = 0.f;
    if (gw < NTOT){
        int beg = rowstart[gw], end = rowstart[gw+1];
        float d = dis[gw];
        float2 v0 = *(const float2*)(xw + (size_t)gw*HD + lane*2);
        float sc = d*d;
        float2 acc = make_float2(v0.x*sc, v0.y*sc);
        int j = beg;
        for (; j + 2 <= end; j += 2){
            int2 e0 = edata[j], e1 = edata[j+1];
            float2 a = *(const float2*)(xw + (size_t)e0.x*HD + lane*2);
            float2 b = *(const float2*)(xw + (size_t)e1.x*HD + lane*2);
            float n0 = __int_as_float(e0.y), n1 = __int_as_float(e1.y);
            acc.x = fmaf(a.x, n0, acc.x); acc.y = fmaf(a.y, n0, acc.y);
            acc.x = fmaf(b.x, n1, acc.x); acc.y = fmaf(b.y, n1, acc.y);
        }
        if (j < end){
            int2 e0 = edata[j];
            float2 a = *(const float2*)(xw + (size_t)e0.x*HD + lane*2);
            float n0 = __int_as_float(e0.y);
            acc.x = fmaf(a.x, n0, acc.x); acc.y = fmaf(a.y, n0, acc.y);
        }
        *(float2*)(agg + (size_t)gw*HD + lane*2) = acc;
        va = fmaxf(acc.x + bias[lane*2],   0.f);
        vb = fmaxf(acc.y + bias[lane*2+1], 0.f);
    }
    ss [wrp][lane*2]   = va;
    ss [wrp][lane*2+1] = vb;
    ss2[wrp][lane*2]   = va*va;
    ss2[wrp][lane*2+1] = vb*vb;
    __syncthreads();
    if (tid < 64){
        float s = 0.f, s2 = 0.f;
        #pragma unroll
        for (int w = 0; w < 8; w++){ s += ss[w][tid]; s2 += ss2[w][tid]; }
        atomicAdd(&stats[tid], s);
        atomicAdd(&stats[64+tid], s2);
    }
}

__global__ void k_bn_fin(const float* __restrict__ gamma, const float* __restrict__ beta,
                         float* __restrict__ stats){
    int ch = threadIdx.x;
    if (ch < 64){
        const float invN = 1.f/(float)NTOT;
        float m = stats[ch]*invN;
        float var = stats[64+ch]*invN - m*m;
        float sc = gamma[ch]*rsqrtf(var + BNEPS);
        stats[128+ch] = sc;
        stats[192+ch] = beta[ch] - m*sc;
    }
}

// ---------------- xw2 = bn1(agg1) @ W2  (tiled 64x64, f32x2, fused BN, prefetch) ----------------
__global__ void __launch_bounds__(256) k_xw2g(const float* __restrict__ A, const float* __restrict__ W,
                                              const float* __restrict__ bias, const float* __restrict__ stats,
                                              float* __restrict__ out){
    __shared__ float As[16][64];
    __shared__ float Bs[16][68];
    __shared__ float bnb[64], bns[64], bnh[64];
    const int tid = threadIdx.x;
    if (tid < 64){ bnb[tid] = bias[tid]; bns[tid] = stats[128+tid]; bnh[tid] = stats[192+tid]; }
    __syncthreads();
    const int bm = blockIdx.x*64;
    const int lr = tid >> 2, lk = (tid & 3)*4;
    const int m  = bm + lr;
    const int ty = tid >> 4, tx = tid & 15;
    const int kkb = tid >> 4, n4b = (tid & 15)*4;
    float2 acc[4][2] = {};
    float4 av = *(const float4*)(A + (size_t)m*HD + lk);
    float4 bv = *(const float4*)(W + (size_t)kkb*HD + n4b);
    for (int k0 = 0; k0 < HD; k0 += 16){
        int cb = k0 + lk;
        float4 aw = av;
        aw.x = fmaxf(aw.x + bnb[cb+0], 0.f)*bns[cb+0] + bnh[cb+0];
        aw.y = fmaxf(aw.y + bnb[cb+1], 0.f)*bns[cb+1] + bnh[cb+1];
        aw.z = fmaxf(aw.z + bnb[cb+2], 0.f)*bns[cb+2] + bnh[cb+2];
        aw.w = fmaxf(aw.w + bnb[cb+3], 0.f)*bns[cb+3] + bnh[cb+3];
        As[lk+0][lr]=aw.x; As[lk+1][lr]=aw.y; As[lk+2][lr]=aw.z; As[lk+3][lr]=aw.w;
        Bs[kkb][n4b+0]=bv.x; Bs[kkb][n4b+1]=bv.y; Bs[kkb][n4b+2]=bv.z; Bs[kkb][n4b+3]=bv.w;
        __syncthreads();
        if (k0 + 16 < HD){
            av = *(const float4*)(A + (size_t)m*HD + k0 + 16 + lk);
            bv = *(const float4*)(W + (size_t)(k0 + 16 + kkb)*HD + n4b);
        }
        #pragma unroll
        for (int q = 0; q < 16; q++){
            float4 a4 = *(const float4*)&As[q][ty*4];
            float4 b4 = *(const float4*)&Bs[q][tx*4];
            float2 bb0 = make_float2(b4.x, b4.y), bb1 = make_float2(b4.z, b4.w);
            float ar[4] = {a4.x, a4.y, a4.z, a4.w};
            #pragma unroll
            for (int i = 0; i < 4; i++){
                float2 ad = dup2(ar[i]);
                acc[i][0] = ffma2(ad, bb0, acc[i][0]);
                acc[i][1] = ffma2(ad, bb1, acc[i][1]);
            }
        }
        __syncthreads();
    }
    #pragma unroll
    for (int i = 0; i < 4; i++){
        int mr = bm + ty*4 + i;
        *(float4*)(out + (size_t)mr*HD + tx*4) =
            make_float4(acc[i][0].x, acc[i][0].y, acc[i][1].x, acc[i][1].y);
    }
}

// ---------------- gate GEMM: out[m][256] = A[m][KD] @ W^T + bias ----------------
template<int KD, bool GATHER>
__global__ void __launch_bounds__(256, 2)
k_gemm_tc(const float* __restrict__ A0, const float* __restrict__ A1,
          const float* __restrict__ whi, const float* __restrict__ wlo,
          const float* __restrict__ bih, const float* __restrict__ bhh,
          const float* __restrict__ b1, const float* __restrict__ b2,
          const float* __restrict__ stats,
          float* __restrict__ out){
    extern __shared__ float sm[];
    float* bias_sm = sm + 64;           // 256 floats
    float* bnb = sm + 320; float* bns = sm + 448; float* bnh = sm + 576;
    const int tid = threadIdx.x;

    if (tid < 128){
        bias_sm[tid]     = bih[tid]     + bhh[tid];
        bias_sm[128+tid] = bih[128+tid] + bhh[128+tid];
    }
    if (GATHER && tid < 64){
        bnb[tid]    = b1[tid]; bns[tid]    = stats[128+tid]; bnh[tid]    = stats[192+tid];
        bnb[64+tid] = b2[tid]; bns[64+tid] = stats[384+tid]; bnh[64+tid] = stats[448+tid];
    }

#if HAS_TCGEN05
    char* smc = (char*)sm;
    const uint32_t sb = smem_u32(sm);
    const uint32_t mb = sb + 8;
    const int wid = tid >> 5, lane = tid & 31;
    if (wid == 0){
        asm volatile("tcgen05.alloc.cta_group::1.sync.aligned.shared::cta.b32 [%0], %1;"
                     :: "r"(sb), "r"(256u) : "memory");
        asm volatile("tcgen05.relinquish_alloc_permit.cta_group::1.sync.aligned;" ::: "memory");
    }
    if (tid == 0)
        asm volatile("mbarrier.init.shared.b64 [%0], %1;" :: "r"(mb), "r"(1u) : "memory");
    __syncthreads();
    uint32_t tmem;
    asm volatile("ld.shared.b32 %0, [%1];" : "=r"(tmem) : "r"(sb));

    const int bm = blockIdx.x*128;
    const int row = tid >> 1;
    const int j4  = (tid & 1)*4;
    const int m = bm + row;
    size_t aoff;
    if (GATHER){
        int t = m/BNS, s = m - t*BNS;
        int b = s/NNODE, n = s - b*NNODE;
        aoff = (size_t)((b*WIN + t)*NNODE + n)*HD;
    } else {
        aoff = (size_t)m*KD;
    }

    const uint64_t dAH = mk_desc(sb + TC_AHI), dAL = mk_desc(sb + TC_ALO);
    const uint64_t dWH = mk_desc(sb + TC_WHI), dWL = mk_desc(sb + TC_WLO);
    const int NCH = KD/32;
    uint32_t parity = 0;
    const uint32_t arow = (uint32_t)((row>>3)*1024 + (row&7)*128);

    float4 pf[4];
    #pragma unroll
    for (int u = 0; u < 4; u++)
        pf[u] = *(const float4*)(A0 + aoff + (j4+u)*4);

    for (int c = 0; c < NCH; c++){
        const int k0 = c*32;
        if (c > 0){ mbar_wait(mb, parity); parity ^= 1; }
        #pragma unroll
        for (int u = 0; u < 4; u++){
            int j = j4 + u;
            float4 v = pf[u];
            if (GATHER){
                int k = k0 + j*4;
                v.x = fmaxf(v.x + bnb[k+0], 0.f)*bns[k+0] + bnh[k+0];
                v.y = fmaxf(v.y + bnb[k+1], 0.f)*bns[k+1] + bnh[k+1];
                v.z = fmaxf(v.z + bnb[k+2], 0.f)*bns[k+2] + bnh[k+2];
                v.w = fmaxf(v.w + bnb[k+3], 0.f)*bns[k+3] + bnh[k+3];
            }
            float4 hi, lo;
            hi.x = tf32r(v.x); lo.x = v.x - hi.x;
            hi.y = tf32r(v.y); lo.y = v.y - hi.y;
            hi.z = tf32r(v.z); lo.z = v.z - hi.z;
            hi.w = tf32r(v.w); lo.w = v.w - hi.w;
            uint32_t sw = swz128(arow + j*16);
            *(float4*)(smc + TC_AHI + sw) = hi;
            *(float4*)(smc + TC_ALO + sw) = lo;
        }
        for (int idx = tid; idx < 2048; idx += 256){
            int g = idx >> 3, j = idx & 7;
            float4 vh = *(const float4*)(whi + (size_t)g*KD + k0 + j*4);
            float4 vl = *(const float4*)(wlo + (size_t)g*KD + k0 + j*4);
            uint32_t sw = swz128((uint32_t)((g>>3)*1024 + (g&7)*128 + j*16));
            *(float4*)(smc + TC_WHI + sw) = vh;
            *(float4*)(smc + TC_WLO + sw) = vl;
        }
        __syncthreads();
        if (tid == 0){
            asm volatile("fence.proxy.async.shared::cta;" ::: "memory");
            #pragma unroll
            for (int s = 0; s < 4; s++){
                uint64_t oa = (uint64_t)(2*s);
                uint32_t en0 = (c == 0 && s == 0) ? 0u : 1u;
                mma_tf32(tmem, dAH + oa, dWH + oa, en0);
                mma_tf32(tmem, dAH + oa, dWL + oa, 1u);
                mma_tf32(tmem, dAL + oa, dWH + oa, 1u);
            }
            asm volatile("tcgen05.commit.cta_group::1.mbarrier::arrive::one.shared::cluster.b64 [%0];"
                         :: "r"(mb) : "memory");
        }
        if (c + 1 < NCH){
            const int k1 = (c+1)*32;
            const float* abase = GATHER ? ((k1 < 64) ? A0 : A1) : A0;
            const int koff = GATHER ? (k1 & 63) : k1;
            #pragma unroll
            for (int u = 0; u < 4; u++)
                pf[u] = *(const float4*)(abase + aoff + koff + (j4+u)*4);
        }
    }
    mbar_wait(mb, parity);
    parity ^= 1;

    asm volatile("tcgen05.fence::after_thread_sync;" ::: "memory");
    {
        int mrow = bm + (wid & 3)*32 + lane;
        int cb   = (wid >> 2)*4;
        float* op = out + (size_t)mrow*256;
        for (int b = cb; b < cb + 4; b++){
            uint32_t r[32];
            LDTM_X32(r, tmem + b*32);
            asm volatile("tcgen05.wait::ld.sync.aligned;" ::: "memory");
            #pragma unroll
            for (int q = 0; q < 8; q++){
                float4 o;
                o.x = __uint_as_float(r[q*4+0]) + bias_sm[b*32 + q*4+0];
                o.y = __uint_as_float(r[q*4+1]) + bias_sm[b*32 + q*4+1];
                o.z = __uint_as_float(r[q*4+2]) + bias_sm[b*32 + q*4+2];
                o.w = __uint_as_float(r[q*4+3]) + bias_sm[b*32 + q*4+3];
                *(float4*)(op + b*32 + q*4) = o;
            }
        }
    }
    __syncthreads();
    if (tid == 0)
        asm volatile("mbarrier.inval.shared.b64 [%0];" :: "r"(mb) : "memory");
    __syncthreads();
    if (wid == 0)
        asm volatile("tcgen05.dealloc.cta_group::1.sync.aligned.b32 %0, %1;"
                     :: "r"(tmem), "r"(256u) : "memory");
#else
    // -------- FFMA2 fallback --------
    float* As = sm + 1024;                 // [16][68]
    float* Bs = sm + 1024 + 16*68;         // [16][260]
    __syncthreads();
    const int bm = blockIdx.x*128;
    const int lr = tid >> 2, lk = (tid & 3)*4;
    const int ty = tid >> 5, tx = tid & 31;
    for (int mh = 0; mh < 2; mh++){
        const int m = bm + mh*64 + lr;
        size_t aoff;
        if (GATHER){
            int t = m/BNS, s = m - t*BNS;
            int b = s/NNODE, n = s - b*NNODE;
            aoff = (size_t)((b*WIN + t)*NNODE + n)*HD;
        } else aoff = (size_t)m*KD;
        float2 acc[8][4] = {};
        for (int k0 = 0; k0 < KD; k0 += 16){
            int k = k0 + lk;
            const float* abase = GATHER ? ((k < 64) ? A0 : A1) : A0;
            int ko = GATHER ? (k & 63) : k;
            float4 v = *(const float4*)(abase + aoff + ko);
            if (GATHER){
                v.x = fmaxf(v.x + bnb[k+0], 0.f)*bns[k+0] + bnh[k+0];
                v.y = fmaxf(v.y + bnb[k+1], 0.f)*bns[k+1] + bnh[k+1];
                v.z = fmaxf(v.z + bnb[k+2], 0.f)*bns[k+2] + bnh[k+2];
                v.w = fmaxf(v.w + bnb[k+3], 0.f)*bns[k+3] + bnh[k+3];
            }
            As[(lk+0)*68 + lr] = v.x;
            As[(lk+1)*68 + lr] = v.y;
            As[(lk+2)*68 + lr] = v.z;
            As[(lk+3)*68 + lr] = v.w;
            for (int i = tid; i < 1024; i += 256){
                int g = i >> 2, kq = (i & 3)*4;
                float4 vh = *(const float4*)(whi + (size_t)g*KD + k0 + kq);
                float4 vl = *(const float4*)(wlo + (size_t)g*KD + k0 + kq);
                Bs[(kq+0)*260 + g] = vh.x + vl.x;
                Bs[(kq+1)*260 + g] = vh.y + vl.y;
                Bs[(kq+2)*260 + g] = vh.z + vl.z;
                Bs[(kq+3)*260 + g] = vh.w + vl.w;
            }
            __syncthreads();
            #pragma unroll
            for (int kk = 0; kk < 16; kk++){
                float4 a0 = *(const float4*)&As[kk*68 + ty*8];
                float4 a1 = *(const float4*)&As[kk*68 + ty*8 + 4];
                float4 b0 = *(const float4*)&Bs[kk*260 + tx*8];
                float4 b1v = *(const float4*)&Bs[kk*260 + tx*8 + 4];
                float2 bb[4] = {make_float2(b0.x,b0.y), make_float2(b0.z,b0.w),
                                make_float2(b1v.x,b1v.y), make_float2(b1v.z,b1v.w)};
                float ar[8] = {a0.x,a0.y,a0.z,a0.w, a1.x,a1.y,a1.z,a1.w};
                #pragma unroll
                for (int i = 0; i < 8; i++){
                    float2 ad = dup2(ar[i]);
                    #pragma unroll
                    for (int p = 0; p < 4; p++)
                        acc[i][p] = ffma2(ad, bb[p], acc[i][p]);
                }
            }
            __syncthreads();
        }
        #pragma unroll
        for (int i = 0; i < 8; i++){
            int mr = bm + mh*64 + ty*8 + i;
            float* op = out + (size_t)mr*256 + tx*8;
            const float* bz = bias_sm + tx*8;
            *(float4*)(op)   = make_float4(acc[i][0].x+bz[0], acc[i][0].y+bz[1],
                                           acc[i][1].x+bz[2], acc[i][1].y+bz[3]);
            *(float4*)(op+4) = make_float4(acc[i][2].x+bz[4], acc[i][2].y+bz[5],
                                           acc[i][3].x+bz[6], acc[i][3].y+bz[7]);
        }
    }
#endif
}

// ---------------- LSTM: 128 seqs / block, 512 threads, TC recurrence ----------------
template<bool WRITE_Y>
__global__ void __launch_bounds__(512, 1) k_lstm(const float* __restrict__ xproj,
                                                 const float* __restrict__ whh_hi,
                                                 const float* __restrict__ whh_lo,
                                                 const float* __restrict__ Whh_raw,
                                                 float* __restrict__ y_out,
                                                 float* __restrict__ hn_out){
    extern __shared__ float sm[];
    const int tid = threadIdx.x;
#if HAS_TCGEN05
    char* smc = (char*)sm;
    const uint32_t sb = smem_u32(sm);
    const uint32_t mb = sb + 8;
    const int wid = tid >> 5, lane = tid & 31;
    for (int idx = tid; idx < 4096; idx += 512){
        int c = idx >> 11;
        int r = idx & 2047;
        int g = r >> 3, j = r & 7;
        uint32_t sw = swz128((uint32_t)((g>>3)*1024 + (g&7)*128 + j*16));
        *(float4*)(smc + LT_W + (c*2+0)*32768 + sw) = *(const float4*)(whh_hi + g*64 + c*32 + j*4);
        *(float4*)(smc + LT_W + (c*2+1)*32768 + sw) = *(const float4*)(whh_lo + g*64 + c*32 + j*4);
    }
    if (wid == 0){
        asm volatile("tcgen05.alloc.cta_group::1.sync.aligned.shared::cta.b32 [%0], %1;"
                     :: "r"(sb), "r"(256u) : "memory");
        asm volatile("tcgen05.relinquish_alloc_permit.cta_group::1.sync.aligned;" ::: "memory");
    }
    if (tid == 0)
        asm volatile("mbarrier.init.shared.b64 [%0], %1;" :: "r"(mb), "r"(1u) : "memory");
    __syncthreads();
    uint32_t tmem;
    asm volatile("ld.shared.b32 %0, [%1];" : "=r"(tmem) : "r"(sb));

    uint64_t dH[2][2], dW[2][2];
    #pragma unroll
    for (int c = 0; c < 2; c++)
        #pragma unroll
        for (int p = 0; p < 2; p++){
            dH[c][p] = mk_desc(sb + LT_H + (uint32_t)(c*2+p)*16384);
            dW[c][p] = mk_desc(sb + LT_W + (uint32_t)(c*2+p)*32768);
        }

    const int sp  = wid & 3;
    const int seq = sp*32 + lane;
    const int j0  = (wid >> 2)*16;
    const int s0  = blockIdx.x*128;
    const int ch  = j0 >> 5;
    const int kw  = j0 & 31;
    const uint32_t hrow = (uint32_t)((seq>>3)*1024 + (seq&7)*128);
    float cst[16];
    #pragma unroll
    for (int i = 0; i < 16; i++) cst[i] = 0.f;
    uint32_t parity = 0;

    for (int t = 0; t < WIN; t++){
        if (t > 0){
            __syncthreads();
            if (tid == 0){
                asm volatile("fence.proxy.async.shared::cta;" ::: "memory");
                bool first = true;
                #pragma unroll
                for (int c = 0; c < 2; c++){
                    #pragma unroll
                    for (int s = 0; s < 4; s++){
                        uint64_t oa = (uint64_t)(2*s);
                        mma_tf32(tmem, dH[c][0] + oa, dW[c][0] + oa, first ? 0u : 1u);
                        first = false;
                        mma_tf32(tmem, dH[c][0] + oa, dW[c][1] + oa, 1u);
                        mma_tf32(tmem, dH[c][1] + oa, dW[c][0] + oa, 1u);
                    }
                }
                asm volatile("tcgen05.commit.cta_group::1.mbarrier::arrive::one.shared::cluster.b64 [%0];"
                             :: "r"(mb) : "memory");
            }
        }
        const float* xp = xproj + ((size_t)t*BNS + s0 + seq)*256 + j0;
        float gi[16], gf[16], gg[16], go[16];
        #pragma unroll
        for (int q = 0; q < 4; q++){
            float4 v;
            v = *(const float4*)(xp + q*4);        gi[q*4]=v.x; gi[q*4+1]=v.y; gi[q*4+2]=v.z; gi[q*4+3]=v.w;
            v = *(const float4*)(xp + 64 + q*4);   gf[q*4]=v.x; gf[q*4+1]=v.y; gf[q*4+2]=v.z; gf[q*4+3]=v.w;
            v = *(const float4*)(xp + 128 + q*4);  gg[q*4]=v.x; gg[q*4+1]=v.y; gg[q*4+2]=v.z; gg[q*4+3]=v.w;
            v = *(const float4*)(xp + 192 + q*4);  go[q*4]=v.x; go[q*4+1]=v.y; go[q*4+2]=v.z; go[q*4+3]=v.w;
        }
        if (t > 0){
            mbar_wait(mb, parity);
            parity ^= 1;
            asm volatile("tcgen05.fence::after_thread_sync;" ::: "memory");
            uint32_t ri[16], rf[16], rg[16], ro[16];
            LDTM_X16(ri, tmem + j0);
            LDTM_X16(rf, tmem + 64 + j0);
            LDTM_X16(rg, tmem + 128 + j0);
            LDTM_X16(ro, tmem + 192 + j0);
            asm volatile("tcgen05.wait::ld.sync.aligned;" ::: "memory");
            #pragma unroll
            for (int i = 0; i < 16; i++){
                gi[i] += __uint_as_float(ri[i]);
                gf[i] += __uint_as_float(rf[i]);
                gg[i] += __uint_as_float(rg[i]);
                go[i] += __uint_as_float(ro[i]);
            }
            asm volatile("tcgen05.fence::before_thread_sync;" ::: "memory");
        }
        float hv[16];
        #pragma unroll
        for (int i = 0; i < 16; i++){
            float iv = sigf(gi[i]);
            float fv = sigf(gf[i]);
            float gv = tanhfast(gg[i]);
            float ov = sigf(go[i]);
            float cc = fmaf(fv, cst[i], iv*gv);
            cst[i] = cc;
            hv[i] = ov*tanhfast(cc);
        }
        if (WRITE_Y){
            float* yp = y_out + ((size_t)t*BNS + s0 + seq)*HD + j0;
            #pragma unroll
            for (int q = 0; q < 4; q++)
                *(float4*)(yp + q*4) = make_float4(hv[q*4], hv[q*4+1], hv[q*4+2], hv[q*4+3]);
        }
        if (t == WIN-1){
            float* hp = hn_out + (size_t)(s0 + seq)*HD + j0;
            #pragma unroll
            for (int q = 0; q < 4; q++)
                *(float4*)(hp + q*4) = make_float4(hv[q*4], hv[q*4+1], hv[q*4+2], hv[q*4+3]);
        }
        #pragma unroll
        for (int q = 0; q < 4; q++){
            float4 hi, lo;
            hi.x = tf32r(hv[q*4+0]); lo.x = hv[q*4+0] - hi.x;
            hi.y = tf32r(hv[q*4+1]); lo.y = hv[q*4+1] - hi.y;
            hi.z = tf32r(hv[q*4+2]); lo.z = hv[q*4+2] - hi.z;
            hi.w = tf32r(hv[q*4+3]); lo.w = hv[q*4+3] - hi.w;
            uint32_t sw = swz128(hrow + (uint32_t)(kw/4 + q)*16);
            *(float4*)(smc + LT_H + (ch*2+0)*16384 + sw) = hi;
            *(float4*)(smc + LT_H + (ch*2+1)*16384 + sw) = lo;
        }
    }
    __syncthreads();
    if (tid == 0)
        asm volatile("mbarrier.inval.shared.b64 [%0];" :: "r"(mb) : "memory");
    __syncthreads();
    if (wid == 0)
        asm volatile("tcgen05.dealloc.cta_group::1.sync.aligned.b32 %0, %1;"
                     :: "r"(tmem), "r"(256u) : "memory");
#else
    // -------- FFMA2 fallback --------
    float* Ws = sm;
    float* Hs = sm + 16384;
    for (int i = tid; i < 16384; i += 512){ int g = i >> 6, k = i & 63; Ws[k*256 + g] = Whh_raw[i]; }
    for (int i = tid; i < 64*HP; i += 512) Hs[i] = 0.f;
    __syncthreads();
    const int tx = tid & 15;
    const int ty = tid >> 4;
    const int s0 = blockIdx.x*128;
    const int sb2 = ty*4;
    float c[4][4]  = {};
    float hv[4][4] = {};
    for (int t = 0; t < WIN; t++){
        float2 ai[4][2], af[4][2], ag[4][2], ao[4][2];
        #pragma unroll
        for (int si = 0; si < 4; si++){
            const float* xp = xproj + ((size_t)t*BNS + (s0 + sb2 + si))*256 + tx*4;
            float4 vi = *(const float4*)(xp);
            float4 vf = *(const float4*)(xp + 64);
            float4 vg = *(const float4*)(xp + 128);
            float4 vo = *(const float4*)(xp + 192);
            ai[si][0]=make_float2(vi.x,vi.y); ai[si][1]=make_float2(vi.z,vi.w);
            af[si][0]=make_float2(vf.x,vf.y); af[si][1]=make_float2(vf.z,vf.w);
            ag[si][0]=make_float2(vg.x,vg.y); ag[si][1]=make_float2(vg.z,vg.w);
            ao[si][0]=make_float2(vo.x,vo.y); ao[si][1]=make_float2(vo.z,vo.w);
        }
        #pragma unroll 4
        for (int k = 0; k < 64; k++){
            float4 h4 = *(const float4*)&Hs[k*HP + sb2];
            const float* wr = &Ws[k*256 + tx*4];
            float4 wi4 = *(const float4*)(wr);
            float4 wf4 = *(const float4*)(wr + 64);
            float4 wg4 = *(const float4*)(wr + 128);
            float4 wo4 = *(const float4*)(wr + 192);
            float2 wi0=make_float2(wi4.x,wi4.y), wi1=make_float2(wi4.z,wi4.w);
            float2 wf0=make_float2(wf4.x,wf4.y), wf1=make_float2(wf4.z,wf4.w);
            float2 wg0=make_float2(wg4.x,wg4.y), wg1=make_float2(wg4.z,wg4.w);
            float2 wo0=make_float2(wo4.x,wo4.y), wo1=make_float2(wo4.z,wo4.w);
            float hs[4] = {h4.x, h4.y, h4.z, h4.w};
            #pragma unroll
            for (int si = 0; si < 4; si++){
                float2 hd = dup2(hs[si]);
                ai[si][0]=ffma2(hd,wi0,ai[si][0]); ai[si][1]=ffma2(hd,wi1,ai[si][1]);
                af[si][0]=ffma2(hd,wf0,af[si][0]); af[si][1]=ffma2(hd,wf1,af[si][1]);
                ag[si][0]=ffma2(hd,wg0,ag[si][0]); ag[si][1]=ffma2(hd,wg1,ag[si][1]);
                ao[si][0]=ffma2(hd,wo0,ao[si][0]); ao[si][1]=ffma2(hd,wo1,ao[si][1]);
            }
        }
        __syncwarp();
        #pragma unroll
        for (int si = 0; si < 4; si++){
            float aiv[4]={ai[si][0].x, ai[si][0].y, ai[si][1].x, ai[si][1].y};
            float afv[4]={af[si][0].x, af[si][0].y, af[si][1].x, af[si][1].y};
            float agv[4]={ag[si][0].x, ag[si][0].y, ag[si][1].x, ag[si][1].y};
            float aov[4]={ao[si][0].x, ao[si][0].y, ao[si][1].x, ao[si][1].y};
            #pragma unroll
            for (int ji = 0; ji < 4; ji++){
                float iv = sigf(aiv[ji]);
                float fv = sigf(afv[ji]);
                float gv = tanhfast(agv[ji]);
                float ov = sigf(aov[ji]);
                float cc = fmaf(fv, c[si][ji], iv*gv);
                c[si][ji] = cc;
                hv[si][ji] = ov*tanhfast(cc);
            }
            if (WRITE_Y){
                float4 o = make_float4(hv[si][0], hv[si][1], hv[si][2], hv[si][3]);
                *(float4*)(y_out + ((size_t)t*BNS + s0 + sb2 + si)*HD + tx*4) = o;
            }
        }
        #pragma unroll
        for (int ji = 0; ji < 4; ji++){
            float4 o = make_float4(hv[0][ji], hv[1][ji], hv[2][ji], hv[3][ji]);
            *(float4*)&Hs[(tx*4 + ji)*HP + sb2] = o;
        }
        __syncwarp();
    }
    #pragma unroll
    for (int si = 0; si < 4; si++){
        float4 o = make_float4(hv[si][0], hv[si][1], hv[si][2], hv[si][3]);
        *(float4*)(hn_out + (size_t)(s0 + sb2 + si)*HD + tx*4) = o;
    }
#endif
}

// ---------------- FC head: 8 seqs/block, 2 per thread ----------------
__global__ void k_fc(const float* __restrict__ hn1, const float* __restrict__ hn2,
                     const float* __restrict__ inner, const float* __restrict__ x,
                     const float* __restrict__ fc1w, const float* __restrict__ fc1b,
                     const float* __restrict__ fc3w, const float* __restrict__ fc3b,
                     float* __restrict__ out){
    __shared__ float Z[8][232];
    __shared__ float red[8][64];
    const int s0 = blockIdx.x*8;
    const int tid = threadIdx.x;
    for (int idx = tid; idx < 8*FC1IN; idx += 256){
        int sl = idx/FC1IN, k = idx - sl*FC1IN;
        int s = s0 + sl;
        float v;
        if (k < 64)        v = hn1[(size_t)s*HD + k];
        else if (k < 128)  v = hn2[(size_t)s*HD + k - 64];
        else if (k == 128) v = inner[s];
        else {
            int si = k - 129;
            int w = si >> 3, f = si & 7;
            int b = s/NNODE, n = s - b*NNODE;
            v = x[((size_t)(b*WIN + w)*NNODE + n)*FIN + f];
        }
        Z[sl][k] = v;
    }
    __syncthreads();
    const int sl = tid >> 6, j = tid & 63;
    float acc0 = fc1b[j], acc1 = fc1b[j];
    #pragma unroll 5
    for (int k = 0; k < FC1IN; k++){
        float wv = fc1w[k*HD + j];
        acc0 = fmaf(Z[sl][k],   wv, acc0);
        acc1 = fmaf(Z[sl+4][k], wv, acc1);
    }
    float w3 = fc3w[j];
    red[sl][j]   = fmaxf(acc0, 0.f)*w3;
    red[sl+4][j] = fmaxf(acc1, 0.f)*w3;
    __syncthreads();
    if (tid < 8){
        float ssum = fc3b[0];
        #pragma unroll
        for (int k = 0; k < 64; k++) ssum += red[tid][k];
        out[s0 + tid] = fmaxf(ssum, 0.f);
    }
}

// ---------------- launch ----------------
extern "C" void kernel_launch(void* const* d_in, const int* in_sizes, int n_in,
                              void* d_out, int out_size){
    const int*   adj   = (const int*)  d_in[0];
    const float* w     = (const float*)d_in[1];
    const float* x     = (const float*)d_in[2];
    const float* inner = (const float*)d_in[3];
    const float* W1    = (const float*)d_in[4];
    const float* b1    = (const float*)d_in[5];
    const float* W2    = (const float*)d_in[6];
    const float* b2    = (const float*)d_in[7];
    const float* gm1   = (const float*)d_in[8];
    const float* bt1   = (const float*)d_in[9];
    const float* gm2   = (const float*)d_in[10];
    const float* bt2   = (const float*)d_in[11];
    const float* Wih1  = (const float*)d_in[12];
    const float* Whh1  = (const float*)d_in[13];
    const float* bih1  = (const float*)d_in[14];
    const float* bhh1  = (const float*)d_in[15];
    const float* Wih2  = (const float*)d_in[16];
    const float* Whh2  = (const float*)d_in[17];
    const float* bih2  = (const float*)d_in[18];
    const float* bhh2  = (const float*)d_in[19];
    const float* fc1w  = (const float*)d_in[20];
    const float* fc1b  = (const float*)d_in[21];
    const float* fc3w  = (const float*)d_in[22];
    const float* fc3b  = (const float*)d_in[23];
    float* out = (float*)d_out;

    float *deg,*dis,*xw,*agg1,*agg2,*stats,*xproj,*y1,*hn1,*hn2;
    float *whi1,*wlo1,*whi2,*wlo2,*hhi1,*hlo1,*hhi2,*hlo2;
    int *cnt,*rowstart,*cursor,*bsum; int2 *edata;
    cudaGetSymbolAddress((void**)&deg,   g_deg);
    cudaGetSymbolAddress((void**)&dis,   g_dis);
    cudaGetSymbolAddress((void**)&xw,    g_xw);
    cudaGetSymbolAddress((void**)&agg1,  g_agg1);
    cudaGetSymbolAddress((void**)&agg2,  g_agg2);
    cudaGetSymbolAddress((void**)&stats, g_stats);
    cudaGetSymbolAddress((void**)&xproj, g_xproj);
    cudaGetSymbolAddress((void**)&y1,    g_y1);
    cudaGetSymbolAddress((void**)&hn1,   g_hn1);
    cudaGetSymbolAddress((void**)&hn2,   g_hn2);
    cudaGetSymbolAddress((void**)&whi1,  g_whi1);
    cudaGetSymbolAddress((void**)&wlo1,  g_wlo1);
    cudaGetSymbolAddress((void**)&whi2,  g_whi2);
    cudaGetSymbolAddress((void**)&wlo2,  g_wlo2);
    cudaGetSymbolAddress((void**)&hhi1,  g_hhi1);
    cudaGetSymbolAddress((void**)&hlo1,  g_hlo1);
    cudaGetSymbolAddress((void**)&hhi2,  g_hhi2);
    cudaGetSymbolAddress((void**)&hlo2,  g_hlo2);
    cudaGetSymbolAddress((void**)&cnt,      g_cnt);
    cudaGetSymbolAddress((void**)&rowstart, g_rowstart);
    cudaGetSymbolAddress((void**)&cursor,   g_cursor);
    cudaGetSymbolAddress((void**)&bsum,     g_bsum);
    cudaGetSymbolAddress((void**)&edata,    g_edata);
    int* boff = bsum + 512;

    cudaFuncSetAttribute(k_lstm<true>,  cudaFuncAttributeMaxDynamicSharedMemorySize, LT_SMEM);
    cudaFuncSetAttribute(k_lstm<false>, cudaFuncAttributeMaxDynamicSharedMemorySize, LT_SMEM);
    cudaFuncSetAttribute(k_gemm_tc<128,true>,  cudaFuncAttributeMaxDynamicSharedMemorySize, TC_SMEM);
    cudaFuncSetAttribute(k_gemm_tc<64,false>,  cudaFuncAttributeMaxDynamicSharedMemorySize, TC_SMEM);

    // fused init + degree + CSR build
    k_initall  <<<NBLK, 256>>>(deg, cnt, Wih1, whi1, wlo1, Wih2, whi2, wlo2,
                               Whh1, hhi1, hlo1, Whh2, hhi2, hlo2);
    k_deg_hist <<<7813, 256>>>(adj + NE, w, deg, cnt);
    k_dis_scan <<<NBLK, 256>>>(deg, dis, cnt, bsum);
    k_scan_b   <<<1, 1024>>>(bsum, boff, rowstart);
    k_scan_c   <<<NBLK, 256>>>(cnt, boff, rowstart, cursor);
    k_scatter  <<<7813, 256>>>(adj, adj + NE, w, dis, cursor, edata);

    // GCN layer 1 (stats fused into gather)
    k_xw1       <<<375, 256>>>(x, W1, xw);
    k_agg_gather<<<24000, 256>>>(xw, dis, rowstart, edata, agg1, b1, stats);
    k_bn_fin    <<<1, 64>>>(gm1, bt1, stats);

    // GCN layer 2
    k_xw2g      <<<3000, 256>>>(agg1, W2, b1, stats, xw);
    k_agg_gather<<<24000, 256>>>(xw, dis, rowstart, edata, agg2, b2, stats + 256);
    k_bn_fin    <<<1, 64>>>(gm2, bt2, stats + 256);

    // LSTM 1 (TC gate GEMM; TC recurrence)
    k_gemm_tc<128, true><<<1500, 256, TC_SMEM>>>(agg1, agg2, whi1, wlo1, bih1, bhh1, b1, b2, stats, xproj);
    k_lstm<true><<<125, 512, LT_SMEM>>>(xproj, hhi1, hlo1, Whh1, y1, hn1);

    // LSTM 2
    k_gemm_tc<64, false><<<1500, 256, TC_SMEM>>>(y1, y1, whi2, wlo2, bih2, bhh2, nullptr, nullptr, nullptr, xproj);
    k_lstm<false><<<125, 512, LT_SMEM>>>(xproj, hhi2, hlo2, Whh2, nullptr, hn2);

    // FC head
    k_fc<<<2000, 256>>>(hn1, hn2, inner, x, fc1w, fc1b, fc3w, fc3b, out);
}

// round 17
// speedup vs baseline: 1.1541x; 1.0106x over previous
#include <cuda_runtime.h>
#include <cstdint>

#define BB     8
#define WIN    12
#define NNODE  2000
#define FIN    8
#define HD     64
#define NTOT   192000          // BB*WIN*NNODE
#define NE     2000000
#define BNS    16000           // BB*NNODE sequences
#define BNEPS  1e-5f
#define FC1IN  225
#define NBLK   750             // NTOT/256

// tc-gemm smem layout (bytes)
#define TC_AHI   4096
#define TC_ALO   20480
#define TC_WHI   36864
#define TC_WLO   69632
#define TC_SMEM  102400
#define TC_IDESC 0x8400910u     // kind::tf32, f32 D, M=128, N=256, K-major both

// tc-lstm smem layout (bytes)
#define LT_H     1024
#define LT_W     (1024 + 4*16384)     // 66560
#define LT_SMEM  (66560 + 4*32768)    // 197632
#define HP       132                  // fallback Hs pitch

#if defined(__CUDA_ARCH_FEAT_SM103_ALL) || defined(__CUDA_ARCH_FEAT_SM100_ALL)
#define HAS_TCGEN05 1
#else
#define HAS_TCGEN05 0
#endif

// ---------------- scratch (device globals; allocation-free) ----------------
__device__ float2 g_degcnt[NTOT];    // .x = weighted degree (incl self), .y = edge count (float)
__device__ float g_dis[NTOT];
__device__ float g_xw  [NTOT*HD];
__device__ float g_agg1[NTOT*HD];
__device__ float g_agg2[NTOT*HD];
__device__ float g_stats[512];
__device__ float g_xproj[(size_t)WIN*BNS*4*HD];
__device__ float g_y1  [(size_t)WIN*BNS*HD];
__device__ float g_hn1 [BNS*HD];
__device__ float g_hn2 [BNS*HD];
__device__ float g_whi1[256*128];
__device__ float g_wlo1[256*128];
__device__ float g_whi2[256*64];
__device__ float g_wlo2[256*64];
__device__ float g_hhi1[256*64];
__device__ float g_hlo1[256*64];
__device__ float g_hhi2[256*64];
__device__ float g_hlo2[256*64];
// CSR scratch
__device__ int   g_rowstart[NTOT+1];
__device__ int   g_cursor[NTOT];
__device__ int   g_bsum[1024];
__device__ int2  g_edata[NE];

// ---------------- helpers ----------------
__device__ __forceinline__ float sigf(float x)  { return __fdividef(1.f, 1.f + __expf(-x)); }
__device__ __forceinline__ float tanhfast(float x){ return 1.f - __fdividef(2.f, __expf(2.f*x) + 1.f); }

__device__ __forceinline__ float2 ffma2(float2 a, float2 b, float2 c){
    float2 d;
    asm("fma.rn.f32x2 %0, %1, %2, %3;"
        : "=l"(reinterpret_cast<unsigned long long&>(d))
        : "l"(reinterpret_cast<unsigned long long&>(a)),
          "l"(reinterpret_cast<unsigned long long&>(b)),
          "l"(reinterpret_cast<unsigned long long&>(c)));
    return d;
}
__device__ __forceinline__ float2 dup2(float x){ return make_float2(x, x); }
__device__ __forceinline__ void fma4(float (&a)[4], float h, float4 w){
    a[0]=fmaf(h,w.x,a[0]); a[1]=fmaf(h,w.y,a[1]); a[2]=fmaf(h,w.z,a[2]); a[3]=fmaf(h,w.w,a[3]);
}
__device__ __forceinline__ float tf32r(float x){
    uint32_t u; asm("cvt.rna.tf32.f32 %0, %1;" : "=r"(u) : "f"(x));
    return __uint_as_float(u);
}
__device__ __forceinline__ void red_add_v2(float* dst, float a, float b){
    asm volatile("red.global.add.v2.f32 [%0], {%1, %2};"
                 :: "l"(dst), "f"(a), "f"(b) : "memory");
}

#if HAS_TCGEN05
__device__ __forceinline__ uint32_t smem_u32(const void* p){
    uint32_t a;
    asm("{ .reg .u64 t; cvta.to.shared.u64 t, %1; cvt.u32.u64 %0, t; }" : "=r"(a) : "l"(p));
    return a;
}
__device__ __forceinline__ uint32_t swz128(uint32_t off){ return off ^ ((off >> 3) & 0x70); }
__device__ __forceinline__ uint64_t mk_desc(uint32_t addr){
    return ((uint64_t)2 << 61) | ((uint64_t)1 << 46) | ((uint64_t)64 << 32) | ((uint64_t)1 << 16)
         | ((uint64_t)(addr >> 4) & 0x3FFF);
}
__device__ __forceinline__ void mma_tf32(uint32_t d, uint64_t ad, uint64_t bd, uint32_t en){
    asm volatile(
        "{\n\t.reg .pred p;\n\tsetp.ne.u32 p, %5, 0;\n\t"
        "tcgen05.mma.cta_group::1.kind::tf32 [%0], %1, %2, %3, {%4, %4, %4, %4}, p;\n\t}"
        :: "r"(d), "l"(ad), "l"(bd), "r"(TC_IDESC), "r"(0u), "r"(en) : "memory");
}
__device__ __forceinline__ void mbar_wait(uint32_t mb, uint32_t parity){
    asm volatile(
        "{\n\t.reg .pred P1;\n\t"
        "W_%=:\n\t"
        "mbarrier.try_wait.parity.acquire.cta.shared::cta.b64 P1, [%0], %1;\n\t"
        "@!P1 bra W_%=;\n\t}"
        :: "r"(mb), "r"(parity) : "memory");
}
#define LDTM_X32(r, addr) \
    asm volatile("tcgen05.ld.sync.aligned.32x32b.x32.b32 " \
        "{%0,%1,%2,%3,%4,%5,%6,%7,%8,%9,%10,%11,%12,%13,%14,%15," \
        "%16,%17,%18,%19,%20,%21,%22,%23,%24,%25,%26,%27,%28,%29,%30,%31}, [%32];" \
        : "=r"((r)[0]),"=r"((r)[1]),"=r"((r)[2]),"=r"((r)[3]),"=r"((r)[4]),"=r"((r)[5]),"=r"((r)[6]),"=r"((r)[7]), \
          "=r"((r)[8]),"=r"((r)[9]),"=r"((r)[10]),"=r"((r)[11]),"=r"((r)[12]),"=r"((r)[13]),"=r"((r)[14]),"=r"((r)[15]), \
          "=r"((r)[16]),"=r"((r)[17]),"=r"((r)[18]),"=r"((r)[19]),"=r"((r)[20]),"=r"((r)[21]),"=r"((r)[22]),"=r"((r)[23]), \
          "=r"((r)[24]),"=r"((r)[25]),"=r"((r)[26]),"=r"((r)[27]),"=r"((r)[28]),"=r"((r)[29]),"=r"((r)[30]),"=r"((r)[31]) \
        : "r"(addr))
#define LDTM_X16(r, addr) \
    asm volatile("tcgen05.ld.sync.aligned.32x32b.x16.b32 " \
        "{%0,%1,%2,%3,%4,%5,%6,%7,%8,%9,%10,%11,%12,%13,%14,%15}, [%16];" \
        : "=r"((r)[0]),"=r"((r)[1]),"=r"((r)[2]),"=r"((r)[3]),"=r"((r)[4]),"=r"((r)[5]),"=r"((r)[6]),"=r"((r)[7]), \
          "=r"((r)[8]),"=r"((r)[9]),"=r"((r)[10]),"=r"((r)[11]),"=r"((r)[12]),"=r"((r)[13]),"=r"((r)[14]),"=r"((r)[15]) \
        : "r"(addr))
#endif

// ---------------- fused init ----------------
__global__ void k_initall(float2* degcnt,
                          const float* __restrict__ Wih1, float* __restrict__ whi1, float* __restrict__ wlo1,
                          const float* __restrict__ Wih2, float* __restrict__ whi2, float* __restrict__ wlo2,
                          const float* __restrict__ Whh1, float* __restrict__ hhi1, float* __restrict__ hlo1,
                          const float* __restrict__ Whh2, float* __restrict__ hhi2, float* __restrict__ hlo2){
    int i = blockIdx.x*blockDim.x + threadIdx.x;
    if (i < NTOT) degcnt[i] = make_float2(1.0f, 0.0f);
    if (i < 512) g_stats[i] = 0.f;
    if (i < 256*128){
        float v = Wih1[i]; float h = tf32r(v);
        whi1[i] = h; wlo1[i] = v - h;
    }
    if (i < 256*64){
        float v = Wih2[i]; float h = tf32r(v);
        whi2[i] = h; wlo2[i] = v - h;
        float v1 = Whh1[i]; float h1 = tf32r(v1);
        hhi1[i] = h1; hlo1[i] = v1 - h1;
        float v2 = Whh2[i]; float h2 = tf32r(v2);
        hhi2[i] = h2; hlo2[i] = v2 - h2;
    }
}
// one vector reduction per edge: {w, 1}
__global__ void k_deg_hist(const int* __restrict__ col, const float* __restrict__ w,
                           float2* degcnt){
    int e = blockIdx.x*blockDim.x + threadIdx.x;
    if (e < NE){
        int c = col[e];
        red_add_v2((float*)(degcnt + c), w[e], 1.0f);
    }
}
__global__ void k_dis_scan(const float2* __restrict__ degcnt, float* dis, int* bsum){
    __shared__ int sh[256];
    int t = threadIdx.x;
    int i = blockIdx.x*256 + t;
    float2 dc = degcnt[i];
    dis[i] = (dc.x > 0.f) ? rsqrtf(dc.x) : 0.f;
    sh[t] = (int)dc.y;
    __syncthreads();
    #pragma unroll
    for (int off = 128; off > 0; off >>= 1){
        if (t < off) sh[t] += sh[t + off];
        __syncthreads();
    }
    if (t == 0) bsum[blockIdx.x] = sh[0];
}
__global__ void k_scan_b(const int* __restrict__ bsum, int* boff, int* rowstart){
    __shared__ int sh[1024];
    int t = threadIdx.x;
    int v = (t < NBLK) ? bsum[t] : 0;
    sh[t] = v;
    __syncthreads();
    #pragma unroll
    for (int off = 1; off < 1024; off <<= 1){
        int x = (t >= off) ? sh[t - off] : 0;
        __syncthreads();
        sh[t] += x;
        __syncthreads();
    }
    if (t < NBLK) boff[t] = sh[t] - v;
    if (t == 0) rowstart[NTOT] = NE;
}
__global__ void k_scan_c(const float2* __restrict__ degcnt, const int* __restrict__ boff,
                         int* rowstart, int* cursor){
    __shared__ int sh[256];
    int t = threadIdx.x;
    int i = blockIdx.x*256 + t;
    int v = (int)degcnt[i].y;
    sh[t] = v;
    __syncthreads();
    #pragma unroll
    for (int off = 1; off < 256; off <<= 1){
        int x = (t >= off) ? sh[t - off] : 0;
        __syncthreads();
        sh[t] += x;
        __syncthreads();
    }
    int ex = boff[blockIdx.x] + sh[t] - v;
    rowstart[i] = ex;
    cursor[i]   = ex;
}
__global__ void k_scatter(const int* __restrict__ rows, const int* __restrict__ cols,
                          const float* __restrict__ w, const float* __restrict__ dis,
                          int* cursor, int2* edata){
    int e = blockIdx.x*blockDim.x + threadIdx.x;
    if (e >= NE) return;
    int r = rows[e], c = cols[e];
    float norm = dis[r]*w[e]*dis[c];
    int pos = atomicAdd(&cursor[c], 1);
    edata[pos] = make_int2(r, __float_as_int(norm));
}

// ---------------- xw = x @ W1  (K=8), 2 nodes per thread ----------------
__global__ void k_xw1(const float* __restrict__ x, const float* __restrict__ W, float* __restrict__ out){
    __shared__ float Ws[FIN*HD];
    for (int i = threadIdx.x; i < FIN*HD; i += blockDim.x) Ws[i] = W[i];
    __syncthreads();
    int base = (blockIdx.x*blockDim.x + threadIdx.x)*2;
    if (base >= NTOT) return;
    #pragma unroll
    for (int u = 0; u < 2; u++){
        int node = base + u;
        float xr[FIN];
        float4 v0 = *(const float4*)(x + (size_t)node*FIN);
        float4 v1 = *(const float4*)(x + (size_t)node*FIN + 4);
        xr[0]=v0.x; xr[1]=v0.y; xr[2]=v0.z; xr[3]=v0.w;
        xr[4]=v1.x; xr[5]=v1.y; xr[6]=v1.z; xr[7]=v1.w;
        #pragma unroll
        for (int j = 0; j < HD; j += 4){
            float a[4] = {0.f,0.f,0.f,0.f};
            #pragma unroll
            for (int k = 0; k < FIN; k++){
                float4 w4 = *(const float4*)&Ws[k*HD + j];
                fma4(a, xr[k], w4);
            }
            *(float4*)(out + (size_t)node*HD + j) = make_float4(a[0],a[1],a[2],a[3]);
        }
    }
}

// ---------------- aggregation: gather + fused BN stats ----------------
__global__ void __launch_bounds__(256) k_agg_gather(const float* __restrict__ xw,
                                                    const float* __restrict__ dis,
                                                    const int* __restrict__ rowstart,
                                                    const int2* __restrict__ edata,
                                                    float* __restrict__ agg,
                                                    const float* __restrict__ bias,
                                                    float* __restrict__ stats){
    __shared__ float ss [8][64];
    __shared__ float ss2[8][64];
    const int tid = threadIdx.x;
    const int wrp = tid >> 5;
    const int lane = tid & 31;
    int gw = blockIdx.x*8 + wrp;
    float va = 0.f, vb = 0.f;
    if (gw < NTOT){
        int beg = rowstart[gw], end = rowstart[gw+1];
        float d = dis[gw];
        float2 v0 = *(const float2*)(xw + (size_t)gw*HD + lane*2);
        float sc = d*d;
        float2 acc = make_float2(v0.x*sc, v0.y*sc);
        int j = beg;
        for (; j + 2 <= end; j += 2){
            int2 e0 = edata[j], e1 = edata[j+1];
            float2 a = *(const float2*)(xw + (size_t)e0.x*HD + lane*2);
            float2 b = *(const float2*)(xw + (size_t)e1.x*HD + lane*2);
            float n0 = __int_as_float(e0.y), n1 = __int_as_float(e1.y);
            acc.x = fmaf(a.x, n0, acc.x); acc.y = fmaf(a.y, n0, acc.y);
            acc.x = fmaf(b.x, n1, acc.x); acc.y = fmaf(b.y, n1, acc.y);
        }
        if (j < end){
            int2 e0 = edata[j];
            float2 a = *(const float2*)(xw + (size_t)e0.x*HD + lane*2);
            float n0 = __int_as_float(e0.y);
            acc.x = fmaf(a.x, n0, acc.x); acc.y = fmaf(a.y, n0, acc.y);
        }
        *(float2*)(agg + (size_t)gw*HD + lane*2) = acc;
        va = fmaxf(acc.x + bias[lane*2],   0.f);
        vb = fmaxf(acc.y + bias[lane*2+1], 0.f);
    }
    ss [wrp][lane*2]   = va;
    ss [wrp][lane*2+1] = vb;
    ss2[wrp][lane*2]   = va*va;
    ss2[wrp][lane*2+1] = vb*vb;
    __syncthreads();
    if (tid < 64){
        float s = 0.f, s2 = 0.f;
        #pragma unroll
        for (int w = 0; w < 8; w++){ s += ss[w][tid]; s2 += ss2[w][tid]; }
        atomicAdd(&stats[tid], s);
        atomicAdd(&stats[64+tid], s2);
    }
}

__global__ void k_bn_fin(const float* __restrict__ gamma, const float* __restrict__ beta,
                         float* __restrict__ stats){
    int ch = threadIdx.x;
    if (ch < 64){
        const float invN = 1.f/(float)NTOT;
        float m = stats[ch]*invN;
        float var = stats[64+ch]*invN - m*m;
        float sc = gamma[ch]*rsqrtf(var + BNEPS);
        stats[128+ch] = sc;
        stats[192+ch] = beta[ch] - m*sc;
    }
}

// ---------------- xw2 = bn1(agg1) @ W2  (tiled 64x64, f32x2, fused BN, prefetch) ----------------
__global__ void __launch_bounds__(256) k_xw2g(const float* __restrict__ A, const float* __restrict__ W,
                                              const float* __restrict__ bias, const float* __restrict__ stats,
                                              float* __restrict__ out){
    __shared__ float As[16][64];
    __shared__ float Bs[16][68];
    __shared__ float bnb[64], bns[64], bnh[64];
    const int tid = threadIdx.x;
    if (tid < 64){ bnb[tid] = bias[tid]; bns[tid] = stats[128+tid]; bnh[tid] = stats[192+tid]; }
    __syncthreads();
    const int bm = blockIdx.x*64;
    const int lr = tid >> 2, lk = (tid & 3)*4;
    const int m  = bm + lr;
    const int ty = tid >> 4, tx = tid & 15;
    const int kkb = tid >> 4, n4b = (tid & 15)*4;
    float2 acc[4][2] = {};
    float4 av = *(const float4*)(A + (size_t)m*HD + lk);
    float4 bv = *(const float4*)(W + (size_t)kkb*HD + n4b);
    for (int k0 = 0; k0 < HD; k0 += 16){
        int cb = k0 + lk;
        float4 aw = av;
        aw.x = fmaxf(aw.x + bnb[cb+0], 0.f)*bns[cb+0] + bnh[cb+0];
        aw.y = fmaxf(aw.y + bnb[cb+1], 0.f)*bns[cb+1] + bnh[cb+1];
        aw.z = fmaxf(aw.z + bnb[cb+2], 0.f)*bns[cb+2] + bnh[cb+2];
        aw.w = fmaxf(aw.w + bnb[cb+3], 0.f)*bns[cb+3] + bnh[cb+3];
        As[lk+0][lr]=aw.x; As[lk+1][lr]=aw.y; As[lk+2][lr]=aw.z; As[lk+3][lr]=aw.w;
        Bs[kkb][n4b+0]=bv.x; Bs[kkb][n4b+1]=bv.y; Bs[kkb][n4b+2]=bv.z; Bs[kkb][n4b+3]=bv.w;
        __syncthreads();
        if (k0 + 16 < HD){
            av = *(const float4*)(A + (size_t)m*HD + k0 + 16 + lk);
            bv = *(const float4*)(W + (size_t)(k0 + 16 + kkb)*HD + n4b);
        }
        #pragma unroll
        for (int q = 0; q < 16; q++){
            float4 a4 = *(const float4*)&As[q][ty*4];
            float4 b4 = *(const float4*)&Bs[q][tx*4];
            float2 bb0 = make_float2(b4.x, b4.y), bb1 = make_float2(b4.z, b4.w);
            float ar[4] = {a4.x, a4.y, a4.z, a4.w};
            #pragma unroll
            for (int i = 0; i < 4; i++){
                float2 ad = dup2(ar[i]);
                acc[i][0] = ffma2(ad, bb0, acc[i][0]);
                acc[i][1] = ffma2(ad, bb1, acc[i][1]);
            }
        }
        __syncthreads();
    }
    #pragma unroll
    for (int i = 0; i < 4; i++){
        int mr = bm + ty*4 + i;
        *(float4*)(out + (size_t)mr*HD + tx*4) =
            make_float4(acc[i][0].x, acc[i][0].y, acc[i][1].x, acc[i][1].y);
    }
}

// ---------------- gate GEMM: out[m][256] = A[m][KD] @ W^T + bias ----------------
template<int KD, bool GATHER>
__global__ void __launch_bounds__(256, 2)
k_gemm_tc(const float* __restrict__ A0, const float* __restrict__ A1,
          const float* __restrict__ whi, const float* __restrict__ wlo,
          const float* __restrict__ bih, const float* __restrict__ bhh,
          const float* __restrict__ b1, const float* __restrict__ b2,
          const float* __restrict__ stats,
          float* __restrict__ out){
    extern __shared__ float sm[];
    float* bias_sm = sm + 64;           // 256 floats
    float* bnb = sm + 320; float* bns = sm + 448; float* bnh = sm + 576;
    const int tid = threadIdx.x;

    if (tid < 128){
        bias_sm[tid]     = bih[tid]     + bhh[tid];
        bias_sm[128+tid] = bih[128+tid] + bhh[128+tid];
    }
    if (GATHER && tid < 64){
        bnb[tid]    = b1[tid]; bns[tid]    = stats[128+tid]; bnh[tid]    = stats[192+tid];
        bnb[64+tid] = b2[tid]; bns[64+tid] = stats[384+tid]; bnh[64+tid] = stats[448+tid];
    }

#if HAS_TCGEN05
    char* smc = (char*)sm;
    const uint32_t sb = smem_u32(sm);
    const uint32_t mb = sb + 8;
    const int wid = tid >> 5, lane = tid & 31;
    if (wid == 0){
        asm volatile("tcgen05.alloc.cta_group::1.sync.aligned.shared::cta.b32 [%0], %1;"
                     :: "r"(sb), "r"(256u) : "memory");
        asm volatile("tcgen05.relinquish_alloc_permit.cta_group::1.sync.aligned;" ::: "memory");
    }
    if (tid == 0)
        asm volatile("mbarrier.init.shared.b64 [%0], %1;" :: "r"(mb), "r"(1u) : "memory");
    __syncthreads();
    uint32_t tmem;
    asm volatile("ld.shared.b32 %0, [%1];" : "=r"(tmem) : "r"(sb));

    const int bm = blockIdx.x*128;
    const int row = tid >> 1;
    const int j4  = (tid & 1)*4;
    const int m = bm + row;
    size_t aoff;
    if (GATHER){
        int t = m/BNS, s = m - t*BNS;
        int b = s/NNODE, n = s - b*NNODE;
        aoff = (size_t)((b*WIN + t)*NNODE + n)*HD;
    } else {
        aoff = (size_t)m*KD;
    }

    const uint64_t dAH = mk_desc(sb + TC_AHI), dAL = mk_desc(sb + TC_ALO);
    const uint64_t dWH = mk_desc(sb + TC_WHI), dWL = mk_desc(sb + TC_WLO);
    const int NCH = KD/32;
    uint32_t parity = 0;
    const uint32_t arow = (uint32_t)((row>>3)*1024 + (row&7)*128);

    float4 pf[4];
    #pragma unroll
    for (int u = 0; u < 4; u++)
        pf[u] = *(const float4*)(A0 + aoff + (j4+u)*4);

    for (int c = 0; c < NCH; c++){
        const int k0 = c*32;
        if (c > 0){ mbar_wait(mb, parity); parity ^= 1; }
        #pragma unroll
        for (int u = 0; u < 4; u++){
            int j = j4 + u;
            float4 v = pf[u];
            if (GATHER){
                int k = k0 + j*4;
                v.x = fmaxf(v.x + bnb[k+0], 0.f)*bns[k+0] + bnh[k+0];
                v.y = fmaxf(v.y + bnb[k+1], 0.f)*bns[k+1] + bnh[k+1];
                v.z = fmaxf(v.z + bnb[k+2], 0.f)*bns[k+2] + bnh[k+2];
                v.w = fmaxf(v.w + bnb[k+3], 0.f)*bns[k+3] + bnh[k+3];
            }
            float4 hi, lo;
            hi.x = tf32r(v.x); lo.x = v.x - hi.x;
            hi.y = tf32r(v.y); lo.y = v.y - hi.y;
            hi.z = tf32r(v.z); lo.z = v.z - hi.z;
            hi.w = tf32r(v.w); lo.w = v.w - hi.w;
            uint32_t sw = swz128(arow + j*16);
            *(float4*)(smc + TC_AHI + sw) = hi;
            *(float4*)(smc + TC_ALO + sw) = lo;
        }
        for (int idx = tid; idx < 2048; idx += 256){
            int g = idx >> 3, j = idx & 7;
            float4 vh = *(const float4*)(whi + (size_t)g*KD + k0 + j*4);
            float4 vl = *(const float4*)(wlo + (size_t)g*KD + k0 + j*4);
            uint32_t sw = swz128((uint32_t)((g>>3)*1024 + (g&7)*128 + j*16));
            *(float4*)(smc + TC_WHI + sw) = vh;
            *(float4*)(smc + TC_WLO + sw) = vl;
        }
        __syncthreads();
        if (tid == 0){
            asm volatile("fence.proxy.async.shared::cta;" ::: "memory");
            #pragma unroll
            for (int s = 0; s < 4; s++){
                uint64_t oa = (uint64_t)(2*s);
                uint32_t en0 = (c == 0 && s == 0) ? 0u : 1u;
                mma_tf32(tmem, dAH + oa, dWH + oa, en0);
                mma_tf32(tmem, dAH + oa, dWL + oa, 1u);
                mma_tf32(tmem, dAL + oa, dWH + oa, 1u);
            }
            asm volatile("tcgen05.commit.cta_group::1.mbarrier::arrive::one.shared::cluster.b64 [%0];"
                         :: "r"(mb) : "memory");
        }
        if (c + 1 < NCH){
            const int k1 = (c+1)*32;
            const float* abase = GATHER ? ((k1 < 64) ? A0 : A1) : A0;
            const int koff = GATHER ? (k1 & 63) : k1;
            #pragma unroll
            for (int u = 0; u < 4; u++)
                pf[u] = *(const float4*)(abase + aoff + koff + (j4+u)*4);
        }
    }
    mbar_wait(mb, parity);
    parity ^= 1;

    asm volatile("tcgen05.fence::after_thread_sync;" ::: "memory");
    {
        int mrow = bm + (wid & 3)*32 + lane;
        int cb   = (wid >> 2)*4;
        float* op = out + (size_t)mrow*256;
        for (int b = cb; b < cb + 4; b++){
            uint32_t r[32];
            LDTM_X32(r, tmem + b*32);
            asm volatile("tcgen05.wait::ld.sync.aligned;" ::: "memory");
            #pragma unroll
            for (int q = 0; q < 8; q++){
                float4 o;
                o.x = __uint_as_float(r[q*4+0]) + bias_sm[b*32 + q*4+0];
                o.y = __uint_as_float(r[q*4+1]) + bias_sm[b*32 + q*4+1];
                o.z = __uint_as_float(r[q*4+2]) + bias_sm[b*32 + q*4+2];
                o.w = __uint_as_float(r[q*4+3]) + bias_sm[b*32 + q*4+3];
                *(float4*)(op + b*32 + q*4) = o;
            }
        }
    }
    __syncthreads();
    if (tid == 0)
        asm volatile("mbarrier.inval.shared.b64 [%0];" :: "r"(mb) : "memory");
    __syncthreads();
    if (wid == 0)
        asm volatile("tcgen05.dealloc.cta_group::1.sync.aligned.b32 %0, %1;"
                     :: "r"(tmem), "r"(256u) : "memory");
#else
    // -------- FFMA2 fallback --------
    float* As = sm + 1024;                 // [16][68]
    float* Bs = sm + 1024 + 16*68;         // [16][260]
    __syncthreads();
    const int bm = blockIdx.x*128;
    const int lr = tid >> 2, lk = (tid & 3)*4;
    const int ty = tid >> 5, tx = tid & 31;
    for (int mh = 0; mh < 2; mh++){
        const int m = bm + mh*64 + lr;
        size_t aoff;
        if (GATHER){
            int t = m/BNS, s = m - t*BNS;
            int b = s/NNODE, n = s - b*NNODE;
            aoff = (size_t)((b*WIN + t)*NNODE + n)*HD;
        } else aoff = (size_t)m*KD;
        float2 acc[8][4] = {};
        for (int k0 = 0; k0 < KD; k0 += 16){
            int k = k0 + lk;
            const float* abase = GATHER ? ((k < 64) ? A0 : A1) : A0;
            int ko = GATHER ? (k & 63) : k;
            float4 v = *(const float4*)(abase + aoff + ko);
            if (GATHER){
                v.x = fmaxf(v.x + bnb[k+0], 0.f)*bns[k+0] + bnh[k+0];
                v.y = fmaxf(v.y + bnb[k+1], 0.f)*bns[k+1] + bnh[k+1];
                v.z = fmaxf(v.z + bnb[k+2], 0.f)*bns[k+2] + bnh[k+2];
                v.w = fmaxf(v.w + bnb[k+3], 0.f)*bns[k+3] + bnh[k+3];
            }
            As[(lk+0)*68 + lr] = v.x;
            As[(lk+1)*68 + lr] = v.y;
            As[(lk+2)*68 + lr] = v.z;
            As[(lk+3)*68 + lr] = v.w;
            for (int i = tid; i < 1024; i += 256){
                int g = i >> 2, kq = (i & 3)*4;
                float4 vh = *(const float4*)(whi + (size_t)g*KD + k0 + kq);
                float4 vl = *(const float4*)(wlo + (size_t)g*KD + k0 + kq);
                Bs[(kq+0)*260 + g] = vh.x + vl.x;
                Bs[(kq+1)*260 + g] = vh.y + vl.y;
                Bs[(kq+2)*260 + g] = vh.z + vl.z;
                Bs[(kq+3)*260 + g] = vh.w + vl.w;
            }
            __syncthreads();
            #pragma unroll
            for (int kk = 0; kk < 16; kk++){
                float4 a0 = *(const float4*)&As[kk*68 + ty*8];
                float4 a1 = *(const float4*)&As[kk*68 + ty*8 + 4];
                float4 b0 = *(const float4*)&Bs[kk*260 + tx*8];
                float4 b1v = *(const float4*)&Bs[kk*260 + tx*8 + 4];
                float2 bb[4] = {make_float2(b0.x,b0.y), make_float2(b0.z,b0.w),
                                make_float2(b1v.x,b1v.y), make_float2(b1v.z,b1v.w)};
                float ar[8] = {a0.x,a0.y,a0.z,a0.w, a1.x,a1.y,a1.z,a1.w};
                #pragma unroll
                for (int i = 0; i < 8; i++){
                    float2 ad = dup2(ar[i]);
                    #pragma unroll
                    for (int p = 0; p < 4; p++)
                        acc[i][p] = ffma2(ad, bb[p], acc[i][p]);
                }
            }
            __syncthreads();
        }
        #pragma unroll
        for (int i = 0; i < 8; i++){
            int mr = bm + mh*64 + ty*8 + i;
            float* op = out + (size_t)mr*256 + tx*8;
            const float* bz = bias_sm + tx*8;
            *(float4*)(op)   = make_float4(acc[i][0].x+bz[0], acc[i][0].y+bz[1],
                                           acc[i][1].x+bz[2], acc[i][1].y+bz[3]);
            *(float4*)(op+4) = make_float4(acc[i][2].x+bz[4], acc[i][2].y+bz[5],
                                           acc[i][3].x+bz[6], acc[i][3].y+bz[7]);
        }
    }
#endif
}

// ---------------- LSTM: 128 seqs / block, 512 threads, TC recurrence ----------------
template<bool WRITE_Y>
__global__ void __launch_bounds__(512, 1) k_lstm(const float* __restrict__ xproj,
                                                 const float* __restrict__ whh_hi,
                                                 const float* __restrict__ whh_lo,
                                                 const float* __restrict__ Whh_raw,
                                                 float* __restrict__ y_out,
                                                 float* __restrict__ hn_out){
    extern __shared__ float sm[];
    const int tid = threadIdx.x;
#if HAS_TCGEN05
    char* smc = (char*)sm;
    const uint32_t sb = smem_u32(sm);
    const uint32_t mb = sb + 8;
    const int wid = tid >> 5, lane = tid & 31;
    for (int idx = tid; idx < 4096; idx += 512){
        int c = idx >> 11;
        int r = idx & 2047;
        int g = r >> 3, j = r & 7;
        uint32_t sw = swz128((uint32_t)((g>>3)*1024 + (g&7)*128 + j*16));
        *(float4*)(smc + LT_W + (c*2+0)*32768 + sw) = *(const float4*)(whh_hi + g*64 + c*32 + j*4);
        *(float4*)(smc + LT_W + (c*2+1)*32768 + sw) = *(const float4*)(whh_lo + g*64 + c*32 + j*4);
    }
    if (wid == 0){
        asm volatile("tcgen05.alloc.cta_group::1.sync.aligned.shared::cta.b32 [%0], %1;"
                     :: "r"(sb), "r"(256u) : "memory");
        asm volatile("tcgen05.relinquish_alloc_permit.cta_group::1.sync.aligned;" ::: "memory");
    }
    if (tid == 0)
        asm volatile("mbarrier.init.shared.b64 [%0], %1;" :: "r"(mb), "r"(1u) : "memory");
    __syncthreads();
    uint32_t tmem;
    asm volatile("ld.shared.b32 %0, [%1];" : "=r"(tmem) : "r"(sb));

    uint64_t dH[2][2], dW[2][2];
    #pragma unroll
    for (int c = 0; c < 2; c++)
        #pragma unroll
        for (int p = 0; p < 2; p++){
            dH[c][p] = mk_desc(sb + LT_H + (uint32_t)(c*2+p)*16384);
            dW[c][p] = mk_desc(sb + LT_W + (uint32_t)(c*2+p)*32768);
        }

    const int sp  = wid & 3;
    const int seq = sp*32 + lane;
    const int j0  = (wid >> 2)*16;
    const int s0  = blockIdx.x*128;
    const int ch  = j0 >> 5;
    const int kw  = j0 & 31;
    const uint32_t hrow = (uint32_t)((seq>>3)*1024 + (seq&7)*128);
    float cst[16];
    #pragma unroll
    for (int i = 0; i < 16; i++) cst[i] = 0.f;
    uint32_t parity = 0;

    for (int t = 0; t < WIN; t++){
        if (t > 0){
            __syncthreads();
            if (tid == 0){
                asm volatile("fence.proxy.async.shared::cta;" ::: "memory");
                bool first = true;
                #pragma unroll
                for (int c = 0; c < 2; c++){
                    #pragma unroll
                    for (int s = 0; s < 4; s++){
                        uint64_t oa = (uint64_t)(2*s);
                        mma_tf32(tmem, dH[c][0] + oa, dW[c][0] + oa, first ? 0u : 1u);
                        first = false;
                        mma_tf32(tmem, dH[c][0] + oa, dW[c][1] + oa, 1u);
                        mma_tf32(tmem, dH[c][1] + oa, dW[c][0] + oa, 1u);
                    }
                }
                asm volatile("tcgen05.commit.cta_group::1.mbarrier::arrive::one.shared::cluster.b64 [%0];"
                             :: "r"(mb) : "memory");
            }
        }
        const float* xp = xproj + ((size_t)t*BNS + s0 + seq)*256 + j0;
        float gi[16], gf[16], gg[16], go[16];
        #pragma unroll
        for (int q = 0; q < 4; q++){
            float4 v;
            v = *(const float4*)(xp + q*4);        gi[q*4]=v.x; gi[q*4+1]=v.y; gi[q*4+2]=v.z; gi[q*4+3]=v.w;
            v = *(const float4*)(xp + 64 + q*4);   gf[q*4]=v.x; gf[q*4+1]=v.y; gf[q*4+2]=v.z; gf[q*4+3]=v.w;
            v = *(const float4*)(xp + 128 + q*4);  gg[q*4]=v.x; gg[q*4+1]=v.y; gg[q*4+2]=v.z; gg[q*4+3]=v.w;
            v = *(const float4*)(xp + 192 + q*4);  go[q*4]=v.x; go[q*4+1]=v.y; go[q*4+2]=v.z; go[q*4+3]=v.w;
        }
        if (t > 0){
            mbar_wait(mb, parity);
            parity ^= 1;
            asm volatile("tcgen05.fence::after_thread_sync;" ::: "memory");
            uint32_t ri[16], rf[16], rg[16], ro[16];
            LDTM_X16(ri, tmem + j0);
            LDTM_X16(rf, tmem + 64 + j0);
            LDTM_X16(rg, tmem + 128 + j0);
            LDTM_X16(ro, tmem + 192 + j0);
            asm volatile("tcgen05.wait::ld.sync.aligned;" ::: "memory");
            #pragma unroll
            for (int i = 0; i < 16; i++){
                gi[i] += __uint_as_float(ri[i]);
                gf[i] += __uint_as_float(rf[i]);
                gg[i] += __uint_as_float(rg[i]);
                go[i] += __uint_as_float(ro[i]);
            }
            asm volatile("tcgen05.fence::before_thread_sync;" ::: "memory");
        }
        float hv[16];
        #pragma unroll
        for (int i = 0; i < 16; i++){
            float iv = sigf(gi[i]);
            float fv = sigf(gf[i]);
            float gv = tanhfast(gg[i]);
            float ov = sigf(go[i]);
            float cc = fmaf(fv, cst[i], iv*gv);
            cst[i] = cc;
            hv[i] = ov*tanhfast(cc);
        }
        if (WRITE_Y){
            float* yp = y_out + ((size_t)t*BNS + s0 + seq)*HD + j0;
            #pragma unroll
            for (int q = 0; q < 4; q++)
                *(float4*)(yp + q*4) = make_float4(hv[q*4], hv[q*4+1], hv[q*4+2], hv[q*4+3]);
        }
        if (t == WIN-1){
            float* hp = hn_out + (size_t)(s0 + seq)*HD + j0;
            #pragma unroll
            for (int q = 0; q < 4; q++)
                *(float4*)(hp + q*4) = make_float4(hv[q*4], hv[q*4+1], hv[q*4+2], hv[q*4+3]);
        }
        #pragma unroll
        for (int q = 0; q < 4; q++){
            float4 hi, lo;
            hi.x = tf32r(hv[q*4+0]); lo.x = hv[q*4+0] - hi.x;
            hi.y = tf32r(hv[q*4+1]); lo.y = hv[q*4+1] - hi.y;
            hi.z = tf32r(hv[q*4+2]); lo.z = hv[q*4+2] - hi.z;
            hi.w = tf32r(hv[q*4+3]); lo.w = hv[q*4+3] - hi.w;
            uint32_t sw = swz128(hrow + (uint32_t)(kw/4 + q)*16);
            *(float4*)(smc + LT_H + (ch*2+0)*16384 + sw) = hi;
            *(float4*)(smc + LT_H + (ch*2+1)*16384 + sw) = lo;
        }
    }
    __syncthreads();
    if (tid == 0)
        asm volatile("mbarrier.inval.shared.b64 [%0];" :: "r"(mb) : "memory");
    __syncthreads();
    if (wid == 0)
        asm volatile("tcgen05.dealloc.cta_group::1.sync.aligned.b32 %0, %1;"
                     :: "r"(tmem), "r"(256u) : "memory");
#else
    // -------- FFMA2 fallback --------
    float* Ws = sm;
    float* Hs = sm + 16384;
    for (int i = tid; i < 16384; i += 512){ int g = i >> 6, k = i & 63; Ws[k*256 + g] = Whh_raw[i]; }
    for (int i = tid; i < 64*HP; i += 512) Hs[i] = 0.f;
    __syncthreads();
    const int tx = tid & 15;
    const int ty = tid >> 4;
    const int s0 = blockIdx.x*128;
    const int sb2 = ty*4;
    float c[4][4]  = {};
    float hv[4][4] = {};
    for (int t = 0; t < WIN; t++){
        float2 ai[4][2], af[4][2], ag[4][2], ao[4][2];
        #pragma unroll
        for (int si = 0; si < 4; si++){
            const float* xp = xproj + ((size_t)t*BNS + (s0 + sb2 + si))*256 + tx*4;
            float4 vi = *(const float4*)(xp);
            float4 vf = *(const float4*)(xp + 64);
            float4 vg = *(const float4*)(xp + 128);
            float4 vo = *(const float4*)(xp + 192);
            ai[si][0]=make_float2(vi.x,vi.y); ai[si][1]=make_float2(vi.z,vi.w);
            af[si][0]=make_float2(vf.x,vf.y); af[si][1]=make_float2(vf.z,vf.w);
            ag[si][0]=make_float2(vg.x,vg.y); ag[si][1]=make_float2(vg.z,vg.w);
            ao[si][0]=make_float2(vo.x,vo.y); ao[si][1]=make_float2(vo.z,vo.w);
        }
        #pragma unroll 4
        for (int k = 0; k < 64; k++){
            float4 h4 = *(const float4*)&Hs[k*HP + sb2];
            const float* wr = &Ws[k*256 + tx*4];
            float4 wi4 = *(const float4*)(wr);
            float4 wf4 = *(const float4*)(wr + 64);
            float4 wg4 = *(const float4*)(wr + 128);
            float4 wo4 = *(const float4*)(wr + 192);
            float2 wi0=make_float2(wi4.x,wi4.y), wi1=make_float2(wi4.z,wi4.w);
            float2 wf0=make_float2(wf4.x,wf4.y), wf1=make_float2(wf4.z,wf4.w);
            float2 wg0=make_float2(wg4.x,wg4.y), wg1=make_float2(wg4.z,wg4.w);
            float2 wo0=make_float2(wo4.x,wo4.y), wo1=make_float2(wo4.z,wo4.w);
            float hs[4] = {h4.x, h4.y, h4.z, h4.w};
            #pragma unroll
            for (int si = 0; si < 4; si++){
                float2 hd = dup2(hs[si]);
                ai[si][0]=ffma2(hd,wi0,ai[si][0]); ai[si][1]=ffma2(hd,wi1,ai[si][1]);
                af[si][0]=ffma2(hd,wf0,af[si][0]); af[si][1]=ffma2(hd,wf1,af[si][1]);
                ag[si][0]=ffma2(hd,wg0,ag[si][0]); ag[si][1]=ffma2(hd,wg1,ag[si][1]);
                ao[si][0]=ffma2(hd,wo0,ao[si][0]); ao[si][1]=ffma2(hd,wo1,ao[si][1]);
            }
        }
        __syncwarp();
        #pragma unroll
        for (int si = 0; si < 4; si++){
            float aiv[4]={ai[si][0].x, ai[si][0].y, ai[si][1].x, ai[si][1].y};
            float afv[4]={af[si][0].x, af[si][0].y, af[si][1].x, af[si][1].y};
            float agv[4]={ag[si][0].x, ag[si][0].y, ag[si][1].x, ag[si][1].y};
            float aov[4]={ao[si][0].x, ao[si][0].y, ao[si][1].x, ao[si][1].y};
            #pragma unroll
            for (int ji = 0; ji < 4; ji++){
                float iv = sigf(aiv[ji]);
                float fv = sigf(afv[ji]);
                float gv = tanhfast(agv[ji]);
                float ov = sigf(aov[ji]);
                float cc = fmaf(fv, c[si][ji], iv*gv);
                c[si][ji] = cc;
                hv[si][ji] = ov*tanhfast(cc);
            }
            if (WRITE_Y){
                float4 o = make_float4(hv[si][0], hv[si][1], hv[si][2], hv[si][3]);
                *(float4*)(y_out + ((size_t)t*BNS + s0 + sb2 + si)*HD + tx*4) = o;
            }
        }
        #pragma unroll
        for (int ji = 0; ji < 4; ji++){
            float4 o = make_float4(hv[0][ji], hv[1][ji], hv[2][ji], hv[3][ji]);
            *(float4*)&Hs[(tx*4 + ji)*HP + sb2] = o;
        }
        __syncwarp();
    }
    #pragma unroll
    for (int si = 0; si < 4; si++){
        float4 o = make_float4(hv[si][0], hv[si][1], hv[si][2], hv[si][3]);
        *(float4*)(hn_out + (size_t)(s0 + sb2 + si)*HD + tx*4) = o;
    }
#endif
}

// ---------------- FC head: 8 seqs/block, 2 per thread ----------------
__global__ void k_fc(const float* __restrict__ hn1, const float* __restrict__ hn2,
                     const float* __restrict__ inner, const float* __restrict__ x,
                     const float* __restrict__ fc1w, const float* __restrict__ fc1b,
                     const float* __restrict__ fc3w, const float* __restrict__ fc3b,
                     float* __restrict__ out){
    __shared__ float Z[8][232];
    __shared__ float red[8][64];
    const int s0 = blockIdx.x*8;
    const int tid = threadIdx.x;
    for (int idx = tid; idx < 8*FC1IN; idx += 256){
        int sl = idx/FC1IN, k = idx - sl*FC1IN;
        int s = s0 + sl;
        float v;
        if (k < 64)        v = hn1[(size_t)s*HD + k];
        else if (k < 128)  v = hn2[(size_t)s*HD + k - 64];
        else if (k == 128) v = inner[s];
        else {
            int si = k - 129;
            int w = si >> 3, f = si & 7;
            int b = s/NNODE, n = s - b*NNODE;
            v = x[((size_t)(b*WIN + w)*NNODE + n)*FIN + f];
        }
        Z[sl][k] = v;
    }
    __syncthreads();
    const int sl = tid >> 6, j = tid & 63;
    float acc0 = fc1b[j], acc1 = fc1b[j];
    #pragma unroll 5
    for (int k = 0; k < FC1IN; k++){
        float wv = fc1w[k*HD + j];
        acc0 = fmaf(Z[sl][k],   wv, acc0);
        acc1 = fmaf(Z[sl+4][k], wv, acc1);
    }
    float w3 = fc3w[j];
    red[sl][j]   = fmaxf(acc0, 0.f)*w3;
    red[sl+4][j] = fmaxf(acc1, 0.f)*w3;
    __syncthreads();
    if (tid < 8){
        float ssum = fc3b[0];
        #pragma unroll
        for (int k = 0; k < 64; k++) ssum += red[tid][k];
        out[s0 + tid] = fmaxf(ssum, 0.f);
    }
}

// ---------------- launch ----------------
extern "C" void kernel_launch(void* const* d_in, const int* in_sizes, int n_in,
                              void* d_out, int out_size){
    const int*   adj   = (const int*)  d_in[0];
    const float* w     = (const float*)d_in[1];
    const float* x     = (const float*)d_in[2];
    const float* inner = (const float*)d_in[3];
    const float* W1    = (const float*)d_in[4];
    const float* b1    = (const float*)d_in[5];
    const float* W2    = (const float*)d_in[6];
    const float* b2    = (const float*)d_in[7];
    const float* gm1   = (const float*)d_in[8];
    const float* bt1   = (const float*)d_in[9];
    const float* gm2   = (const float*)d_in[10];
    const float* bt2   = (const float*)d_in[11];
    const float* Wih1  = (const float*)d_in[12];
    const float* Whh1  = (const float*)d_in[13];
    const float* bih1  = (const float*)d_in[14];
    const float* bhh1  = (const float*)d_in[15];
    const float* Wih2  = (const float*)d_in[16];
    const float* Whh2  = (const float*)d_in[17];
    const float* bih2  = (const float*)d_in[18];
    const float* bhh2  = (const float*)d_in[19];
    const float* fc1w  = (const float*)d_in[20];
    const float* fc1b  = (const float*)d_in[21];
    const float* fc3w  = (const float*)d_in[22];
    const float* fc3b  = (const float*)d_in[23];
    float* out = (float*)d_out;

    float *dis,*xw,*agg1,*agg2,*stats,*xproj,*y1,*hn1,*hn2;
    float *whi1,*wlo1,*whi2,*wlo2,*hhi1,*hlo1,*hhi2,*hlo2;
    float2 *degcnt;
    int *rowstart,*cursor,*bsum; int2 *edata;
    cudaGetSymbolAddress((void**)&degcnt, g_degcnt);
    cudaGetSymbolAddress((void**)&dis,   g_dis);
    cudaGetSymbolAddress((void**)&xw,    g_xw);
    cudaGetSymbolAddress((void**)&agg1,  g_agg1);
    cudaGetSymbolAddress((void**)&agg2,  g_agg2);
    cudaGetSymbolAddress((void**)&stats, g_stats);
    cudaGetSymbolAddress((void**)&xproj, g_xproj);
    cudaGetSymbolAddress((void**)&y1,    g_y1);
    cudaGetSymbolAddress((void**)&hn1,   g_hn1);
    cudaGetSymbolAddress((void**)&hn2,   g_hn2);
    cudaGetSymbolAddress((void**)&whi1,  g_whi1);
    cudaGetSymbolAddress((void**)&wlo1,  g_wlo1);
    cudaGetSymbolAddress((void**)&whi2,  g_whi2);
    cudaGetSymbolAddress((void**)&wlo2,  g_wlo2);
    cudaGetSymbolAddress((void**)&hhi1,  g_hhi1);
    cudaGetSymbolAddress((void**)&hlo1,  g_hlo1);
    cudaGetSymbolAddress((void**)&hhi2,  g_hhi2);
    cudaGetSymbolAddress((void**)&hlo2,  g_hlo2);
    cudaGetSymbolAddress((void**)&rowstart, g_rowstart);
    cudaGetSymbolAddress((void**)&cursor,   g_cursor);
    cudaGetSymbolAddress((void**)&bsum,     g_bsum);
    cudaGetSymbolAddress((void**)&edata,    g_edata);
    int* boff = bsum + 512;

    cudaFuncSetAttribute(k_lstm<true>,  cudaFuncAttributeMaxDynamicSharedMemorySize, LT_SMEM);
    cudaFuncSetAttribute(k_lstm<false>, cudaFuncAttributeMaxDynamicSharedMemorySize, LT_SMEM);
    cudaFuncSetAttribute(k_gemm_tc<128,true>,  cudaFuncAttributeMaxDynamicSharedMemorySize, TC_SMEM);
    cudaFuncSetAttribute(k_gemm_tc<64,false>,  cudaFuncAttributeMaxDynamicSharedMemorySize, TC_SMEM);

    // fused init + degree + CSR build
    k_initall  <<<NBLK, 256>>>(degcnt, Wih1, whi1, wlo1, Wih2, whi2, wlo2,
                               Whh1, hhi1, hlo1, Whh2, hhi2, hlo2);
    k_deg_hist <<<7813, 256>>>(adj + NE, w, degcnt);
    k_dis_scan <<<NBLK, 256>>>(degcnt, dis, bsum);
    k_scan_b   <<<1, 1024>>>(bsum, boff, rowstart);
    k_scan_c   <<<NBLK, 256>>>(degcnt, boff, rowstart, cursor);
    k_scatter  <<<7813, 256>>>(adj, adj + NE, w, dis, cursor, edata);

    // GCN layer 1 (stats fused into gather)
    k_xw1       <<<375, 256>>>(x, W1, xw);
    k_agg_gather<<<24000, 256>>>(xw, dis, rowstart, edata, agg1, b1, stats);
    k_bn_fin    <<<1, 64>>>(gm1, bt1, stats);

    // GCN layer 2
    k_xw2g      <<<3000, 256>>>(agg1, W2, b1, stats, xw);
    k_agg_gather<<<24000, 256>>>(xw, dis, rowstart, edata, agg2, b2, stats + 256);
    k_bn_fin    <<<1, 64>>>(gm2, bt2, stats + 256);

    // LSTM 1 (TC gate GEMM; TC recurrence)
    k_gemm_tc<128, true><<<1500, 256, TC_SMEM>>>(agg1, agg2, whi1, wlo1, bih1, bhh1, b1, b2, stats, xproj);
    k_lstm<true><<<125, 512, LT_SMEM>>>(xproj, hhi1, hlo1, Whh1, y1, hn1);

    // LSTM 2
    k_gemm_tc<64, false><<<1500, 256, TC_SMEM>>>(y1, y1, whi2, wlo2, bih2, bhh2, nullptr, nullptr, nullptr, xproj);
    k_lstm<false><<<125, 512, LT_SMEM>>>(xproj, hhi2, hlo2, Whh2, nullptr, hn2);

    // FC head
    k_fc<<<2000, 256>>>(hn1, hn2, inner, x, fc1w, fc1b, fc3w, fc3b, out);
}